// round 1
// baseline (speedup 1.0000x reference)
#include <cuda_runtime.h>
#include <math.h>

#define D_MODEL 768
#define NUM_HEADS 12
#define DK 64
#define BATCH 2
#define SEQ 2048
#define MTOT (BATCH * SEQ)   // 4096

// ---------------- scratch (no allocations allowed) ----------------
__device__ float g_Q[MTOT * D_MODEL];
__device__ float g_K[MTOT * D_MODEL];
__device__ float g_V[MTOT * D_MODEL];
__device__ float g_A[MTOT * D_MODEL];

// ---------------- NT GEMM: C[m,n] = sum_k A[m,k] * B[n,k] ----------------
// Tiles: 64x64 output, BK=32. 256 threads, 4x4 register tile per thread.
// M % 64 == 0, N % 64 == 0, K % 32 == 0 (holds: 4096/768/768).
__global__ __launch_bounds__(256)
void gemm_nt(const float* __restrict__ A, const float* __restrict__ B,
             float* __restrict__ C, int M, int N, int K) {
    __shared__ float As[64][33];
    __shared__ float Bs[64][33];

    const int tid = threadIdx.x;
    const int ty = tid >> 4;        // 0..15
    const int tx = tid & 15;        // 0..15
    const int m0 = blockIdx.y * 64;
    const int n0 = blockIdx.x * 64;

    float acc[4][4] = {};

    for (int k0 = 0; k0 < K; k0 += 32) {
        // load 64x32 tiles of A and B as float4 (512 float4 each, 2/thread)
        #pragma unroll
        for (int l = 0; l < 2; l++) {
            int idx = tid + l * 256;
            int r = idx >> 3;              // 8 float4 per row
            int c = (idx & 7) << 2;
            float4 va = *reinterpret_cast<const float4*>(
                &A[(size_t)(m0 + r) * K + k0 + c]);
            As[r][c + 0] = va.x; As[r][c + 1] = va.y;
            As[r][c + 2] = va.z; As[r][c + 3] = va.w;
            float4 vb = *reinterpret_cast<const float4*>(
                &B[(size_t)(n0 + r) * K + k0 + c]);
            Bs[r][c + 0] = vb.x; Bs[r][c + 1] = vb.y;
            Bs[r][c + 2] = vb.z; Bs[r][c + 3] = vb.w;
        }
        __syncthreads();

        #pragma unroll
        for (int k = 0; k < 32; k++) {
            float a[4], b[4];
            #pragma unroll
            for (int i = 0; i < 4; i++) a[i] = As[ty * 4 + i][k];
            #pragma unroll
            for (int j = 0; j < 4; j++) b[j] = Bs[tx * 4 + j][k];
            #pragma unroll
            for (int i = 0; i < 4; i++)
                #pragma unroll
                for (int j = 0; j < 4; j++)
                    acc[i][j] = fmaf(a[i], b[j], acc[i][j]);
        }
        __syncthreads();
    }

    #pragma unroll
    for (int i = 0; i < 4; i++)
        #pragma unroll
        for (int j = 0; j < 4; j++)
            C[(size_t)(m0 + ty * 4 + i) * N + n0 + tx * 4 + j] = acc[i][j];
}

// ---------------- causal flash attention (fp32) ----------------
// grid: (SEQ/64, BATCH*NUM_HEADS), 256 threads.
// Each block: 64 queries of one (b,h); loops over key blocks 0..qb.
#define LD 65   // smem row pitch (padding to break bank conflicts)

__global__ __launch_bounds__(256)
void attn_kernel() {
    extern __shared__ float sm[];
    float (*Qs)[LD] = (float(*)[LD])(sm);
    float (*Ks)[LD] = (float(*)[LD])(sm + 64 * LD);
    float (*Vs)[LD] = (float(*)[LD])(sm + 2 * 64 * LD);
    float (*Ps)[LD] = (float(*)[LD])(sm + 3 * 64 * LD);

    const int tid = threadIdx.x;
    const int ty = tid >> 4;
    const int tx = tid & 15;
    const int qb = blockIdx.x;
    const int b  = blockIdx.y / NUM_HEADS;
    const int h  = blockIdx.y % NUM_HEADS;
    const float scale = 0.125f;   // 1/sqrt(64)

    const size_t base = (size_t)b * SEQ * D_MODEL + (size_t)h * DK;

    // load Q tile (64 x 64): 1024 float4, 4 per thread
    #pragma unroll
    for (int l = 0; l < 4; l++) {
        int idx = tid + l * 256;
        int r = idx >> 4;                  // 16 float4 per row
        int c = (idx & 15) << 2;
        float4 v = *reinterpret_cast<const float4*>(
            &g_Q[base + (size_t)(qb * 64 + r) * D_MODEL + c]);
        Qs[r][c + 0] = v.x; Qs[r][c + 1] = v.y;
        Qs[r][c + 2] = v.z; Qs[r][c + 3] = v.w;
    }

    float acc[4][4] = {};
    float m_i[4], l_i[4];
    #pragma unroll
    for (int i = 0; i < 4; i++) { m_i[i] = -INFINITY; l_i[i] = 0.0f; }

    for (int kb = 0; kb <= qb; kb++) {
        __syncthreads();   // protect Ks/Vs/Ps reuse from previous iteration
        // load K and V tiles
        #pragma unroll
        for (int l = 0; l < 4; l++) {
            int idx = tid + l * 256;
            int r = idx >> 4;
            int c = (idx & 15) << 2;
            size_t goff = base + (size_t)(kb * 64 + r) * D_MODEL + c;
            float4 vk = *reinterpret_cast<const float4*>(&g_K[goff]);
            Ks[r][c + 0] = vk.x; Ks[r][c + 1] = vk.y;
            Ks[r][c + 2] = vk.z; Ks[r][c + 3] = vk.w;
            float4 vv = *reinterpret_cast<const float4*>(&g_V[goff]);
            Vs[r][c + 0] = vv.x; Vs[r][c + 1] = vv.y;
            Vs[r][c + 2] = vv.z; Vs[r][c + 3] = vv.w;
        }
        __syncthreads();   // also covers the initial Q-tile stores

        // S = Q @ K^T (4x4 per thread)
        float s[4][4] = {};
        #pragma unroll
        for (int k = 0; k < 64; k++) {
            float a[4], bb[4];
            #pragma unroll
            for (int i = 0; i < 4; i++) a[i]  = Qs[ty * 4 + i][k];
            #pragma unroll
            for (int j = 0; j < 4; j++) bb[j] = Ks[tx * 4 + j][k];
            #pragma unroll
            for (int i = 0; i < 4; i++)
                #pragma unroll
                for (int j = 0; j < 4; j++)
                    s[i][j] = fmaf(a[i], bb[j], s[i][j]);
        }

        // scale + causal mask (only diagonal block needs masking)
        const bool diag = (kb == qb);
        #pragma unroll
        for (int i = 0; i < 4; i++)
            #pragma unroll
            for (int j = 0; j < 4; j++) {
                s[i][j] *= scale;
                if (diag && (tx * 4 + j > ty * 4 + i)) s[i][j] = -INFINITY;
            }

        // online softmax: row reductions across the 16 tx-lanes
        #pragma unroll
        for (int i = 0; i < 4; i++) {
            float rm = s[i][0];
            rm = fmaxf(rm, s[i][1]);
            rm = fmaxf(rm, s[i][2]);
            rm = fmaxf(rm, s[i][3]);
            #pragma unroll
            for (int o = 8; o >= 1; o >>= 1)
                rm = fmaxf(rm, __shfl_xor_sync(0xffffffffu, rm, o));
            float mn = fmaxf(m_i[i], rm);          // always finite (diag elem)
            float alpha = __expf(m_i[i] - mn);     // exp(-inf)=0 on first block
            float rs = 0.0f;
            #pragma unroll
            for (int j = 0; j < 4; j++) {
                s[i][j] = __expf(s[i][j] - mn);    // masked -> exp(-inf)=0
                rs += s[i][j];
            }
            #pragma unroll
            for (int o = 8; o >= 1; o >>= 1)
                rs += __shfl_xor_sync(0xffffffffu, rs, o);
            l_i[i] = l_i[i] * alpha + rs;
            m_i[i] = mn;
            #pragma unroll
            for (int j = 0; j < 4; j++) {
                acc[i][j] *= alpha;
                Ps[ty * 4 + i][tx * 4 + j] = s[i][j];
            }
        }
        __syncthreads();

        // acc += P @ V
        #pragma unroll
        for (int k = 0; k < 64; k++) {
            float p[4], vv[4];
            #pragma unroll
            for (int i = 0; i < 4; i++) p[i]  = Ps[ty * 4 + i][k];
            #pragma unroll
            for (int j = 0; j < 4; j++) vv[j] = Vs[k][tx * 4 + j];
            #pragma unroll
            for (int i = 0; i < 4; i++)
                #pragma unroll
                for (int j = 0; j < 4; j++)
                    acc[i][j] = fmaf(p[i], vv[j], acc[i][j]);
        }
    }

    // epilogue: normalize and write to g_A
    #pragma unroll
    for (int i = 0; i < 4; i++) {
        float inv = 1.0f / l_i[i];
        #pragma unroll
        for (int j = 0; j < 4; j++)
            g_A[base + (size_t)(qb * 64 + ty * 4 + i) * D_MODEL + tx * 4 + j]
                = acc[i][j] * inv;
    }
}

// ---------------- launch ----------------
extern "C" void kernel_launch(void* const* d_in, const int* in_sizes, int n_in,
                              void* d_out, int out_size) {
    const float* x  = (const float*)d_in[0];
    const float* wq = (const float*)d_in[1];
    const float* wk = (const float*)d_in[2];
    const float* wv = (const float*)d_in[3];
    const float* wo = (const float*)d_in[4];
    float* out = (float*)d_out;

    float *Q, *K, *V, *A;
    cudaGetSymbolAddress((void**)&Q, g_Q);
    cudaGetSymbolAddress((void**)&K, g_K);
    cudaGetSymbolAddress((void**)&V, g_V);
    cudaGetSymbolAddress((void**)&A, g_A);

    dim3 gemm_grid(D_MODEL / 64, MTOT / 64);   // (12, 64)
    gemm_nt<<<gemm_grid, 256>>>(x, wq, Q, MTOT, D_MODEL, D_MODEL);
    gemm_nt<<<gemm_grid, 256>>>(x, wk, K, MTOT, D_MODEL, D_MODEL);
    gemm_nt<<<gemm_grid, 256>>>(x, wv, V, MTOT, D_MODEL, D_MODEL);

    const int smem_bytes = 4 * 64 * LD * sizeof(float);   // 66560
    cudaFuncSetAttribute(attn_kernel,
                         cudaFuncAttributeMaxDynamicSharedMemorySize, smem_bytes);
    dim3 attn_grid(SEQ / 64, BATCH * NUM_HEADS);          // (32, 24)
    attn_kernel<<<attn_grid, 256, smem_bytes>>>();

    gemm_nt<<<gemm_grid, 256>>>(A, wo, out, MTOT, D_MODEL, D_MODEL);
}

// round 3
// speedup vs baseline: 1.3527x; 1.3527x over previous
#include <cuda_runtime.h>
#include <cuda_bf16.h>
#include <math.h>
#include <stdint.h>

#define D_MODEL 768
#define NUM_HEADS 12
#define DK 64
#define BATCH 2
#define SEQ 2048
#define MTOT (BATCH * SEQ)          // 4096
#define XN (MTOT * D_MODEL)         // 3145728
#define WN (D_MODEL * D_MODEL)      // 589824

// ---------------- scratch (no allocations allowed) ----------------
__device__ float g_Q[XN];
__device__ float g_K[XN];
__device__ float g_V[XN];
__device__ float g_A[XN];
__device__ __nv_bfloat16 g_xh[XN], g_xl[XN];
__device__ __nv_bfloat16 g_ah[XN], g_al[XN];
__device__ __nv_bfloat16 g_wh[4 * WN], g_wl[4 * WN];

// ---------------- helpers ----------------
__device__ __forceinline__ uint32_t smem_u32(const void* p) {
    uint32_t a;
    asm("{ .reg .u64 t; cvta.to.shared.u64 t, %1; cvt.u32.u64 %0, t; }"
        : "=r"(a) : "l"(p));
    return a;
}
__device__ __forceinline__ void cp16(uint32_t saddr, const void* gaddr) {
    asm volatile("cp.async.cg.shared.global [%0], [%1], 16;"
                 :: "r"(saddr), "l"(gaddr) : "memory");
}
__device__ __forceinline__ void ldm4(uint32_t* r, uint32_t addr) {
    asm volatile("ldmatrix.sync.aligned.m8n8.x4.shared.b16 {%0,%1,%2,%3}, [%4];"
                 : "=r"(r[0]), "=r"(r[1]), "=r"(r[2]), "=r"(r[3]) : "r"(addr));
}
__device__ __forceinline__ void mma_bf16(float* c, const uint32_t* a,
                                         uint32_t b0, uint32_t b1) {
    asm volatile(
        "mma.sync.aligned.m16n8k16.row.col.f32.bf16.bf16.f32 "
        "{%0,%1,%2,%3}, {%4,%5,%6,%7}, {%8,%9}, {%0,%1,%2,%3};"
        : "+f"(c[0]), "+f"(c[1]), "+f"(c[2]), "+f"(c[3])
        : "r"(a[0]), "r"(a[1]), "r"(a[2]), "r"(a[3]), "r"(b0), "r"(b1));
}

// ---------------- split fp32 -> bf16 hi/lo ----------------
__global__ __launch_bounds__(256)
void split_kernel(const float* __restrict__ src, __nv_bfloat16* __restrict__ hi,
                  __nv_bfloat16* __restrict__ lo, int n4) {
    int i = blockIdx.x * blockDim.x + threadIdx.x;
    if (i >= n4) return;
    float4 v = reinterpret_cast<const float4*>(src)[i];
    float vs[4] = {v.x, v.y, v.z, v.w};
    __nv_bfloat16 h[4], l[4];
    #pragma unroll
    for (int j = 0; j < 4; j++) {
        h[j] = __float2bfloat16(vs[j]);
        l[j] = __float2bfloat16(vs[j] - __bfloat162float(h[j]));
    }
    __nv_bfloat162* h2 = reinterpret_cast<__nv_bfloat162*>(hi);
    __nv_bfloat162* l2 = reinterpret_cast<__nv_bfloat162*>(lo);
    h2[2 * i + 0] = __nv_bfloat162(h[0], h[1]);
    h2[2 * i + 1] = __nv_bfloat162(h[2], h[3]);
    l2[2 * i + 0] = __nv_bfloat162(l[0], l[1]);
    l2[2 * i + 1] = __nv_bfloat162(l[2], l[3]);
}

// ---------------- mma.sync bf16-split NT GEMM ----------------
// C[m,n] = sum_k A[m,k]*B[n,k] via AhBh + AhBl + AlBh, fp32 accum.
// Block 128x128, BK=32, 256 threads (8 warps: 4 in M x 2 in N, warp = 32x64).
#define BM 128
#define BN 128
#define BK 32
#define PITCHB 80                    // smem row pitch bytes (32 bf16 + 16B pad)
#define TILE_BYTES (128 * PITCHB)    // 10240
#define OFF_AH 0
#define OFF_AL (1 * TILE_BYTES)
#define OFF_BH (2 * TILE_BYTES)
#define OFF_BL (3 * TILE_BYTES)
#define STAGE_BYTES (4 * TILE_BYTES) // 40960
#define GEMM_SMEM (2 * STAGE_BYTES)  // 81920

__device__ __forceinline__ void load_stage(
    uint32_t sbase, const __nv_bfloat16* Ah, const __nv_bfloat16* Al,
    const __nv_bfloat16* Bh, const __nv_bfloat16* Bl,
    int m0, int n0, int k0, int K, int tid) {
    #pragma unroll
    for (int l = 0; l < 2; l++) {
        int idx = tid + l * 256;
        int r = idx >> 2;            // 0..127
        int c = idx & 3;             // 4 x 16B per row
        uint32_t so = (uint32_t)(r * PITCHB + c * 16);
        size_t ga = (size_t)(m0 + r) * K + k0 + c * 8;
        cp16(sbase + OFF_AH + so, Ah + ga);
        cp16(sbase + OFF_AL + so, Al + ga);
        size_t gb = (size_t)(n0 + r) * K + k0 + c * 8;
        cp16(sbase + OFF_BH + so, Bh + gb);
        cp16(sbase + OFF_BL + so, Bl + gb);
    }
    asm volatile("cp.async.commit_group;" ::: "memory");
}

__global__ __launch_bounds__(256)
void gemm_mma(const __nv_bfloat16* __restrict__ Ah, const __nv_bfloat16* __restrict__ Al,
              const __nv_bfloat16* __restrict__ Bh, const __nv_bfloat16* __restrict__ Bl,
              float* __restrict__ C, int M, int N, int K) {
    extern __shared__ char smc[];
    const uint32_t sb = smem_u32(smc);
    const int tid = threadIdx.x;
    const int lane = tid & 31;
    const int wid = tid >> 5;
    const int wm = (wid & 3) * 32;   // warp M offset in block
    const int wn = (wid >> 2) * 64;  // warp N offset in block
    const int m0 = blockIdx.y * BM;
    const int n0 = blockIdx.x * BN;

    float acc[2][8][4] = {};

    // precomputed ldmatrix lane offsets (bytes within a tile)
    const int a_lr = lane & 15, a_lc = lane >> 4;           // A: 16 rows x 2 k-halves
    const int b_lr = lane & 7, b_kh = (lane >> 3) & 1, b_nh = lane >> 4;

    load_stage(sb, Ah, Al, Bh, Bl, m0, n0, 0, K, tid);

    const int nstage = K / BK;       // 24
    for (int kt = 0; kt < nstage; kt++) {
        if (kt + 1 < nstage)
            load_stage(sb + ((kt + 1) & 1) * STAGE_BYTES,
                       Ah, Al, Bh, Bl, m0, n0, (kt + 1) * BK, K, tid);
        if (kt + 1 < nstage)
            asm volatile("cp.async.wait_group 1;" ::: "memory");
        else
            asm volatile("cp.async.wait_group 0;" ::: "memory");
        __syncthreads();

        const uint32_t st = sb + (kt & 1) * STAGE_BYTES;
        #pragma unroll
        for (int kk = 0; kk < 2; kk++) {        // two k16 steps
            const uint32_t kcol = (uint32_t)((kk * 16 + a_lc * 8) * 2);
            uint32_t ah[2][4], al[2][4];
            #pragma unroll
            for (int mi = 0; mi < 2; mi++) {
                uint32_t ro = (uint32_t)((wm + mi * 16 + a_lr) * PITCHB) + kcol;
                ldm4(ah[mi], st + OFF_AH + ro);
                ldm4(al[mi], st + OFF_AL + ro);
            }
            const uint32_t bkcol = (uint32_t)((kk * 16 + b_kh * 8) * 2);
            uint32_t bh[4][4], bl[4][4];
            #pragma unroll
            for (int ni = 0; ni < 4; ni++) {
                uint32_t ro = (uint32_t)((wn + ni * 16 + b_lr + b_nh * 8) * PITCHB) + bkcol;
                ldm4(bh[ni], st + OFF_BH + ro);
                ldm4(bl[ni], st + OFF_BL + ro);
            }
            #pragma unroll
            for (int mi = 0; mi < 2; mi++)
                #pragma unroll
                for (int nj = 0; nj < 8; nj++) {
                    const int ni = nj >> 1, od = (nj & 1) * 2;
                    mma_bf16(acc[mi][nj], ah[mi], bh[ni][od], bh[ni][od + 1]);
                    mma_bf16(acc[mi][nj], al[mi], bh[ni][od], bh[ni][od + 1]);
                    mma_bf16(acc[mi][nj], ah[mi], bl[ni][od], bl[ni][od + 1]);
                }
        }
        __syncthreads();
    }

    // epilogue
    const int g = lane >> 2, t = lane & 3;
    #pragma unroll
    for (int mi = 0; mi < 2; mi++)
        #pragma unroll
        for (int nj = 0; nj < 8; nj++) {
            int row = m0 + wm + mi * 16 + g;
            int col = n0 + wn + nj * 8 + t * 2;
            *reinterpret_cast<float2*>(&C[(size_t)row * N + col]) =
                make_float2(acc[mi][nj][0], acc[mi][nj][1]);
            *reinterpret_cast<float2*>(&C[(size_t)(row + 8) * N + col]) =
                make_float2(acc[mi][nj][2], acc[mi][nj][3]);
        }
}

// ---------------- causal flash attention (fp32, vectorized smem) ----------------
#define LDA 68

__global__ __launch_bounds__(256)
void attn_kernel() {
    extern __shared__ float sm[];
    float (*Qt)[LDA] = (float(*)[LDA])(sm);                 // Qt[k][q]
    float (*Kt)[LDA] = (float(*)[LDA])(sm + 64 * LDA);      // Kt[k][n]
    float (*Vs)[LDA] = (float(*)[LDA])(sm + 2 * 64 * LDA);  // Vs[tok][n]
    float (*Ps)[LDA] = (float(*)[LDA])(sm + 3 * 64 * LDA);  // Ps[q][tok]

    const int tid = threadIdx.x;
    const int ty = tid >> 4;
    const int tx = tid & 15;
    const int qb = blockIdx.x;
    const int b  = blockIdx.y / NUM_HEADS;
    const int h  = blockIdx.y % NUM_HEADS;
    const float scale = 0.125f;

    const size_t base = (size_t)b * SEQ * D_MODEL + (size_t)h * DK;

    #pragma unroll
    for (int l = 0; l < 4; l++) {
        int idx = tid + l * 256;
        int r = idx >> 4;
        int c = (idx & 15) << 2;
        float4 v = *reinterpret_cast<const float4*>(
            &g_Q[base + (size_t)(qb * 64 + r) * D_MODEL + c]);
        Qt[c + 0][r] = v.x; Qt[c + 1][r] = v.y;
        Qt[c + 2][r] = v.z; Qt[c + 3][r] = v.w;
    }

    float acc[4][4] = {};
    float m_i[4], l_i[4];
    #pragma unroll
    for (int i = 0; i < 4; i++) { m_i[i] = -INFINITY; l_i[i] = 0.0f; }

    for (int kb = 0; kb <= qb; kb++) {
        __syncthreads();
        #pragma unroll
        for (int l = 0; l < 4; l++) {
            int idx = tid + l * 256;
            int r = idx >> 4;
            int c = (idx & 15) << 2;
            size_t goff = base + (size_t)(kb * 64 + r) * D_MODEL + c;
            float4 vk = *reinterpret_cast<const float4*>(&g_K[goff]);
            Kt[c + 0][r] = vk.x; Kt[c + 1][r] = vk.y;
            Kt[c + 2][r] = vk.z; Kt[c + 3][r] = vk.w;
            float4 vv = *reinterpret_cast<const float4*>(&g_V[goff]);
            *reinterpret_cast<float4*>(&Vs[r][c]) = vv;
        }
        __syncthreads();

        float s[4][4] = {};
        #pragma unroll 8
        for (int k = 0; k < 64; k++) {
            float4 a4 = *reinterpret_cast<const float4*>(&Qt[k][ty * 4]);
            float4 b4 = *reinterpret_cast<const float4*>(&Kt[k][tx * 4]);
            float a[4] = {a4.x, a4.y, a4.z, a4.w};
            float bb[4] = {b4.x, b4.y, b4.z, b4.w};
            #pragma unroll
            for (int i = 0; i < 4; i++)
                #pragma unroll
                for (int j = 0; j < 4; j++)
                    s[i][j] = fmaf(a[i], bb[j], s[i][j]);
        }

        const bool diag = (kb == qb);
        #pragma unroll
        for (int i = 0; i < 4; i++)
            #pragma unroll
            for (int j = 0; j < 4; j++) {
                s[i][j] *= scale;
                if (diag && (tx * 4 + j > ty * 4 + i)) s[i][j] = -INFINITY;
            }

        #pragma unroll
        for (int i = 0; i < 4; i++) {
            float rm = fmaxf(fmaxf(s[i][0], s[i][1]), fmaxf(s[i][2], s[i][3]));
            #pragma unroll
            for (int o = 8; o >= 1; o >>= 1)
                rm = fmaxf(rm, __shfl_xor_sync(0xffffffffu, rm, o));
            float mn = fmaxf(m_i[i], rm);
            float alpha = __expf(m_i[i] - mn);
            float rs = 0.0f;
            #pragma unroll
            for (int j = 0; j < 4; j++) {
                s[i][j] = __expf(s[i][j] - mn);
                rs += s[i][j];
            }
            #pragma unroll
            for (int o = 8; o >= 1; o >>= 1)
                rs += __shfl_xor_sync(0xffffffffu, rs, o);
            l_i[i] = l_i[i] * alpha + rs;
            m_i[i] = mn;
            #pragma unroll
            for (int j = 0; j < 4; j++) {
                acc[i][j] *= alpha;
                Ps[ty * 4 + i][tx * 4 + j] = s[i][j];
            }
        }
        __syncthreads();

        #pragma unroll 8
        for (int k = 0; k < 64; k++) {
            float4 v4 = *reinterpret_cast<const float4*>(&Vs[k][tx * 4]);
            float vv[4] = {v4.x, v4.y, v4.z, v4.w};
            float p[4];
            #pragma unroll
            for (int i = 0; i < 4; i++) p[i] = Ps[ty * 4 + i][k];
            #pragma unroll
            for (int i = 0; i < 4; i++)
                #pragma unroll
                for (int j = 0; j < 4; j++)
                    acc[i][j] = fmaf(p[i], vv[j], acc[i][j]);
        }
    }

    #pragma unroll
    for (int i = 0; i < 4; i++) {
        float inv = 1.0f / l_i[i];
        #pragma unroll
        for (int j = 0; j < 4; j++)
            g_A[base + (size_t)(qb * 64 + ty * 4 + i) * D_MODEL + tx * 4 + j]
                = acc[i][j] * inv;
    }
}

// ---------------- launch ----------------
extern "C" void kernel_launch(void* const* d_in, const int* in_sizes, int n_in,
                              void* d_out, int out_size) {
    const float* x  = (const float*)d_in[0];
    const float* wq = (const float*)d_in[1];
    const float* wk = (const float*)d_in[2];
    const float* wv = (const float*)d_in[3];
    const float* wo = (const float*)d_in[4];
    float* out = (float*)d_out;

    float *Q, *K, *V, *A;
    cudaGetSymbolAddress((void**)&Q, g_Q);
    cudaGetSymbolAddress((void**)&K, g_K);
    cudaGetSymbolAddress((void**)&V, g_V);
    cudaGetSymbolAddress((void**)&A, g_A);
    __nv_bfloat16 *xh, *xl, *ah, *al, *wh, *wl;
    cudaGetSymbolAddress((void**)&xh, g_xh);
    cudaGetSymbolAddress((void**)&xl, g_xl);
    cudaGetSymbolAddress((void**)&ah, g_ah);
    cudaGetSymbolAddress((void**)&al, g_al);
    cudaGetSymbolAddress((void**)&wh, g_wh);
    cudaGetSymbolAddress((void**)&wl, g_wl);

    // 1. split inputs
    split_kernel<<<(XN / 4 + 255) / 256, 256>>>(x, xh, xl, XN / 4);
    split_kernel<<<(WN / 4 + 255) / 256, 256>>>(wq, wh + 0 * WN, wl + 0 * WN, WN / 4);
    split_kernel<<<(WN / 4 + 255) / 256, 256>>>(wk, wh + 1 * WN, wl + 1 * WN, WN / 4);
    split_kernel<<<(WN / 4 + 255) / 256, 256>>>(wv, wh + 2 * WN, wl + 2 * WN, WN / 4);
    split_kernel<<<(WN / 4 + 255) / 256, 256>>>(wo, wh + 3 * WN, wl + 3 * WN, WN / 4);

    // 2. projections via mma.sync
    cudaFuncSetAttribute(gemm_mma, cudaFuncAttributeMaxDynamicSharedMemorySize, GEMM_SMEM);
    dim3 ggrid(D_MODEL / BN, MTOT / BM);   // (6, 32)
    gemm_mma<<<ggrid, 256, GEMM_SMEM>>>(xh, xl, wh + 0 * WN, wl + 0 * WN, Q,
                                        MTOT, D_MODEL, D_MODEL);
    gemm_mma<<<ggrid, 256, GEMM_SMEM>>>(xh, xl, wh + 1 * WN, wl + 1 * WN, K,
                                        MTOT, D_MODEL, D_MODEL);
    gemm_mma<<<ggrid, 256, GEMM_SMEM>>>(xh, xl, wh + 2 * WN, wl + 2 * WN, V,
                                        MTOT, D_MODEL, D_MODEL);

    // 3. attention
    const int asm_bytes = 4 * 64 * LDA * sizeof(float);   // 69632
    cudaFuncSetAttribute(attn_kernel,
                         cudaFuncAttributeMaxDynamicSharedMemorySize, asm_bytes);
    dim3 attn_grid(SEQ / 64, BATCH * NUM_HEADS);
    attn_kernel<<<attn_grid, 256, asm_bytes>>>();

    // 4. output projection
    split_kernel<<<(XN / 4 + 255) / 256, 256>>>(A, ah, al, XN / 4);
    gemm_mma<<<ggrid, 256, GEMM_SMEM>>>(ah, al, wh + 3 * WN, wl + 3 * WN, out,
                                        MTOT, D_MODEL, D_MODEL);
}

// round 4
// speedup vs baseline: 2.3286x; 1.7214x over previous
#include <cuda_runtime.h>
#include <cuda_bf16.h>
#include <math.h>
#include <stdint.h>

#define D_MODEL 768
#define NUM_HEADS 12
#define DK 64
#define BATCH 2
#define SEQ 2048
#define MTOT (BATCH * SEQ)          // 4096
#define XN (MTOT * D_MODEL)         // 3145728
#define WN (D_MODEL * D_MODEL)      // 589824

// ---------------- scratch ----------------
__device__ __nv_bfloat16 g_xh[XN], g_xl[XN];
__device__ __nv_bfloat16 g_qh[XN], g_ql[XN];
__device__ __nv_bfloat16 g_kh[XN], g_kl[XN];
__device__ __nv_bfloat16 g_vh[XN], g_vl[XN];
__device__ __nv_bfloat16 g_ah[XN], g_al[XN];
__device__ __nv_bfloat16 g_wh[4 * WN], g_wl[4 * WN];

// ---------------- helpers ----------------
__device__ __forceinline__ uint32_t smem_u32(const void* p) {
    uint32_t a;
    asm("{ .reg .u64 t; cvta.to.shared.u64 t, %1; cvt.u32.u64 %0, t; }"
        : "=r"(a) : "l"(p));
    return a;
}
__device__ __forceinline__ void cp16(uint32_t saddr, const void* gaddr) {
    asm volatile("cp.async.cg.shared.global [%0], [%1], 16;"
                 :: "r"(saddr), "l"(gaddr) : "memory");
}
__device__ __forceinline__ void ldm4(uint32_t* r, uint32_t addr) {
    asm volatile("ldmatrix.sync.aligned.m8n8.x4.shared.b16 {%0,%1,%2,%3}, [%4];"
                 : "=r"(r[0]), "=r"(r[1]), "=r"(r[2]), "=r"(r[3]) : "r"(addr));
}
__device__ __forceinline__ void ldm4t(uint32_t* r, uint32_t addr) {
    asm volatile("ldmatrix.sync.aligned.m8n8.x4.trans.shared.b16 {%0,%1,%2,%3}, [%4];"
                 : "=r"(r[0]), "=r"(r[1]), "=r"(r[2]), "=r"(r[3]) : "r"(addr));
}
__device__ __forceinline__ void mma_bf16(float* c, const uint32_t* a,
                                         uint32_t b0, uint32_t b1) {
    asm volatile(
        "mma.sync.aligned.m16n8k16.row.col.f32.bf16.bf16.f32 "
        "{%0,%1,%2,%3}, {%4,%5,%6,%7}, {%8,%9}, {%0,%1,%2,%3};"
        : "+f"(c[0]), "+f"(c[1]), "+f"(c[2]), "+f"(c[3])
        : "r"(a[0]), "r"(a[1]), "r"(a[2]), "r"(a[3]), "r"(b0), "r"(b1));
}
__device__ __forceinline__ uint32_t pack2(float x, float y) {
    __nv_bfloat162 v(__float2bfloat16_rn(x), __float2bfloat16_rn(y));
    return *reinterpret_cast<uint32_t*>(&v);
}
__device__ __forceinline__ void split2(float x, float y, uint32_t& h, uint32_t& l) {
    __nv_bfloat16 hx = __float2bfloat16_rn(x), hy = __float2bfloat16_rn(y);
    __nv_bfloat162 vh(hx, hy);
    __nv_bfloat162 vl(__float2bfloat16_rn(x - __bfloat162float(hx)),
                      __float2bfloat16_rn(y - __bfloat162float(hy)));
    h = *reinterpret_cast<uint32_t*>(&vh);
    l = *reinterpret_cast<uint32_t*>(&vl);
}

// ---------------- split fp32 -> bf16 hi/lo ----------------
__global__ __launch_bounds__(256)
void split_kernel(const float* __restrict__ src, __nv_bfloat16* __restrict__ hi,
                  __nv_bfloat16* __restrict__ lo, int n4) {
    int i = blockIdx.x * blockDim.x + threadIdx.x;
    if (i >= n4) return;
    float4 v = reinterpret_cast<const float4*>(src)[i];
    uint32_t h0, l0, h1, l1;
    split2(v.x, v.y, h0, l0);
    split2(v.z, v.w, h1, l1);
    reinterpret_cast<uint2*>(hi)[i] = make_uint2(h0, h1);
    reinterpret_cast<uint2*>(lo)[i] = make_uint2(l0, l1);
}

// ---------------- mma.sync bf16-split NT GEMM ----------------
#define BM 128
#define BN 128
#define BK 32
#define PITCHB 80
#define TILE_BYTES (128 * PITCHB)
#define OFF_AH 0
#define OFF_AL (1 * TILE_BYTES)
#define OFF_BH (2 * TILE_BYTES)
#define OFF_BL (3 * TILE_BYTES)
#define STAGE_BYTES (4 * TILE_BYTES)
#define GEMM_SMEM (2 * STAGE_BYTES)

__device__ __forceinline__ void load_stage(
    uint32_t sbase, const __nv_bfloat16* Ah, const __nv_bfloat16* Al,
    const __nv_bfloat16* Bh, const __nv_bfloat16* Bl,
    int m0, int n0, int k0, int K, int tid) {
    #pragma unroll
    for (int l = 0; l < 2; l++) {
        int idx = tid + l * 256;
        int r = idx >> 2;
        int c = idx & 3;
        uint32_t so = (uint32_t)(r * PITCHB + c * 16);
        size_t ga = (size_t)(m0 + r) * K + k0 + c * 8;
        cp16(sbase + OFF_AH + so, Ah + ga);
        cp16(sbase + OFF_AL + so, Al + ga);
        size_t gb = (size_t)(n0 + r) * K + k0 + c * 8;
        cp16(sbase + OFF_BH + so, Bh + gb);
        cp16(sbase + OFF_BL + so, Bl + gb);
    }
    asm volatile("cp.async.commit_group;" ::: "memory");
}

template<bool SPLIT_OUT>
__global__ __launch_bounds__(256)
void gemm_mma(const __nv_bfloat16* __restrict__ Ah, const __nv_bfloat16* __restrict__ Al,
              const __nv_bfloat16* __restrict__ Bh, const __nv_bfloat16* __restrict__ Bl,
              float* __restrict__ C, __nv_bfloat16* __restrict__ Ch,
              __nv_bfloat16* __restrict__ Cl, int M, int N, int K) {
    extern __shared__ char smc[];
    const uint32_t sb = smem_u32(smc);
    const int tid = threadIdx.x;
    const int lane = tid & 31;
    const int wid = tid >> 5;
    const int wm = (wid & 3) * 32;
    const int wn = (wid >> 2) * 64;
    const int m0 = blockIdx.y * BM;
    const int n0 = blockIdx.x * BN;

    float acc[2][8][4] = {};
    const int a_lr = lane & 15, a_lc = lane >> 4;
    const int b_lr = lane & 7, b_kh = (lane >> 3) & 1, b_nh = lane >> 4;

    load_stage(sb, Ah, Al, Bh, Bl, m0, n0, 0, K, tid);

    const int nstage = K / BK;
    for (int kt = 0; kt < nstage; kt++) {
        if (kt + 1 < nstage)
            load_stage(sb + ((kt + 1) & 1) * STAGE_BYTES,
                       Ah, Al, Bh, Bl, m0, n0, (kt + 1) * BK, K, tid);
        if (kt + 1 < nstage)
            asm volatile("cp.async.wait_group 1;" ::: "memory");
        else
            asm volatile("cp.async.wait_group 0;" ::: "memory");
        __syncthreads();

        const uint32_t st = sb + (kt & 1) * STAGE_BYTES;
        #pragma unroll
        for (int kk = 0; kk < 2; kk++) {
            const uint32_t kcol = (uint32_t)((kk * 16 + a_lc * 8) * 2);
            uint32_t ah[2][4], al[2][4];
            #pragma unroll
            for (int mi = 0; mi < 2; mi++) {
                uint32_t ro = (uint32_t)((wm + mi * 16 + a_lr) * PITCHB) + kcol;
                ldm4(ah[mi], st + OFF_AH + ro);
                ldm4(al[mi], st + OFF_AL + ro);
            }
            const uint32_t bkcol = (uint32_t)((kk * 16 + b_kh * 8) * 2);
            uint32_t bh[4][4], bl[4][4];
            #pragma unroll
            for (int ni = 0; ni < 4; ni++) {
                uint32_t ro = (uint32_t)((wn + ni * 16 + b_lr + b_nh * 8) * PITCHB) + bkcol;
                ldm4(bh[ni], st + OFF_BH + ro);
                ldm4(bl[ni], st + OFF_BL + ro);
            }
            #pragma unroll
            for (int mi = 0; mi < 2; mi++)
                #pragma unroll
                for (int nj = 0; nj < 8; nj++) {
                    const int ni = nj >> 1, od = (nj & 1) * 2;
                    mma_bf16(acc[mi][nj], ah[mi], bh[ni][od], bh[ni][od + 1]);
                    mma_bf16(acc[mi][nj], al[mi], bh[ni][od], bh[ni][od + 1]);
                    mma_bf16(acc[mi][nj], ah[mi], bl[ni][od], bl[ni][od + 1]);
                }
        }
        __syncthreads();
    }

    const int g = lane >> 2, t = lane & 3;
    #pragma unroll
    for (int mi = 0; mi < 2; mi++)
        #pragma unroll
        for (int nj = 0; nj < 8; nj++) {
            int row = m0 + wm + mi * 16 + g;
            int col = n0 + wn + nj * 8 + t * 2;
            if (SPLIT_OUT) {
                uint32_t h0, l0, h1, l1;
                split2(acc[mi][nj][0], acc[mi][nj][1], h0, l0);
                split2(acc[mi][nj][2], acc[mi][nj][3], h1, l1);
                *reinterpret_cast<uint32_t*>(&Ch[(size_t)row * N + col]) = h0;
                *reinterpret_cast<uint32_t*>(&Cl[(size_t)row * N + col]) = l0;
                *reinterpret_cast<uint32_t*>(&Ch[(size_t)(row + 8) * N + col]) = h1;
                *reinterpret_cast<uint32_t*>(&Cl[(size_t)(row + 8) * N + col]) = l1;
            } else {
                *reinterpret_cast<float2*>(&C[(size_t)row * N + col]) =
                    make_float2(acc[mi][nj][0], acc[mi][nj][1]);
                *reinterpret_cast<float2*>(&C[(size_t)(row + 8) * N + col]) =
                    make_float2(acc[mi][nj][2], acc[mi][nj][3]);
            }
        }
}

// ---------------- tensor-core causal flash attention ----------------
// CTA: 128 queries x one (b,h). 8 warps, 16 q-rows each. K/V tile = 64 keys.
#define P144 144
#define SQH 0
#define SQL 18432
#define SKV 36864
#define KVSTAGE 36864          // KH 0 | KL 9216 | VH 18432 | VL 27648
#define ATT_SMEM (SKV + 2 * KVSTAGE)   // 110592

__global__ __launch_bounds__(256, 2)
void attn_mma() {
    extern __shared__ char smc[];
    const uint32_t sb = smem_u32(smc);
    const int tid = threadIdx.x;
    const int lane = tid & 31;
    const int wid = tid >> 5;
    const int qb = (int)(gridDim.x - 1) - (int)blockIdx.x;   // heavy blocks first
    const int b = blockIdx.y / NUM_HEADS;
    const int h = blockIdx.y % NUM_HEADS;
    const int wm = wid * 16;
    const int g = lane >> 2, t = lane & 3;
    const float scale = 0.125f;

    const size_t qrow0 = (size_t)b * SEQ + (size_t)qb * 128;
    const size_t krow0 = (size_t)b * SEQ;
    const size_t hoff = (size_t)h * DK;

    // Q tiles (hi+lo), persistent
    #pragma unroll
    for (int l = 0; l < 4; l++) {
        int idx = tid + l * 256;
        int r = idx >> 3, c = idx & 7;
        size_t ga = (qrow0 + r) * D_MODEL + hoff + c * 8;
        uint32_t so = (uint32_t)(r * P144 + c * 16);
        cp16(sb + SQH + so, g_qh + ga);
        cp16(sb + SQL + so, g_ql + ga);
    }

    const int ntiles = 2 * qb + 2;
    auto load_kv = [&](int kt, int buf) {
        uint32_t stb = sb + SKV + (uint32_t)buf * KVSTAGE;
        #pragma unroll
        for (int l = 0; l < 2; l++) {
            int idx = tid + l * 256;
            int r = idx >> 3, c = idx & 7;
            size_t ga = (krow0 + (size_t)kt * 64 + r) * D_MODEL + hoff + c * 8;
            uint32_t so = (uint32_t)(r * P144 + c * 16);
            cp16(stb + so, g_kh + ga);
            cp16(stb + 9216 + so, g_kl + ga);
            cp16(stb + 18432 + so, g_vh + ga);
            cp16(stb + 27648 + so, g_vl + ga);
        }
        asm volatile("cp.async.commit_group;" ::: "memory");
    };

    load_kv(0, 0);
    if (ntiles > 1) load_kv(1, 1);

    float oacc[8][4] = {};
    float m_i[2] = {-INFINITY, -INFINITY};
    float l_i[2] = {0.0f, 0.0f};

    const int a_lr = lane & 15, a_lc = lane >> 4;
    const int b_lr = lane & 7, b_kh = (lane >> 3) & 1, b_nh = lane >> 4;
    const int v_r = lane & 15, v_c = (lane >> 4) * 8;

    for (int kt = 0; kt < ntiles; kt++) {
        if (kt + 1 < ntiles)
            asm volatile("cp.async.wait_group 1;" ::: "memory");
        else
            asm volatile("cp.async.wait_group 0;" ::: "memory");
        __syncthreads();

        const uint32_t stb = sb + SKV + (uint32_t)(kt & 1) * KVSTAGE;

        // ---- S = Q K^T (3 split products), fp32 accum ----
        float sacc[8][4] = {};
        #pragma unroll
        for (int kk = 0; kk < 4; kk++) {
            const uint32_t kcol = (uint32_t)((kk * 16 + a_lc * 8) * 2);
            uint32_t qh[4], ql[4];
            ldm4(qh, sb + SQH + (uint32_t)((wm + a_lr) * P144) + kcol);
            ldm4(ql, sb + SQL + (uint32_t)((wm + a_lr) * P144) + kcol);
            const uint32_t bkcol = (uint32_t)((kk * 16 + b_kh * 8) * 2);
            #pragma unroll
            for (int np = 0; np < 4; np++) {
                uint32_t kh[4], kl[4];
                uint32_t ro = (uint32_t)((np * 16 + b_lr + b_nh * 8) * P144) + bkcol;
                ldm4(kh, stb + ro);
                ldm4(kl, stb + 9216 + ro);
                mma_bf16(sacc[2 * np],     qh, kh[0], kh[1]);
                mma_bf16(sacc[2 * np],     ql, kh[0], kh[1]);
                mma_bf16(sacc[2 * np],     qh, kl[0], kl[1]);
                mma_bf16(sacc[2 * np + 1], qh, kh[2], kh[3]);
                mma_bf16(sacc[2 * np + 1], ql, kh[2], kh[3]);
                mma_bf16(sacc[2 * np + 1], qh, kl[2], kl[3]);
            }
        }

        // scale + causal mask (only diagonal-region tiles)
        if (kt >= 2 * qb) {
            const int grow0 = qb * 128 + wm + g;
            #pragma unroll
            for (int nt = 0; nt < 8; nt++) {
                const int gcol = kt * 64 + nt * 8 + t * 2;
                #pragma unroll
                for (int j = 0; j < 4; j++) {
                    const int row = grow0 + (j >> 1) * 8;
                    const int col = gcol + (j & 1);
                    sacc[nt][j] = (col > row) ? -INFINITY : sacc[nt][j] * scale;
                }
            }
        } else {
            #pragma unroll
            for (int nt = 0; nt < 8; nt++)
                #pragma unroll
                for (int j = 0; j < 4; j++) sacc[nt][j] *= scale;
        }

        // ---- online softmax per row-half ----
        #pragma unroll
        for (int hh = 0; hh < 2; hh++) {
            float rm = -INFINITY;
            #pragma unroll
            for (int nt = 0; nt < 8; nt++)
                rm = fmaxf(rm, fmaxf(sacc[nt][2 * hh], sacc[nt][2 * hh + 1]));
            rm = fmaxf(rm, __shfl_xor_sync(0xffffffffu, rm, 1));
            rm = fmaxf(rm, __shfl_xor_sync(0xffffffffu, rm, 2));
            float mn = fmaxf(m_i[hh], rm);
            float alpha = __expf(m_i[hh] - mn);
            float rs = 0.0f;
            #pragma unroll
            for (int nt = 0; nt < 8; nt++) {
                float p0 = __expf(sacc[nt][2 * hh] - mn);
                float p1 = __expf(sacc[nt][2 * hh + 1] - mn);
                sacc[nt][2 * hh] = p0;
                sacc[nt][2 * hh + 1] = p1;
                rs += p0 + p1;
            }
            rs += __shfl_xor_sync(0xffffffffu, rs, 1);
            rs += __shfl_xor_sync(0xffffffffu, rs, 2);
            l_i[hh] = l_i[hh] * alpha + rs;
            m_i[hh] = mn;
            #pragma unroll
            for (int nt = 0; nt < 8; nt++) {
                oacc[nt][2 * hh] *= alpha;
                oacc[nt][2 * hh + 1] *= alpha;
            }
        }

        // ---- O += P V (3 split products); P packed from S fragments ----
        #pragma unroll
        for (int ks = 0; ks < 4; ks++) {
            uint32_t ph[4], pl[4];
            split2(sacc[2 * ks][0],     sacc[2 * ks][1],     ph[0], pl[0]);
            split2(sacc[2 * ks][2],     sacc[2 * ks][3],     ph[1], pl[1]);
            split2(sacc[2 * ks + 1][0], sacc[2 * ks + 1][1], ph[2], pl[2]);
            split2(sacc[2 * ks + 1][2], sacc[2 * ks + 1][3], ph[3], pl[3]);
            const uint32_t vrow = (uint32_t)((ks * 16 + v_r) * P144);
            #pragma unroll
            for (int np = 0; np < 4; np++) {
                uint32_t vh[4], vl[4];
                uint32_t vo = vrow + (uint32_t)((np * 16 + v_c) * 2);
                ldm4t(vh, stb + 18432 + vo);
                ldm4t(vl, stb + 27648 + vo);
                mma_bf16(oacc[2 * np],     ph, vh[0], vh[1]);
                mma_bf16(oacc[2 * np],     pl, vh[0], vh[1]);
                mma_bf16(oacc[2 * np],     ph, vl[0], vl[1]);
                mma_bf16(oacc[2 * np + 1], ph, vh[2], vh[3]);
                mma_bf16(oacc[2 * np + 1], pl, vh[2], vh[3]);
                mma_bf16(oacc[2 * np + 1], ph, vl[2], vl[3]);
            }
        }

        __syncthreads();
        if (kt + 2 < ntiles) load_kv(kt + 2, kt & 1);
    }

    // epilogue: normalize, split, store bf16 hi/lo
    const float inv0 = 1.0f / l_i[0], inv1 = 1.0f / l_i[1];
    #pragma unroll
    for (int nt = 0; nt < 8; nt++) {
        size_t r0 = (qrow0 + wm + g) * D_MODEL + hoff + nt * 8 + t * 2;
        size_t r1 = r0 + 8 * D_MODEL;
        uint32_t h0, l0, h1, l1;
        split2(oacc[nt][0] * inv0, oacc[nt][1] * inv0, h0, l0);
        split2(oacc[nt][2] * inv1, oacc[nt][3] * inv1, h1, l1);
        *reinterpret_cast<uint32_t*>(&g_ah[r0]) = h0;
        *reinterpret_cast<uint32_t*>(&g_al[r0]) = l0;
        *reinterpret_cast<uint32_t*>(&g_ah[r1]) = h1;
        *reinterpret_cast<uint32_t*>(&g_al[r1]) = l1;
    }
}

// ---------------- launch ----------------
extern "C" void kernel_launch(void* const* d_in, const int* in_sizes, int n_in,
                              void* d_out, int out_size) {
    const float* x  = (const float*)d_in[0];
    const float* wq = (const float*)d_in[1];
    const float* wk = (const float*)d_in[2];
    const float* wv = (const float*)d_in[3];
    const float* wo = (const float*)d_in[4];
    float* out = (float*)d_out;

    __nv_bfloat16 *xh, *xl, *qh, *ql, *kh, *kl, *vh, *vl, *ah, *al, *wh, *wl;
    cudaGetSymbolAddress((void**)&xh, g_xh);
    cudaGetSymbolAddress((void**)&xl, g_xl);
    cudaGetSymbolAddress((void**)&qh, g_qh);
    cudaGetSymbolAddress((void**)&ql, g_ql);
    cudaGetSymbolAddress((void**)&kh, g_kh);
    cudaGetSymbolAddress((void**)&kl, g_kl);
    cudaGetSymbolAddress((void**)&vh, g_vh);
    cudaGetSymbolAddress((void**)&vl, g_vl);
    cudaGetSymbolAddress((void**)&ah, g_ah);
    cudaGetSymbolAddress((void**)&al, g_al);
    cudaGetSymbolAddress((void**)&wh, g_wh);
    cudaGetSymbolAddress((void**)&wl, g_wl);

    // 1. splits
    split_kernel<<<(XN / 4 + 255) / 256, 256>>>(x, xh, xl, XN / 4);
    split_kernel<<<(WN / 4 + 255) / 256, 256>>>(wq, wh + 0 * WN, wl + 0 * WN, WN / 4);
    split_kernel<<<(WN / 4 + 255) / 256, 256>>>(wk, wh + 1 * WN, wl + 1 * WN, WN / 4);
    split_kernel<<<(WN / 4 + 255) / 256, 256>>>(wv, wh + 2 * WN, wl + 2 * WN, WN / 4);
    split_kernel<<<(WN / 4 + 255) / 256, 256>>>(wo, wh + 3 * WN, wl + 3 * WN, WN / 4);

    // 2. projections -> bf16 hi/lo directly
    cudaFuncSetAttribute(gemm_mma<true>, cudaFuncAttributeMaxDynamicSharedMemorySize, GEMM_SMEM);
    cudaFuncSetAttribute(gemm_mma<false>, cudaFuncAttributeMaxDynamicSharedMemorySize, GEMM_SMEM);
    dim3 ggrid(D_MODEL / BN, MTOT / BM);
    gemm_mma<true><<<ggrid, 256, GEMM_SMEM>>>(xh, xl, wh + 0 * WN, wl + 0 * WN,
                                              nullptr, qh, ql, MTOT, D_MODEL, D_MODEL);
    gemm_mma<true><<<ggrid, 256, GEMM_SMEM>>>(xh, xl, wh + 1 * WN, wl + 1 * WN,
                                              nullptr, kh, kl, MTOT, D_MODEL, D_MODEL);
    gemm_mma<true><<<ggrid, 256, GEMM_SMEM>>>(xh, xl, wh + 2 * WN, wl + 2 * WN,
                                              nullptr, vh, vl, MTOT, D_MODEL, D_MODEL);

    // 3. tensor-core flash attention
    cudaFuncSetAttribute(attn_mma, cudaFuncAttributeMaxDynamicSharedMemorySize, ATT_SMEM);
    dim3 agrid(SEQ / 128, BATCH * NUM_HEADS);   // (16, 24)
    attn_mma<<<agrid, 256, ATT_SMEM>>>();

    // 4. output projection -> fp32
    gemm_mma<false><<<ggrid, 256, GEMM_SMEM>>>(ah, al, wh + 3 * WN, wl + 3 * WN,
                                               out, nullptr, nullptr, MTOT, D_MODEL, D_MODEL);
}

// round 5
// speedup vs baseline: 2.7848x; 1.1959x over previous
#include <cuda_runtime.h>
#include <cuda_bf16.h>
#include <math.h>
#include <stdint.h>

#define D_MODEL 768
#define NUM_HEADS 12
#define DK 64
#define BATCH 2
#define SEQ 2048
#define MTOT (BATCH * SEQ)          // 4096
#define XN (MTOT * D_MODEL)         // 3145728
#define WN (D_MODEL * D_MODEL)      // 589824
#define D_QKV 2304                  // fused Q|K|V column dim

// ---------------- scratch ----------------
__device__ __nv_bfloat16 g_xh[XN], g_xl[XN];
__device__ __nv_bfloat16 g_qkvh[MTOT * D_QKV], g_qkvl[MTOT * D_QKV];
__device__ __nv_bfloat16 g_ah[XN], g_al[XN];
__device__ __nv_bfloat16 g_wh[4 * WN], g_wl[4 * WN];

// ---------------- helpers ----------------
__device__ __forceinline__ uint32_t smem_u32(const void* p) {
    uint32_t a;
    asm("{ .reg .u64 t; cvta.to.shared.u64 t, %1; cvt.u32.u64 %0, t; }"
        : "=r"(a) : "l"(p));
    return a;
}
__device__ __forceinline__ void cp16(uint32_t saddr, const void* gaddr) {
    asm volatile("cp.async.cg.shared.global [%0], [%1], 16;"
                 :: "r"(saddr), "l"(gaddr) : "memory");
}
__device__ __forceinline__ void ldm4(uint32_t* r, uint32_t addr) {
    asm volatile("ldmatrix.sync.aligned.m8n8.x4.shared.b16 {%0,%1,%2,%3}, [%4];"
                 : "=r"(r[0]), "=r"(r[1]), "=r"(r[2]), "=r"(r[3]) : "r"(addr));
}
__device__ __forceinline__ void ldm4t(uint32_t* r, uint32_t addr) {
    asm volatile("ldmatrix.sync.aligned.m8n8.x4.trans.shared.b16 {%0,%1,%2,%3}, [%4];"
                 : "=r"(r[0]), "=r"(r[1]), "=r"(r[2]), "=r"(r[3]) : "r"(addr));
}
__device__ __forceinline__ void mma_bf16(float* c, const uint32_t* a,
                                         uint32_t b0, uint32_t b1) {
    asm volatile(
        "mma.sync.aligned.m16n8k16.row.col.f32.bf16.bf16.f32 "
        "{%0,%1,%2,%3}, {%4,%5,%6,%7}, {%8,%9}, {%0,%1,%2,%3};"
        : "+f"(c[0]), "+f"(c[1]), "+f"(c[2]), "+f"(c[3])
        : "r"(a[0]), "r"(a[1]), "r"(a[2]), "r"(a[3]), "r"(b0), "r"(b1));
}
__device__ __forceinline__ void split2(float x, float y, uint32_t& h, uint32_t& l) {
    __nv_bfloat16 hx = __float2bfloat16_rn(x), hy = __float2bfloat16_rn(y);
    __nv_bfloat162 vh(hx, hy);
    __nv_bfloat162 vl(__float2bfloat16_rn(x - __bfloat162float(hx)),
                      __float2bfloat16_rn(y - __bfloat162float(hy)));
    h = *reinterpret_cast<uint32_t*>(&vh);
    l = *reinterpret_cast<uint32_t*>(&vl);
}

// ---------------- split fp32 -> bf16 hi/lo ----------------
__global__ __launch_bounds__(256)
void split_kernel(const float* __restrict__ src, __nv_bfloat16* __restrict__ hi,
                  __nv_bfloat16* __restrict__ lo, int n4) {
    int i = blockIdx.x * blockDim.x + threadIdx.x;
    if (i >= n4) return;
    float4 v = reinterpret_cast<const float4*>(src)[i];
    uint32_t h0, l0, h1, l1;
    split2(v.x, v.y, h0, l0);
    split2(v.z, v.w, h1, l1);
    reinterpret_cast<uint2*>(hi)[i] = make_uint2(h0, h1);
    reinterpret_cast<uint2*>(lo)[i] = make_uint2(l0, l1);
}

// ---------------- mma.sync bf16-split NT GEMM ----------------
// Block 256x128, BK=32, 8 warps (4 in M x 2 in N), warp tile 64x64.
#define BM 256
#define BN 128
#define BK 32
#define PITCHB 80
#define ATILE (256 * PITCHB)         // 20480
#define BTILE (128 * PITCHB)         // 10240
#define OFF_AH 0
#define OFF_AL ATILE
#define OFF_BH (2 * ATILE)
#define OFF_BL (2 * ATILE + BTILE)
#define STAGE_BYTES (2 * ATILE + 2 * BTILE)   // 61440
#define GEMM_SMEM (2 * STAGE_BYTES)           // 122880

__device__ __forceinline__ void load_stage(
    uint32_t sbase, const __nv_bfloat16* Ah, const __nv_bfloat16* Al,
    const __nv_bfloat16* Bh, const __nv_bfloat16* Bl,
    int m0, int n0, int k0, int K, int tid) {
    #pragma unroll
    for (int l = 0; l < 4; l++) {               // A: 256 rows x 4 x 16B
        int idx = tid + l * 256;
        int r = idx >> 2;
        int c = idx & 3;
        uint32_t so = (uint32_t)(r * PITCHB + c * 16);
        size_t ga = (size_t)(m0 + r) * K + k0 + c * 8;
        cp16(sbase + OFF_AH + so, Ah + ga);
        cp16(sbase + OFF_AL + so, Al + ga);
    }
    #pragma unroll
    for (int l = 0; l < 2; l++) {               // B: 128 rows x 4 x 16B
        int idx = tid + l * 256;
        int r = idx >> 2;
        int c = idx & 3;
        uint32_t so = (uint32_t)(r * PITCHB + c * 16);
        size_t gb = (size_t)(n0 + r) * K + k0 + c * 8;
        cp16(sbase + OFF_BH + so, Bh + gb);
        cp16(sbase + OFF_BL + so, Bl + gb);
    }
    asm volatile("cp.async.commit_group;" ::: "memory");
}

template<bool SPLIT_OUT>
__global__ __launch_bounds__(256)
void gemm_mma(const __nv_bfloat16* __restrict__ Ah, const __nv_bfloat16* __restrict__ Al,
              const __nv_bfloat16* __restrict__ Bh, const __nv_bfloat16* __restrict__ Bl,
              float* __restrict__ C, __nv_bfloat16* __restrict__ Ch,
              __nv_bfloat16* __restrict__ Cl, int M, int N, int K) {
    extern __shared__ char smc[];
    const uint32_t sb = smem_u32(smc);
    const int tid = threadIdx.x;
    const int lane = tid & 31;
    const int wid = tid >> 5;
    const int wm = (wid & 3) * 64;
    const int wn = (wid >> 2) * 64;
    const int m0 = blockIdx.y * BM;
    const int n0 = blockIdx.x * BN;

    float acc[4][8][4] = {};
    const int a_lr = lane & 15, a_lc = lane >> 4;
    const int b_lr = lane & 7, b_kh = (lane >> 3) & 1, b_nh = lane >> 4;

    load_stage(sb, Ah, Al, Bh, Bl, m0, n0, 0, K, tid);

    const int nstage = K / BK;
    for (int kt = 0; kt < nstage; kt++) {
        if (kt + 1 < nstage)
            load_stage(sb + ((kt + 1) & 1) * STAGE_BYTES,
                       Ah, Al, Bh, Bl, m0, n0, (kt + 1) * BK, K, tid);
        if (kt + 1 < nstage)
            asm volatile("cp.async.wait_group 1;" ::: "memory");
        else
            asm volatile("cp.async.wait_group 0;" ::: "memory");
        __syncthreads();

        const uint32_t st = sb + (kt & 1) * STAGE_BYTES;
        #pragma unroll
        for (int kk = 0; kk < 2; kk++) {
            const uint32_t kcol = (uint32_t)((kk * 16 + a_lc * 8) * 2);
            uint32_t ah[4][4], al[4][4];
            #pragma unroll
            for (int mi = 0; mi < 4; mi++) {
                uint32_t ro = (uint32_t)((wm + mi * 16 + a_lr) * PITCHB) + kcol;
                ldm4(ah[mi], st + OFF_AH + ro);
                ldm4(al[mi], st + OFF_AL + ro);
            }
            const uint32_t bkcol = (uint32_t)((kk * 16 + b_kh * 8) * 2);
            uint32_t bh[4][4], bl[4][4];
            #pragma unroll
            for (int ni = 0; ni < 4; ni++) {
                uint32_t ro = (uint32_t)((wn + ni * 16 + b_lr + b_nh * 8) * PITCHB) + bkcol;
                ldm4(bh[ni], st + OFF_BH + ro);
                ldm4(bl[ni], st + OFF_BL + ro);
            }
            #pragma unroll
            for (int mi = 0; mi < 4; mi++)
                #pragma unroll
                for (int nj = 0; nj < 8; nj++) {
                    const int ni = nj >> 1, od = (nj & 1) * 2;
                    mma_bf16(acc[mi][nj], ah[mi], bh[ni][od], bh[ni][od + 1]);
                    mma_bf16(acc[mi][nj], al[mi], bh[ni][od], bh[ni][od + 1]);
                    mma_bf16(acc[mi][nj], ah[mi], bl[ni][od], bl[ni][od + 1]);
                }
        }
        __syncthreads();
    }

    const int g = lane >> 2, t = lane & 3;
    #pragma unroll
    for (int mi = 0; mi < 4; mi++)
        #pragma unroll
        for (int nj = 0; nj < 8; nj++) {
            int row = m0 + wm + mi * 16 + g;
            int col = n0 + wn + nj * 8 + t * 2;
            if (SPLIT_OUT) {
                uint32_t h0, l0, h1, l1;
                split2(acc[mi][nj][0], acc[mi][nj][1], h0, l0);
                split2(acc[mi][nj][2], acc[mi][nj][3], h1, l1);
                *reinterpret_cast<uint32_t*>(&Ch[(size_t)row * N + col]) = h0;
                *reinterpret_cast<uint32_t*>(&Cl[(size_t)row * N + col]) = l0;
                *reinterpret_cast<uint32_t*>(&Ch[(size_t)(row + 8) * N + col]) = h1;
                *reinterpret_cast<uint32_t*>(&Cl[(size_t)(row + 8) * N + col]) = l1;
            } else {
                *reinterpret_cast<float2*>(&C[(size_t)row * N + col]) =
                    make_float2(acc[mi][nj][0], acc[mi][nj][1]);
                *reinterpret_cast<float2*>(&C[(size_t)(row + 8) * N + col]) =
                    make_float2(acc[mi][nj][2], acc[mi][nj][3]);
            }
        }
}

// ---------------- tensor-core causal flash attention ----------------
// Q/K/V read from the fused [MTOT][D_QKV] buffers (stride 2304).
#define P144 144
#define SQH 0
#define SQL 18432
#define SKV 36864
#define KVSTAGE 36864          // KH 0 | KL 9216 | VH 18432 | VL 27648
#define ATT_SMEM (SKV + 2 * KVSTAGE)   // 110592

__global__ __launch_bounds__(256, 2)
void attn_mma() {
    extern __shared__ char smc[];
    const uint32_t sb = smem_u32(smc);
    const int tid = threadIdx.x;
    const int lane = tid & 31;
    const int wid = tid >> 5;
    const int qb = (int)(gridDim.x - 1) - (int)blockIdx.x;
    const int b = blockIdx.y / NUM_HEADS;
    const int h = blockIdx.y % NUM_HEADS;
    const int wm = wid * 16;
    const int g = lane >> 2, t = lane & 3;
    const float scale = 0.125f;

    const size_t qrow0 = (size_t)b * SEQ + (size_t)qb * 128;
    const size_t krow0 = (size_t)b * SEQ;
    const size_t qoff = (size_t)h * DK;            // Q cols [0,768)
    const size_t koff = 768 + (size_t)h * DK;      // K cols [768,1536)
    const size_t voff = 1536 + (size_t)h * DK;     // V cols [1536,2304)

    #pragma unroll
    for (int l = 0; l < 4; l++) {
        int idx = tid + l * 256;
        int r = idx >> 3, c = idx & 7;
        size_t ga = (qrow0 + r) * D_QKV + qoff + c * 8;
        uint32_t so = (uint32_t)(r * P144 + c * 16);
        cp16(sb + SQH + so, g_qkvh + ga);
        cp16(sb + SQL + so, g_qkvl + ga);
    }

    const int ntiles = 2 * qb + 2;
    auto load_kv = [&](int kt, int buf) {
        uint32_t stb = sb + SKV + (uint32_t)buf * KVSTAGE;
        #pragma unroll
        for (int l = 0; l < 2; l++) {
            int idx = tid + l * 256;
            int r = idx >> 3, c = idx & 7;
            size_t grow = (krow0 + (size_t)kt * 64 + r) * D_QKV;
            uint32_t so = (uint32_t)(r * P144 + c * 16);
            cp16(stb + so, g_qkvh + grow + koff + c * 8);
            cp16(stb + 9216 + so, g_qkvl + grow + koff + c * 8);
            cp16(stb + 18432 + so, g_qkvh + grow + voff + c * 8);
            cp16(stb + 27648 + so, g_qkvl + grow + voff + c * 8);
        }
        asm volatile("cp.async.commit_group;" ::: "memory");
    };

    load_kv(0, 0);
    if (ntiles > 1) load_kv(1, 1);

    float oacc[8][4] = {};
    float m_i[2] = {-INFINITY, -INFINITY};
    float l_i[2] = {0.0f, 0.0f};

    const int a_lr = lane & 15, a_lc = lane >> 4;
    const int b_lr = lane & 7, b_kh = (lane >> 3) & 1, b_nh = lane >> 4;
    const int v_r = lane & 15, v_c = (lane >> 4) * 8;

    for (int kt = 0; kt < ntiles; kt++) {
        if (kt + 1 < ntiles)
            asm volatile("cp.async.wait_group 1;" ::: "memory");
        else
            asm volatile("cp.async.wait_group 0;" ::: "memory");
        __syncthreads();

        const uint32_t stb = sb + SKV + (uint32_t)(kt & 1) * KVSTAGE;

        float sacc[8][4] = {};
        #pragma unroll
        for (int kk = 0; kk < 4; kk++) {
            const uint32_t kcol = (uint32_t)((kk * 16 + a_lc * 8) * 2);
            uint32_t qh[4], ql[4];
            ldm4(qh, sb + SQH + (uint32_t)((wm + a_lr) * P144) + kcol);
            ldm4(ql, sb + SQL + (uint32_t)((wm + a_lr) * P144) + kcol);
            const uint32_t bkcol = (uint32_t)((kk * 16 + b_kh * 8) * 2);
            #pragma unroll
            for (int np = 0; np < 4; np++) {
                uint32_t kh[4], kl[4];
                uint32_t ro = (uint32_t)((np * 16 + b_lr + b_nh * 8) * P144) + bkcol;
                ldm4(kh, stb + ro);
                ldm4(kl, stb + 9216 + ro);
                mma_bf16(sacc[2 * np],     qh, kh[0], kh[1]);
                mma_bf16(sacc[2 * np],     ql, kh[0], kh[1]);
                mma_bf16(sacc[2 * np],     qh, kl[0], kl[1]);
                mma_bf16(sacc[2 * np + 1], qh, kh[2], kh[3]);
                mma_bf16(sacc[2 * np + 1], ql, kh[2], kh[3]);
                mma_bf16(sacc[2 * np + 1], qh, kl[2], kl[3]);
            }
        }

        if (kt >= 2 * qb) {
            const int grow0 = qb * 128 + wm + g;
            #pragma unroll
            for (int nt = 0; nt < 8; nt++) {
                const int gcol = kt * 64 + nt * 8 + t * 2;
                #pragma unroll
                for (int j = 0; j < 4; j++) {
                    const int row = grow0 + (j >> 1) * 8;
                    const int col = gcol + (j & 1);
                    sacc[nt][j] = (col > row) ? -INFINITY : sacc[nt][j] * scale;
                }
            }
        } else {
            #pragma unroll
            for (int nt = 0; nt < 8; nt++)
                #pragma unroll
                for (int j = 0; j < 4; j++) sacc[nt][j] *= scale;
        }

        #pragma unroll
        for (int hh = 0; hh < 2; hh++) {
            float rm = -INFINITY;
            #pragma unroll
            for (int nt = 0; nt < 8; nt++)
                rm = fmaxf(rm, fmaxf(sacc[nt][2 * hh], sacc[nt][2 * hh + 1]));
            rm = fmaxf(rm, __shfl_xor_sync(0xffffffffu, rm, 1));
            rm = fmaxf(rm, __shfl_xor_sync(0xffffffffu, rm, 2));
            float mn = fmaxf(m_i[hh], rm);
            float alpha = __expf(m_i[hh] - mn);
            float rs = 0.0f;
            #pragma unroll
            for (int nt = 0; nt < 8; nt++) {
                float p0 = __expf(sacc[nt][2 * hh] - mn);
                float p1 = __expf(sacc[nt][2 * hh + 1] - mn);
                sacc[nt][2 * hh] = p0;
                sacc[nt][2 * hh + 1] = p1;
                rs += p0 + p1;
            }
            rs += __shfl_xor_sync(0xffffffffu, rs, 1);
            rs += __shfl_xor_sync(0xffffffffu, rs, 2);
            l_i[hh] = l_i[hh] * alpha + rs;
            m_i[hh] = mn;
            #pragma unroll
            for (int nt = 0; nt < 8; nt++) {
                oacc[nt][2 * hh] *= alpha;
                oacc[nt][2 * hh + 1] *= alpha;
            }
        }

        #pragma unroll
        for (int ks = 0; ks < 4; ks++) {
            uint32_t ph[4], pl[4];
            split2(sacc[2 * ks][0],     sacc[2 * ks][1],     ph[0], pl[0]);
            split2(sacc[2 * ks][2],     sacc[2 * ks][3],     ph[1], pl[1]);
            split2(sacc[2 * ks + 1][0], sacc[2 * ks + 1][1], ph[2], pl[2]);
            split2(sacc[2 * ks + 1][2], sacc[2 * ks + 1][3], ph[3], pl[3]);
            const uint32_t vrow = (uint32_t)((ks * 16 + v_r) * P144);
            #pragma unroll
            for (int np = 0; np < 4; np++) {
                uint32_t vh[4], vl[4];
                uint32_t vo = vrow + (uint32_t)((np * 16 + v_c) * 2);
                ldm4t(vh, stb + 18432 + vo);
                ldm4t(vl, stb + 27648 + vo);
                mma_bf16(oacc[2 * np],     ph, vh[0], vh[1]);
                mma_bf16(oacc[2 * np],     pl, vh[0], vh[1]);
                mma_bf16(oacc[2 * np],     ph, vl[0], vl[1]);
                mma_bf16(oacc[2 * np + 1], ph, vh[2], vh[3]);
                mma_bf16(oacc[2 * np + 1], pl, vh[2], vh[3]);
                mma_bf16(oacc[2 * np + 1], ph, vl[2], vl[3]);
            }
        }

        __syncthreads();
        if (kt + 2 < ntiles) load_kv(kt + 2, kt & 1);
    }

    const float inv0 = 1.0f / l_i[0], inv1 = 1.0f / l_i[1];
    const size_t hoff = (size_t)h * DK;
    #pragma unroll
    for (int nt = 0; nt < 8; nt++) {
        size_t r0 = (qrow0 + wm + g) * D_MODEL + hoff + nt * 8 + t * 2;
        size_t r1 = r0 + 8 * D_MODEL;
        uint32_t h0, l0, h1, l1;
        split2(oacc[nt][0] * inv0, oacc[nt][1] * inv0, h0, l0);
        split2(oacc[nt][2] * inv1, oacc[nt][3] * inv1, h1, l1);
        *reinterpret_cast<uint32_t*>(&g_ah[r0]) = h0;
        *reinterpret_cast<uint32_t*>(&g_al[r0]) = l0;
        *reinterpret_cast<uint32_t*>(&g_ah[r1]) = h1;
        *reinterpret_cast<uint32_t*>(&g_al[r1]) = l1;
    }
}

// ---------------- launch ----------------
extern "C" void kernel_launch(void* const* d_in, const int* in_sizes, int n_in,
                              void* d_out, int out_size) {
    const float* x  = (const float*)d_in[0];
    const float* wq = (const float*)d_in[1];
    const float* wk = (const float*)d_in[2];
    const float* wv = (const float*)d_in[3];
    const float* wo = (const float*)d_in[4];
    float* out = (float*)d_out;

    __nv_bfloat16 *xh, *xl, *qkvh, *qkvl, *ah, *al, *wh, *wl;
    cudaGetSymbolAddress((void**)&xh, g_xh);
    cudaGetSymbolAddress((void**)&xl, g_xl);
    cudaGetSymbolAddress((void**)&qkvh, g_qkvh);
    cudaGetSymbolAddress((void**)&qkvl, g_qkvl);
    cudaGetSymbolAddress((void**)&ah, g_ah);
    cudaGetSymbolAddress((void**)&al, g_al);
    cudaGetSymbolAddress((void**)&wh, g_wh);
    cudaGetSymbolAddress((void**)&wl, g_wl);

    // 1. splits (weights land contiguously: q|k|v|o)
    split_kernel<<<(XN / 4 + 255) / 256, 256>>>(x, xh, xl, XN / 4);
    split_kernel<<<(WN / 4 + 255) / 256, 256>>>(wq, wh + 0 * WN, wl + 0 * WN, WN / 4);
    split_kernel<<<(WN / 4 + 255) / 256, 256>>>(wk, wh + 1 * WN, wl + 1 * WN, WN / 4);
    split_kernel<<<(WN / 4 + 255) / 256, 256>>>(wv, wh + 2 * WN, wl + 2 * WN, WN / 4);
    split_kernel<<<(WN / 4 + 255) / 256, 256>>>(wo, wh + 3 * WN, wl + 3 * WN, WN / 4);

    // 2. fused QKV projection (N = 2304)
    cudaFuncSetAttribute(gemm_mma<true>, cudaFuncAttributeMaxDynamicSharedMemorySize, GEMM_SMEM);
    cudaFuncSetAttribute(gemm_mma<false>, cudaFuncAttributeMaxDynamicSharedMemorySize, GEMM_SMEM);
    dim3 qkvgrid(D_QKV / BN, MTOT / BM);   // (18, 16)
    gemm_mma<true><<<qkvgrid, 256, GEMM_SMEM>>>(xh, xl, wh, wl,
                                                nullptr, qkvh, qkvl,
                                                MTOT, D_QKV, D_MODEL);

    // 3. tensor-core flash attention
    cudaFuncSetAttribute(attn_mma, cudaFuncAttributeMaxDynamicSharedMemorySize, ATT_SMEM);
    dim3 agrid(SEQ / 128, BATCH * NUM_HEADS);
    attn_mma<<<agrid, 256, ATT_SMEM>>>();

    // 4. output projection -> fp32
    dim3 ogrid(D_MODEL / BN, MTOT / BM);   // (6, 16)
    gemm_mma<false><<<ogrid, 256, GEMM_SMEM>>>(ah, al, wh + 3 * WN, wl + 3 * WN,
                                               out, nullptr, nullptr,
                                               MTOT, D_MODEL, D_MODEL);
}

// round 6
// speedup vs baseline: 3.2468x; 1.1659x over previous
#include <cuda_runtime.h>
#include <cuda_bf16.h>
#include <cuda_fp16.h>
#include <math.h>
#include <stdint.h>

#define D_MODEL 768
#define NUM_HEADS 12
#define DK 64
#define BATCH 2
#define SEQ 2048
#define MTOT (BATCH * SEQ)          // 4096
#define XN (MTOT * D_MODEL)         // 3145728
#define WN (D_MODEL * D_MODEL)      // 589824
#define D_QKV 2304                  // fused Q|K|V column dim

// ---------------- scratch ----------------
__device__ __nv_bfloat16 g_xh[XN], g_xl[XN];
__device__ __half g_qkvh[MTOT * D_QKV], g_qkvl[MTOT * D_QKV];
__device__ __nv_bfloat16 g_ah[XN], g_al[XN];
__device__ __nv_bfloat16 g_wh[4 * WN], g_wl[4 * WN];

// ---------------- helpers ----------------
__device__ __forceinline__ uint32_t smem_u32(const void* p) {
    uint32_t a;
    asm("{ .reg .u64 t; cvta.to.shared.u64 t, %1; cvt.u32.u64 %0, t; }"
        : "=r"(a) : "l"(p));
    return a;
}
__device__ __forceinline__ void cp16(uint32_t saddr, const void* gaddr) {
    asm volatile("cp.async.cg.shared.global [%0], [%1], 16;"
                 :: "r"(saddr), "l"(gaddr) : "memory");
}
__device__ __forceinline__ void ldm4(uint32_t* r, uint32_t addr) {
    asm volatile("ldmatrix.sync.aligned.m8n8.x4.shared.b16 {%0,%1,%2,%3}, [%4];"
                 : "=r"(r[0]), "=r"(r[1]), "=r"(r[2]), "=r"(r[3]) : "r"(addr));
}
__device__ __forceinline__ void ldm4t(uint32_t* r, uint32_t addr) {
    asm volatile("ldmatrix.sync.aligned.m8n8.x4.trans.shared.b16 {%0,%1,%2,%3}, [%4];"
                 : "=r"(r[0]), "=r"(r[1]), "=r"(r[2]), "=r"(r[3]) : "r"(addr));
}
__device__ __forceinline__ void mma_bf16(float* c, const uint32_t* a,
                                         uint32_t b0, uint32_t b1) {
    asm volatile(
        "mma.sync.aligned.m16n8k16.row.col.f32.bf16.bf16.f32 "
        "{%0,%1,%2,%3}, {%4,%5,%6,%7}, {%8,%9}, {%0,%1,%2,%3};"
        : "+f"(c[0]), "+f"(c[1]), "+f"(c[2]), "+f"(c[3])
        : "r"(a[0]), "r"(a[1]), "r"(a[2]), "r"(a[3]), "r"(b0), "r"(b1));
}
__device__ __forceinline__ void mma_f16(float* c, const uint32_t* a,
                                        uint32_t b0, uint32_t b1) {
    asm volatile(
        "mma.sync.aligned.m16n8k16.row.col.f32.f16.f16.f32 "
        "{%0,%1,%2,%3}, {%4,%5,%6,%7}, {%8,%9}, {%0,%1,%2,%3};"
        : "+f"(c[0]), "+f"(c[1]), "+f"(c[2]), "+f"(c[3])
        : "r"(a[0]), "r"(a[1]), "r"(a[2]), "r"(a[3]), "r"(b0), "r"(b1));
}
__device__ __forceinline__ void split2(float x, float y, uint32_t& h, uint32_t& l) {
    __nv_bfloat16 hx = __float2bfloat16_rn(x), hy = __float2bfloat16_rn(y);
    __nv_bfloat162 vh(hx, hy);
    __nv_bfloat162 vl(__float2bfloat16_rn(x - __bfloat162float(hx)),
                      __float2bfloat16_rn(y - __bfloat162float(hy)));
    h = *reinterpret_cast<uint32_t*>(&vh);
    l = *reinterpret_cast<uint32_t*>(&vl);
}
__device__ __forceinline__ void split2h(float x, float y, uint32_t& h, uint32_t& l) {
    __half hx = __float2half_rn(x), hy = __float2half_rn(y);
    __half2 vh(hx, hy);
    __half2 vl(__float2half_rn(x - __half2float(hx)),
               __float2half_rn(y - __half2float(hy)));
    h = *reinterpret_cast<uint32_t*>(&vh);
    l = *reinterpret_cast<uint32_t*>(&vl);
}

// ---------------- split fp32 -> bf16 hi/lo ----------------
__global__ __launch_bounds__(256)
void split_kernel(const float* __restrict__ src, __nv_bfloat16* __restrict__ hi,
                  __nv_bfloat16* __restrict__ lo, int n4) {
    int i = blockIdx.x * blockDim.x + threadIdx.x;
    if (i >= n4) return;
    float4 v = reinterpret_cast<const float4*>(src)[i];
    uint32_t h0, l0, h1, l1;
    split2(v.x, v.y, h0, l0);
    split2(v.z, v.w, h1, l1);
    reinterpret_cast<uint2*>(hi)[i] = make_uint2(h0, h1);
    reinterpret_cast<uint2*>(lo)[i] = make_uint2(l0, l1);
}

// ---------------- mma.sync bf16-split NT GEMM (3-stage pipeline) ----------------
// Block 256x128, BK=32, 8 warps (4 in M x 2 in N), warp tile 64x64.
#define BM 256
#define BN 128
#define BK 32
#define PITCHB 80
#define ATILE (256 * PITCHB)         // 20480
#define BTILE (128 * PITCHB)         // 10240
#define OFF_AH 0
#define OFF_AL ATILE
#define OFF_BH (2 * ATILE)
#define OFF_BL (2 * ATILE + BTILE)
#define STAGE_BYTES (2 * ATILE + 2 * BTILE)   // 61440
#define GEMM_SMEM (3 * STAGE_BYTES)           // 184320

__device__ __forceinline__ void wait_rem(int rem) {
    if (rem >= 2)      asm volatile("cp.async.wait_group 2;" ::: "memory");
    else if (rem == 1) asm volatile("cp.async.wait_group 1;" ::: "memory");
    else               asm volatile("cp.async.wait_group 0;" ::: "memory");
}

__device__ __forceinline__ void load_stage(
    uint32_t sbase, const __nv_bfloat16* Ah, const __nv_bfloat16* Al,
    const __nv_bfloat16* Bh, const __nv_bfloat16* Bl,
    int m0, int n0, int k0, int K, int tid) {
    #pragma unroll
    for (int l = 0; l < 4; l++) {               // A: 256 rows x 4 x 16B
        int idx = tid + l * 256;
        int r = idx >> 2;
        int c = idx & 3;
        uint32_t so = (uint32_t)(r * PITCHB + c * 16);
        size_t ga = (size_t)(m0 + r) * K + k0 + c * 8;
        cp16(sbase + OFF_AH + so, Ah + ga);
        cp16(sbase + OFF_AL + so, Al + ga);
    }
    #pragma unroll
    for (int l = 0; l < 2; l++) {               // B: 128 rows x 4 x 16B
        int idx = tid + l * 256;
        int r = idx >> 2;
        int c = idx & 3;
        uint32_t so = (uint32_t)(r * PITCHB + c * 16);
        size_t gb = (size_t)(n0 + r) * K + k0 + c * 8;
        cp16(sbase + OFF_BH + so, Bh + gb);
        cp16(sbase + OFF_BL + so, Bl + gb);
    }
    asm volatile("cp.async.commit_group;" ::: "memory");
}

// SPLIT_OUT=true: write fp16 hi/lo (QKV path, Q pre-scaled by 0.125).
// SPLIT_OUT=false: write fp32 (O projection).
template<bool SPLIT_OUT>
__global__ __launch_bounds__(256)
void gemm_mma(const __nv_bfloat16* __restrict__ Ah, const __nv_bfloat16* __restrict__ Al,
              const __nv_bfloat16* __restrict__ Bh, const __nv_bfloat16* __restrict__ Bl,
              float* __restrict__ C, __half* __restrict__ Ch,
              __half* __restrict__ Cl, int M, int N, int K) {
    extern __shared__ char smc[];
    const uint32_t sb = smem_u32(smc);
    const int tid = threadIdx.x;
    const int lane = tid & 31;
    const int wid = tid >> 5;
    const int wm = (wid & 3) * 64;
    const int wn = (wid >> 2) * 64;
    const int m0 = blockIdx.y * BM;
    const int n0 = blockIdx.x * BN;

    float acc[4][8][4] = {};
    const int a_lr = lane & 15, a_lc = lane >> 4;
    const int b_lr = lane & 7, b_kh = (lane >> 3) & 1, b_nh = lane >> 4;

    const int nstage = K / BK;
    load_stage(sb, Ah, Al, Bh, Bl, m0, n0, 0, K, tid);
    if (nstage > 1)
        load_stage(sb + STAGE_BYTES, Ah, Al, Bh, Bl, m0, n0, BK, K, tid);

    for (int kt = 0; kt < nstage; kt++) {
        if (kt + 2 < nstage)
            load_stage(sb + (uint32_t)((kt + 2) % 3) * STAGE_BYTES,
                       Ah, Al, Bh, Bl, m0, n0, (kt + 2) * BK, K, tid);
        wait_rem(nstage - kt - 1);
        __syncthreads();

        const uint32_t st = sb + (uint32_t)(kt % 3) * STAGE_BYTES;
        #pragma unroll
        for (int kk = 0; kk < 2; kk++) {
            const uint32_t kcol = (uint32_t)((kk * 16 + a_lc * 8) * 2);
            uint32_t ah[4][4], al[4][4];
            #pragma unroll
            for (int mi = 0; mi < 4; mi++) {
                uint32_t ro = (uint32_t)((wm + mi * 16 + a_lr) * PITCHB) + kcol;
                ldm4(ah[mi], st + OFF_AH + ro);
                ldm4(al[mi], st + OFF_AL + ro);
            }
            const uint32_t bkcol = (uint32_t)((kk * 16 + b_kh * 8) * 2);
            uint32_t bh[4][4], bl[4][4];
            #pragma unroll
            for (int ni = 0; ni < 4; ni++) {
                uint32_t ro = (uint32_t)((wn + ni * 16 + b_lr + b_nh * 8) * PITCHB) + bkcol;
                ldm4(bh[ni], st + OFF_BH + ro);
                ldm4(bl[ni], st + OFF_BL + ro);
            }
            #pragma unroll
            for (int mi = 0; mi < 4; mi++)
                #pragma unroll
                for (int nj = 0; nj < 8; nj++) {
                    const int ni = nj >> 1, od = (nj & 1) * 2;
                    mma_bf16(acc[mi][nj], ah[mi], bh[ni][od], bh[ni][od + 1]);
                    mma_bf16(acc[mi][nj], al[mi], bh[ni][od], bh[ni][od + 1]);
                    mma_bf16(acc[mi][nj], ah[mi], bl[ni][od], bl[ni][od + 1]);
                }
        }
        __syncthreads();
    }

    const int g = lane >> 2, t = lane & 3;
    // Q columns (< 768) are pre-scaled by 1/sqrt(dk)=0.125 (exact in fp16).
    const float sc = (SPLIT_OUT && n0 < 768) ? 0.125f : 1.0f;
    #pragma unroll
    for (int mi = 0; mi < 4; mi++)
        #pragma unroll
        for (int nj = 0; nj < 8; nj++) {
            int row = m0 + wm + mi * 16 + g;
            int col = n0 + wn + nj * 8 + t * 2;
            if (SPLIT_OUT) {
                uint32_t h0, l0, h1, l1;
                split2h(acc[mi][nj][0] * sc, acc[mi][nj][1] * sc, h0, l0);
                split2h(acc[mi][nj][2] * sc, acc[mi][nj][3] * sc, h1, l1);
                *reinterpret_cast<uint32_t*>(&Ch[(size_t)row * N + col]) = h0;
                *reinterpret_cast<uint32_t*>(&Cl[(size_t)row * N + col]) = l0;
                *reinterpret_cast<uint32_t*>(&Ch[(size_t)(row + 8) * N + col]) = h1;
                *reinterpret_cast<uint32_t*>(&Cl[(size_t)(row + 8) * N + col]) = l1;
            } else {
                *reinterpret_cast<float2*>(&C[(size_t)row * N + col]) =
                    make_float2(acc[mi][nj][0], acc[mi][nj][1]);
                *reinterpret_cast<float2*>(&C[(size_t)(row + 8) * N + col]) =
                    make_float2(acc[mi][nj][2], acc[mi][nj][3]);
            }
        }
}

// ---------------- fp16 2-product causal flash attention ----------------
// S = (Qh+Ql)*Kh ; O = (Ph+Pl)*Vh.  Q pre-scaled by 0.125.
// KV stage = KH | VH (fp16 hi only), 3-stage cp.async pipeline.
#define P144 144
#define SQH 0
#define SQL 18432
#define SKV 36864
#define KVSTAGE 18432          // KH 0 | VH 9216
#define ATT_SMEM (SKV + 3 * KVSTAGE)   // 92160

__global__ __launch_bounds__(256, 2)
void attn_mma() {
    extern __shared__ char smc[];
    const uint32_t sb = smem_u32(smc);
    const int tid = threadIdx.x;
    const int lane = tid & 31;
    const int wid = tid >> 5;
    const int qb = (int)(gridDim.x - 1) - (int)blockIdx.x;   // heavy blocks first
    const int b = blockIdx.y / NUM_HEADS;
    const int h = blockIdx.y % NUM_HEADS;
    const int wm = wid * 16;
    const int g = lane >> 2, t = lane & 3;

    const size_t qrow0 = (size_t)b * SEQ + (size_t)qb * 128;
    const size_t krow0 = (size_t)b * SEQ;
    const size_t qoff = (size_t)h * DK;
    const size_t koff = 768 + (size_t)h * DK;
    const size_t voff = 1536 + (size_t)h * DK;

    // Q tiles (hi+lo fp16), persistent
    #pragma unroll
    for (int l = 0; l < 4; l++) {
        int idx = tid + l * 256;
        int r = idx >> 3, c = idx & 7;
        size_t ga = (qrow0 + r) * D_QKV + qoff + c * 8;
        uint32_t so = (uint32_t)(r * P144 + c * 16);
        cp16(sb + SQH + so, g_qkvh + ga);
        cp16(sb + SQL + so, g_qkvl + ga);
    }

    const int ntiles = 2 * qb + 2;
    auto load_kv = [&](int kt) {
        uint32_t stb = sb + SKV + (uint32_t)(kt % 3) * KVSTAGE;
        #pragma unroll
        for (int l = 0; l < 2; l++) {
            int idx = tid + l * 256;
            int r = idx >> 3, c = idx & 7;
            size_t grow = (krow0 + (size_t)kt * 64 + r) * D_QKV;
            uint32_t so = (uint32_t)(r * P144 + c * 16);
            cp16(stb + so, g_qkvh + grow + koff + c * 8);
            cp16(stb + 9216 + so, g_qkvh + grow + voff + c * 8);
        }
        asm volatile("cp.async.commit_group;" ::: "memory");
    };

    load_kv(0);
    if (ntiles > 1) load_kv(1);
    if (ntiles > 2) load_kv(2);

    float oacc[8][4] = {};
    float m_i[2] = {-INFINITY, -INFINITY};
    float l_i[2] = {0.0f, 0.0f};

    const int a_lr = lane & 15, a_lc = lane >> 4;
    const int b_lr = lane & 7, b_kh = (lane >> 3) & 1, b_nh = lane >> 4;
    const int v_r = lane & 15, v_c = (lane >> 4) * 8;

    for (int kt = 0; kt < ntiles; kt++) {
        wait_rem(ntiles - kt - 1);
        __syncthreads();

        const uint32_t stb = sb + SKV + (uint32_t)(kt % 3) * KVSTAGE;
        // last tile: warps 0-3 cover rows entirely above the keys -> fully masked
        const bool skip = (kt == 2 * qb + 1) && (wid < 4);

        if (!skip) {
            // ---- S = Q Kh (2 split products), fp32 accum ----
            float sacc[8][4] = {};
            #pragma unroll
            for (int kk = 0; kk < 4; kk++) {
                const uint32_t kcol = (uint32_t)((kk * 16 + a_lc * 8) * 2);
                uint32_t qh[4], ql[4];
                ldm4(qh, sb + SQH + (uint32_t)((wm + a_lr) * P144) + kcol);
                ldm4(ql, sb + SQL + (uint32_t)((wm + a_lr) * P144) + kcol);
                const uint32_t bkcol = (uint32_t)((kk * 16 + b_kh * 8) * 2);
                #pragma unroll
                for (int np = 0; np < 4; np++) {
                    uint32_t kh[4];
                    ldm4(kh, stb + (uint32_t)((np * 16 + b_lr + b_nh * 8) * P144) + bkcol);
                    mma_f16(sacc[2 * np],     qh, kh[0], kh[1]);
                    mma_f16(sacc[2 * np],     ql, kh[0], kh[1]);
                    mma_f16(sacc[2 * np + 1], qh, kh[2], kh[3]);
                    mma_f16(sacc[2 * np + 1], ql, kh[2], kh[3]);
                }
            }

            // causal mask: diagonal tile (partial for some warps)
            const bool needmask = (kt == 2 * qb && wid < 4) ||
                                  (kt == 2 * qb + 1 && wid >= 4);
            if (needmask) {
                const int grow0 = qb * 128 + wm + g;
                #pragma unroll
                for (int nt = 0; nt < 8; nt++) {
                    const int gcol = kt * 64 + nt * 8 + t * 2;
                    #pragma unroll
                    for (int j = 0; j < 4; j++) {
                        const int row = grow0 + (j >> 1) * 8;
                        const int col = gcol + (j & 1);
                        if (col > row) sacc[nt][j] = -INFINITY;
                    }
                }
            }

            // ---- online softmax per row-half ----
            #pragma unroll
            for (int hh = 0; hh < 2; hh++) {
                float rm = -INFINITY;
                #pragma unroll
                for (int nt = 0; nt < 8; nt++)
                    rm = fmaxf(rm, fmaxf(sacc[nt][2 * hh], sacc[nt][2 * hh + 1]));
                rm = fmaxf(rm, __shfl_xor_sync(0xffffffffu, rm, 1));
                rm = fmaxf(rm, __shfl_xor_sync(0xffffffffu, rm, 2));
                float mn = fmaxf(m_i[hh], rm);
                float alpha = __expf(m_i[hh] - mn);
                float rs = 0.0f;
                #pragma unroll
                for (int nt = 0; nt < 8; nt++) {
                    float p0 = __expf(sacc[nt][2 * hh] - mn);
                    float p1 = __expf(sacc[nt][2 * hh + 1] - mn);
                    sacc[nt][2 * hh] = p0;
                    sacc[nt][2 * hh + 1] = p1;
                    rs += p0 + p1;
                }
                rs += __shfl_xor_sync(0xffffffffu, rs, 1);
                rs += __shfl_xor_sync(0xffffffffu, rs, 2);
                l_i[hh] = l_i[hh] * alpha + rs;
                m_i[hh] = mn;
                #pragma unroll
                for (int nt = 0; nt < 8; nt++) {
                    oacc[nt][2 * hh] *= alpha;
                    oacc[nt][2 * hh + 1] *= alpha;
                }
            }

            // ---- O += P Vh (2 split products) ----
            #pragma unroll
            for (int ks = 0; ks < 4; ks++) {
                uint32_t ph[4], pl[4];
                split2h(sacc[2 * ks][0],     sacc[2 * ks][1],     ph[0], pl[0]);
                split2h(sacc[2 * ks][2],     sacc[2 * ks][3],     ph[1], pl[1]);
                split2h(sacc[2 * ks + 1][0], sacc[2 * ks + 1][1], ph[2], pl[2]);
                split2h(sacc[2 * ks + 1][2], sacc[2 * ks + 1][3], ph[3], pl[3]);
                const uint32_t vrow = (uint32_t)((ks * 16 + v_r) * P144);
                #pragma unroll
                for (int np = 0; np < 4; np++) {
                    uint32_t vh[4];
                    ldm4t(vh, stb + 9216 + vrow + (uint32_t)((np * 16 + v_c) * 2));
                    mma_f16(oacc[2 * np],     ph, vh[0], vh[1]);
                    mma_f16(oacc[2 * np],     pl, vh[0], vh[1]);
                    mma_f16(oacc[2 * np + 1], ph, vh[2], vh[3]);
                    mma_f16(oacc[2 * np + 1], pl, vh[2], vh[3]);
                }
            }
        }

        __syncthreads();
        if (kt + 3 < ntiles) load_kv(kt + 3);
    }

    // epilogue: normalize, split to bf16 hi/lo for the O projection
    const float inv0 = 1.0f / l_i[0], inv1 = 1.0f / l_i[1];
    const size_t hoff = (size_t)h * DK;
    #pragma unroll
    for (int nt = 0; nt < 8; nt++) {
        size_t r0 = (qrow0 + wm + g) * D_MODEL + hoff + nt * 8 + t * 2;
        size_t r1 = r0 + 8 * D_MODEL;
        uint32_t h0, l0, h1, l1;
        split2(oacc[nt][0] * inv0, oacc[nt][1] * inv0, h0, l0);
        split2(oacc[nt][2] * inv1, oacc[nt][3] * inv1, h1, l1);
        *reinterpret_cast<uint32_t*>(&g_ah[r0]) = h0;
        *reinterpret_cast<uint32_t*>(&g_al[r0]) = l0;
        *reinterpret_cast<uint32_t*>(&g_ah[r1]) = h1;
        *reinterpret_cast<uint32_t*>(&g_al[r1]) = l1;
    }
}

// ---------------- launch ----------------
extern "C" void kernel_launch(void* const* d_in, const int* in_sizes, int n_in,
                              void* d_out, int out_size) {
    const float* x  = (const float*)d_in[0];
    const float* wq = (const float*)d_in[1];
    const float* wk = (const float*)d_in[2];
    const float* wv = (const float*)d_in[3];
    const float* wo = (const float*)d_in[4];
    float* out = (float*)d_out;

    __nv_bfloat16 *xh, *xl, *ah, *al, *wh, *wl;
    __half *qkvh, *qkvl;
    cudaGetSymbolAddress((void**)&xh, g_xh);
    cudaGetSymbolAddress((void**)&xl, g_xl);
    cudaGetSymbolAddress((void**)&qkvh, g_qkvh);
    cudaGetSymbolAddress((void**)&qkvl, g_qkvl);
    cudaGetSymbolAddress((void**)&ah, g_ah);
    cudaGetSymbolAddress((void**)&al, g_al);
    cudaGetSymbolAddress((void**)&wh, g_wh);
    cudaGetSymbolAddress((void**)&wl, g_wl);

    // 1. splits (weights land contiguously: q|k|v|o)
    split_kernel<<<(XN / 4 + 255) / 256, 256>>>(x, xh, xl, XN / 4);
    split_kernel<<<(WN / 4 + 255) / 256, 256>>>(wq, wh + 0 * WN, wl + 0 * WN, WN / 4);
    split_kernel<<<(WN / 4 + 255) / 256, 256>>>(wk, wh + 1 * WN, wl + 1 * WN, WN / 4);
    split_kernel<<<(WN / 4 + 255) / 256, 256>>>(wv, wh + 2 * WN, wl + 2 * WN, WN / 4);
    split_kernel<<<(WN / 4 + 255) / 256, 256>>>(wo, wh + 3 * WN, wl + 3 * WN, WN / 4);

    // 2. fused QKV projection (N = 2304) -> fp16 hi/lo, Q pre-scaled
    cudaFuncSetAttribute(gemm_mma<true>, cudaFuncAttributeMaxDynamicSharedMemorySize, GEMM_SMEM);
    cudaFuncSetAttribute(gemm_mma<false>, cudaFuncAttributeMaxDynamicSharedMemorySize, GEMM_SMEM);
    dim3 qkvgrid(D_QKV / BN, MTOT / BM);   // (18, 16)
    gemm_mma<true><<<qkvgrid, 256, GEMM_SMEM>>>(xh, xl, wh, wl,
                                                nullptr, qkvh, qkvl,
                                                MTOT, D_QKV, D_MODEL);

    // 3. fp16 2-product flash attention
    cudaFuncSetAttribute(attn_mma, cudaFuncAttributeMaxDynamicSharedMemorySize, ATT_SMEM);
    dim3 agrid(SEQ / 128, BATCH * NUM_HEADS);
    attn_mma<<<agrid, 256, ATT_SMEM>>>();

    // 4. output projection -> fp32
    dim3 ogrid(D_MODEL / BN, MTOT / BM);   // (6, 16)
    gemm_mma<false><<<ogrid, 256, GEMM_SMEM>>>(ah, al, wh + 3 * WN, wl + 3 * WN,
                                               out, nullptr, nullptr,
                                               MTOT, D_MODEL, D_MODEL);
}

// round 7
// speedup vs baseline: 3.7629x; 1.1590x over previous
#include <cuda_runtime.h>
#include <cuda_bf16.h>
#include <cuda_fp16.h>
#include <math.h>
#include <stdint.h>

#define D_MODEL 768
#define NUM_HEADS 12
#define DK 64
#define BATCH 2
#define SEQ 2048
#define MTOT (BATCH * SEQ)          // 4096
#define XN (MTOT * D_MODEL)         // 3145728
#define WN (D_MODEL * D_MODEL)      // 589824
#define D_QKV 2304                  // fused Q|K|V column dim

// ---------------- scratch ----------------
__device__ __half g_xh[XN], g_xl[XN];
__device__ __half g_qkvh[MTOT * D_QKV], g_qkvl[MTOT * D_QKV];
__device__ __half g_ah[XN], g_al[XN];
__device__ __half g_wh[4 * WN];          // fp16-rounded weights q|k|v|o

// ---------------- helpers ----------------
__device__ __forceinline__ uint32_t smem_u32(const void* p) {
    uint32_t a;
    asm("{ .reg .u64 t; cvta.to.shared.u64 t, %1; cvt.u32.u64 %0, t; }"
        : "=r"(a) : "l"(p));
    return a;
}
__device__ __forceinline__ void cp16(uint32_t saddr, const void* gaddr) {
    asm volatile("cp.async.cg.shared.global [%0], [%1], 16;"
                 :: "r"(saddr), "l"(gaddr) : "memory");
}
__device__ __forceinline__ void ldm4(uint32_t* r, uint32_t addr) {
    asm volatile("ldmatrix.sync.aligned.m8n8.x4.shared.b16 {%0,%1,%2,%3}, [%4];"
                 : "=r"(r[0]), "=r"(r[1]), "=r"(r[2]), "=r"(r[3]) : "r"(addr));
}
__device__ __forceinline__ void ldm4t(uint32_t* r, uint32_t addr) {
    asm volatile("ldmatrix.sync.aligned.m8n8.x4.trans.shared.b16 {%0,%1,%2,%3}, [%4];"
                 : "=r"(r[0]), "=r"(r[1]), "=r"(r[2]), "=r"(r[3]) : "r"(addr));
}
__device__ __forceinline__ void mma_f16(float* c, const uint32_t* a,
                                        uint32_t b0, uint32_t b1) {
    asm volatile(
        "mma.sync.aligned.m16n8k16.row.col.f32.f16.f16.f32 "
        "{%0,%1,%2,%3}, {%4,%5,%6,%7}, {%8,%9}, {%0,%1,%2,%3};"
        : "+f"(c[0]), "+f"(c[1]), "+f"(c[2]), "+f"(c[3])
        : "r"(a[0]), "r"(a[1]), "r"(a[2]), "r"(a[3]), "r"(b0), "r"(b1));
}
__device__ __forceinline__ void split2h(float x, float y, uint32_t& h, uint32_t& l) {
    __half hx = __float2half_rn(x), hy = __float2half_rn(y);
    __half2 vh(hx, hy);
    __half2 vl(__float2half_rn(x - __half2float(hx)),
               __float2half_rn(y - __half2float(hy)));
    h = *reinterpret_cast<uint32_t*>(&vh);
    l = *reinterpret_cast<uint32_t*>(&vl);
}

// ---------------- fp32 -> fp16 hi/lo split ----------------
__global__ __launch_bounds__(256)
void split_kernel(const float* __restrict__ src, __half* __restrict__ hi,
                  __half* __restrict__ lo, int n4) {
    int i = blockIdx.x * blockDim.x + threadIdx.x;
    if (i >= n4) return;
    float4 v = reinterpret_cast<const float4*>(src)[i];
    uint32_t h0, l0, h1, l1;
    split2h(v.x, v.y, h0, l0);
    split2h(v.z, v.w, h1, l1);
    reinterpret_cast<uint2*>(hi)[i] = make_uint2(h0, h1);
    reinterpret_cast<uint2*>(lo)[i] = make_uint2(l0, l1);
}

// ---------------- fp32 -> fp16 round (weights) ----------------
__global__ __launch_bounds__(256)
void round_kernel(const float* __restrict__ src, __half* __restrict__ dst, int n4) {
    int i = blockIdx.x * blockDim.x + threadIdx.x;
    if (i >= n4) return;
    float4 v = reinterpret_cast<const float4*>(src)[i];
    __half2 a(__float2half_rn(v.x), __float2half_rn(v.y));
    __half2 b(__float2half_rn(v.z), __float2half_rn(v.w));
    reinterpret_cast<uint2*>(dst)[i] =
        make_uint2(*reinterpret_cast<uint32_t*>(&a), *reinterpret_cast<uint32_t*>(&b));
}

// ---------------- fp16 2-product NT GEMM: C = (Ah+Al)*Bh ----------------
// Block 256x128, BK=32, 8 warps (4 in M x 2 in N), warp tile 64x64. 3-stage.
#define BM 256
#define BN 128
#define BK 32
#define PITCHB 80
#define ATILE (256 * PITCHB)         // 20480
#define BTILE (128 * PITCHB)         // 10240
#define OFF_AH 0
#define OFF_AL ATILE
#define OFF_BH (2 * ATILE)
#define STAGE_BYTES (2 * ATILE + BTILE)       // 51200
#define GEMM_SMEM (3 * STAGE_BYTES)           // 153600

__device__ __forceinline__ void wait_rem(int rem) {
    if (rem >= 2)      asm volatile("cp.async.wait_group 2;" ::: "memory");
    else if (rem == 1) asm volatile("cp.async.wait_group 1;" ::: "memory");
    else               asm volatile("cp.async.wait_group 0;" ::: "memory");
}

__device__ __forceinline__ void load_stage(
    uint32_t sbase, const __half* Ah, const __half* Al, const __half* Bh,
    int m0, int n0, int k0, int K, int tid) {
    #pragma unroll
    for (int l = 0; l < 4; l++) {               // A: 256 rows x 4 x 16B
        int idx = tid + l * 256;
        int r = idx >> 2;
        int c = idx & 3;
        uint32_t so = (uint32_t)(r * PITCHB + c * 16);
        size_t ga = (size_t)(m0 + r) * K + k0 + c * 8;
        cp16(sbase + OFF_AH + so, Ah + ga);
        cp16(sbase + OFF_AL + so, Al + ga);
    }
    #pragma unroll
    for (int l = 0; l < 2; l++) {               // B: 128 rows x 4 x 16B
        int idx = tid + l * 256;
        int r = idx >> 2;
        int c = idx & 3;
        uint32_t so = (uint32_t)(r * PITCHB + c * 16);
        size_t gb = (size_t)(n0 + r) * K + k0 + c * 8;
        cp16(sbase + OFF_BH + so, Bh + gb);
    }
    asm volatile("cp.async.commit_group;" ::: "memory");
}

// SPLIT_OUT=true: write fp16 hi/lo (QKV path, Q pre-scaled by 0.125).
// SPLIT_OUT=false: write fp32 (O projection).
template<bool SPLIT_OUT>
__global__ __launch_bounds__(256)
void gemm_mma(const __half* __restrict__ Ah, const __half* __restrict__ Al,
              const __half* __restrict__ Bh,
              float* __restrict__ C, __half* __restrict__ Ch,
              __half* __restrict__ Cl, int M, int N, int K) {
    extern __shared__ char smc[];
    const uint32_t sb = smem_u32(smc);
    const int tid = threadIdx.x;
    const int lane = tid & 31;
    const int wid = tid >> 5;
    const int wm = (wid & 3) * 64;
    const int wn = (wid >> 2) * 64;
    const int m0 = blockIdx.y * BM;
    const int n0 = blockIdx.x * BN;

    float acc[4][8][4] = {};
    const int a_lr = lane & 15, a_lc = lane >> 4;
    const int b_lr = lane & 7, b_kh = (lane >> 3) & 1, b_nh = lane >> 4;

    const int nstage = K / BK;
    load_stage(sb, Ah, Al, Bh, m0, n0, 0, K, tid);
    if (nstage > 1)
        load_stage(sb + STAGE_BYTES, Ah, Al, Bh, m0, n0, BK, K, tid);

    for (int kt = 0; kt < nstage; kt++) {
        if (kt + 2 < nstage)
            load_stage(sb + (uint32_t)((kt + 2) % 3) * STAGE_BYTES,
                       Ah, Al, Bh, m0, n0, (kt + 2) * BK, K, tid);
        wait_rem(nstage - kt - 1);
        __syncthreads();

        const uint32_t st = sb + (uint32_t)(kt % 3) * STAGE_BYTES;
        #pragma unroll
        for (int kk = 0; kk < 2; kk++) {
            const uint32_t kcol = (uint32_t)((kk * 16 + a_lc * 8) * 2);
            uint32_t ah[4][4], al[4][4];
            #pragma unroll
            for (int mi = 0; mi < 4; mi++) {
                uint32_t ro = (uint32_t)((wm + mi * 16 + a_lr) * PITCHB) + kcol;
                ldm4(ah[mi], st + OFF_AH + ro);
                ldm4(al[mi], st + OFF_AL + ro);
            }
            const uint32_t bkcol = (uint32_t)((kk * 16 + b_kh * 8) * 2);
            uint32_t bh[4][4];
            #pragma unroll
            for (int ni = 0; ni < 4; ni++) {
                uint32_t ro = (uint32_t)((wn + ni * 16 + b_lr + b_nh * 8) * PITCHB) + bkcol;
                ldm4(bh[ni], st + OFF_BH + ro);
            }
            #pragma unroll
            for (int mi = 0; mi < 4; mi++)
                #pragma unroll
                for (int nj = 0; nj < 8; nj++) {
                    const int ni = nj >> 1, od = (nj & 1) * 2;
                    mma_f16(acc[mi][nj], ah[mi], bh[ni][od], bh[ni][od + 1]);
                    mma_f16(acc[mi][nj], al[mi], bh[ni][od], bh[ni][od + 1]);
                }
        }
        __syncthreads();
    }

    const int g = lane >> 2, t = lane & 3;
    // Q columns (< 768) pre-scaled by 1/sqrt(dk)=0.125 (exact in fp16).
    const float sc = (SPLIT_OUT && n0 < 768) ? 0.125f : 1.0f;
    #pragma unroll
    for (int mi = 0; mi < 4; mi++)
        #pragma unroll
        for (int nj = 0; nj < 8; nj++) {
            int row = m0 + wm + mi * 16 + g;
            int col = n0 + wn + nj * 8 + t * 2;
            if (SPLIT_OUT) {
                uint32_t h0, l0, h1, l1;
                split2h(acc[mi][nj][0] * sc, acc[mi][nj][1] * sc, h0, l0);
                split2h(acc[mi][nj][2] * sc, acc[mi][nj][3] * sc, h1, l1);
                *reinterpret_cast<uint32_t*>(&Ch[(size_t)row * N + col]) = h0;
                *reinterpret_cast<uint32_t*>(&Cl[(size_t)row * N + col]) = l0;
                *reinterpret_cast<uint32_t*>(&Ch[(size_t)(row + 8) * N + col]) = h1;
                *reinterpret_cast<uint32_t*>(&Cl[(size_t)(row + 8) * N + col]) = l1;
            } else {
                *reinterpret_cast<float2*>(&C[(size_t)row * N + col]) =
                    make_float2(acc[mi][nj][0], acc[mi][nj][1]);
                *reinterpret_cast<float2*>(&C[(size_t)(row + 8) * N + col]) =
                    make_float2(acc[mi][nj][2], acc[mi][nj][3]);
            }
        }
}

// ---------------- fp16 2-product causal flash attention ----------------
// S = (Qh+Ql)*Kh ; O = (Ph+Pl)*Vh.  Q pre-scaled by 0.125.
#define P144 144
#define SQH 0
#define SQL 18432
#define SKV 36864
#define KVSTAGE 18432          // KH 0 | VH 9216
#define ATT_SMEM (SKV + 3 * KVSTAGE)   // 92160

__global__ __launch_bounds__(256, 2)
void attn_mma() {
    extern __shared__ char smc[];
    const uint32_t sb = smem_u32(smc);
    const int tid = threadIdx.x;
    const int lane = tid & 31;
    const int wid = tid >> 5;
    const int qb = (int)(gridDim.x - 1) - (int)blockIdx.x;   // heavy blocks first
    const int b = blockIdx.y / NUM_HEADS;
    const int h = blockIdx.y % NUM_HEADS;
    const int wm = wid * 16;
    const int g = lane >> 2, t = lane & 3;

    const size_t qrow0 = (size_t)b * SEQ + (size_t)qb * 128;
    const size_t krow0 = (size_t)b * SEQ;
    const size_t qoff = (size_t)h * DK;
    const size_t koff = 768 + (size_t)h * DK;
    const size_t voff = 1536 + (size_t)h * DK;

    // Q tiles (hi+lo fp16), persistent
    #pragma unroll
    for (int l = 0; l < 4; l++) {
        int idx = tid + l * 256;
        int r = idx >> 3, c = idx & 7;
        size_t ga = (qrow0 + r) * D_QKV + qoff + c * 8;
        uint32_t so = (uint32_t)(r * P144 + c * 16);
        cp16(sb + SQH + so, g_qkvh + ga);
        cp16(sb + SQL + so, g_qkvl + ga);
    }

    const int ntiles = 2 * qb + 2;
    auto load_kv = [&](int kt) {
        uint32_t stb = sb + SKV + (uint32_t)(kt % 3) * KVSTAGE;
        #pragma unroll
        for (int l = 0; l < 2; l++) {
            int idx = tid + l * 256;
            int r = idx >> 3, c = idx & 7;
            size_t grow = (krow0 + (size_t)kt * 64 + r) * D_QKV;
            uint32_t so = (uint32_t)(r * P144 + c * 16);
            cp16(stb + so, g_qkvh + grow + koff + c * 8);
            cp16(stb + 9216 + so, g_qkvh + grow + voff + c * 8);
        }
        asm volatile("cp.async.commit_group;" ::: "memory");
    };

    load_kv(0);
    if (ntiles > 1) load_kv(1);
    if (ntiles > 2) load_kv(2);

    float oacc[8][4] = {};
    float m_i[2] = {-INFINITY, -INFINITY};
    float l_i[2] = {0.0f, 0.0f};

    const int a_lr = lane & 15, a_lc = lane >> 4;
    const int b_lr = lane & 7, b_kh = (lane >> 3) & 1, b_nh = lane >> 4;
    const int v_r = lane & 15, v_c = (lane >> 4) * 8;

    for (int kt = 0; kt < ntiles; kt++) {
        wait_rem(ntiles - kt - 1);
        __syncthreads();

        const uint32_t stb = sb + SKV + (uint32_t)(kt % 3) * KVSTAGE;
        const bool skip = (kt == 2 * qb + 1) && (wid < 4);

        if (!skip) {
            float sacc[8][4] = {};
            #pragma unroll
            for (int kk = 0; kk < 4; kk++) {
                const uint32_t kcol = (uint32_t)((kk * 16 + a_lc * 8) * 2);
                uint32_t qh[4], ql[4];
                ldm4(qh, sb + SQH + (uint32_t)((wm + a_lr) * P144) + kcol);
                ldm4(ql, sb + SQL + (uint32_t)((wm + a_lr) * P144) + kcol);
                const uint32_t bkcol = (uint32_t)((kk * 16 + b_kh * 8) * 2);
                #pragma unroll
                for (int np = 0; np < 4; np++) {
                    uint32_t kh[4];
                    ldm4(kh, stb + (uint32_t)((np * 16 + b_lr + b_nh * 8) * P144) + bkcol);
                    mma_f16(sacc[2 * np],     qh, kh[0], kh[1]);
                    mma_f16(sacc[2 * np],     ql, kh[0], kh[1]);
                    mma_f16(sacc[2 * np + 1], qh, kh[2], kh[3]);
                    mma_f16(sacc[2 * np + 1], ql, kh[2], kh[3]);
                }
            }

            const bool needmask = (kt == 2 * qb && wid < 4) ||
                                  (kt == 2 * qb + 1 && wid >= 4);
            if (needmask) {
                const int grow0 = qb * 128 + wm + g;
                #pragma unroll
                for (int nt = 0; nt < 8; nt++) {
                    const int gcol = kt * 64 + nt * 8 + t * 2;
                    #pragma unroll
                    for (int j = 0; j < 4; j++) {
                        const int row = grow0 + (j >> 1) * 8;
                        const int col = gcol + (j & 1);
                        if (col > row) sacc[nt][j] = -INFINITY;
                    }
                }
            }

            #pragma unroll
            for (int hh = 0; hh < 2; hh++) {
                float rm = -INFINITY;
                #pragma unroll
                for (int nt = 0; nt < 8; nt++)
                    rm = fmaxf(rm, fmaxf(sacc[nt][2 * hh], sacc[nt][2 * hh + 1]));
                rm = fmaxf(rm, __shfl_xor_sync(0xffffffffu, rm, 1));
                rm = fmaxf(rm, __shfl_xor_sync(0xffffffffu, rm, 2));
                float mn = fmaxf(m_i[hh], rm);
                float alpha = __expf(m_i[hh] - mn);
                float rs = 0.0f;
                #pragma unroll
                for (int nt = 0; nt < 8; nt++) {
                    float p0 = __expf(sacc[nt][2 * hh] - mn);
                    float p1 = __expf(sacc[nt][2 * hh + 1] - mn);
                    sacc[nt][2 * hh] = p0;
                    sacc[nt][2 * hh + 1] = p1;
                    rs += p0 + p1;
                }
                rs += __shfl_xor_sync(0xffffffffu, rs, 1);
                rs += __shfl_xor_sync(0xffffffffu, rs, 2);
                l_i[hh] = l_i[hh] * alpha + rs;
                m_i[hh] = mn;
                #pragma unroll
                for (int nt = 0; nt < 8; nt++) {
                    oacc[nt][2 * hh] *= alpha;
                    oacc[nt][2 * hh + 1] *= alpha;
                }
            }

            #pragma unroll
            for (int ks = 0; ks < 4; ks++) {
                uint32_t ph[4], pl[4];
                split2h(sacc[2 * ks][0],     sacc[2 * ks][1],     ph[0], pl[0]);
                split2h(sacc[2 * ks][2],     sacc[2 * ks][3],     ph[1], pl[1]);
                split2h(sacc[2 * ks + 1][0], sacc[2 * ks + 1][1], ph[2], pl[2]);
                split2h(sacc[2 * ks + 1][2], sacc[2 * ks + 1][3], ph[3], pl[3]);
                const uint32_t vrow = (uint32_t)((ks * 16 + v_r) * P144);
                #pragma unroll
                for (int np = 0; np < 4; np++) {
                    uint32_t vh[4];
                    ldm4t(vh, stb + 9216 + vrow + (uint32_t)((np * 16 + v_c) * 2));
                    mma_f16(oacc[2 * np],     ph, vh[0], vh[1]);
                    mma_f16(oacc[2 * np],     pl, vh[0], vh[1]);
                    mma_f16(oacc[2 * np + 1], ph, vh[2], vh[3]);
                    mma_f16(oacc[2 * np + 1], pl, vh[2], vh[3]);
                }
            }
        }

        __syncthreads();
        if (kt + 3 < ntiles) load_kv(kt + 3);
    }

    // epilogue: normalize, split to fp16 hi/lo for the O projection
    const float inv0 = 1.0f / l_i[0], inv1 = 1.0f / l_i[1];
    const size_t hoff = (size_t)h * DK;
    #pragma unroll
    for (int nt = 0; nt < 8; nt++) {
        size_t r0 = (qrow0 + wm + g) * D_MODEL + hoff + nt * 8 + t * 2;
        size_t r1 = r0 + 8 * D_MODEL;
        uint32_t h0, l0, h1, l1;
        split2h(oacc[nt][0] * inv0, oacc[nt][1] * inv0, h0, l0);
        split2h(oacc[nt][2] * inv1, oacc[nt][3] * inv1, h1, l1);
        *reinterpret_cast<uint32_t*>(&g_ah[r0]) = h0;
        *reinterpret_cast<uint32_t*>(&g_al[r0]) = l0;
        *reinterpret_cast<uint32_t*>(&g_ah[r1]) = h1;
        *reinterpret_cast<uint32_t*>(&g_al[r1]) = l1;
    }
}

// ---------------- launch ----------------
extern "C" void kernel_launch(void* const* d_in, const int* in_sizes, int n_in,
                              void* d_out, int out_size) {
    const float* x  = (const float*)d_in[0];
    const float* wq = (const float*)d_in[1];
    const float* wk = (const float*)d_in[2];
    const float* wv = (const float*)d_in[3];
    const float* wo = (const float*)d_in[4];
    float* out = (float*)d_out;

    __half *xh, *xl, *qkvh, *qkvl, *ah, *al, *wh;
    cudaGetSymbolAddress((void**)&xh, g_xh);
    cudaGetSymbolAddress((void**)&xl, g_xl);
    cudaGetSymbolAddress((void**)&qkvh, g_qkvh);
    cudaGetSymbolAddress((void**)&qkvl, g_qkvl);
    cudaGetSymbolAddress((void**)&ah, g_ah);
    cudaGetSymbolAddress((void**)&al, g_al);
    cudaGetSymbolAddress((void**)&wh, g_wh);

    // 1. x -> fp16 hi/lo; weights -> fp16 (contiguous q|k|v|o)
    split_kernel<<<(XN / 4 + 255) / 256, 256>>>(x, xh, xl, XN / 4);
    round_kernel<<<(WN / 4 + 255) / 256, 256>>>(wq, wh + 0 * WN, WN / 4);
    round_kernel<<<(WN / 4 + 255) / 256, 256>>>(wk, wh + 1 * WN, WN / 4);
    round_kernel<<<(WN / 4 + 255) / 256, 256>>>(wv, wh + 2 * WN, WN / 4);
    round_kernel<<<(WN / 4 + 255) / 256, 256>>>(wo, wh + 3 * WN, WN / 4);

    // 2. fused QKV projection (N = 2304) -> fp16 hi/lo, Q pre-scaled
    cudaFuncSetAttribute(gemm_mma<true>, cudaFuncAttributeMaxDynamicSharedMemorySize, GEMM_SMEM);
    cudaFuncSetAttribute(gemm_mma<false>, cudaFuncAttributeMaxDynamicSharedMemorySize, GEMM_SMEM);
    dim3 qkvgrid(D_QKV / BN, MTOT / BM);   // (18, 16)
    gemm_mma<true><<<qkvgrid, 256, GEMM_SMEM>>>(xh, xl, wh,
                                                nullptr, qkvh, qkvl,
                                                MTOT, D_QKV, D_MODEL);

    // 3. fp16 2-product flash attention
    cudaFuncSetAttribute(attn_mma, cudaFuncAttributeMaxDynamicSharedMemorySize, ATT_SMEM);
    dim3 agrid(SEQ / 128, BATCH * NUM_HEADS);
    attn_mma<<<agrid, 256, ATT_SMEM>>>();

    // 4. output projection -> fp32
    dim3 ogrid(D_MODEL / BN, MTOT / BM);   // (6, 16)
    gemm_mma<false><<<ogrid, 256, GEMM_SMEM>>>(ah, al, wh + 3 * WN,
                                               out, nullptr, nullptr,
                                               MTOT, D_MODEL, D_MODEL);
}

// round 8
// speedup vs baseline: 4.1470x; 1.1021x over previous
#include <cuda_runtime.h>
#include <cuda_bf16.h>
#include <cuda_fp16.h>
#include <math.h>
#include <stdint.h>

#define D_MODEL 768
#define NUM_HEADS 12
#define DK 64
#define BATCH 2
#define SEQ 2048
#define MTOT (BATCH * SEQ)          // 4096
#define XN (MTOT * D_MODEL)         // 3145728
#define WN (D_MODEL * D_MODEL)      // 589824
#define D_QKV 2304                  // fused Q|K|V column dim

// ---------------- scratch ----------------
__device__ __half g_xh[XN], g_xl[XN];
__device__ __half g_qkvh[MTOT * D_QKV], g_qkvl[MTOT * D_QKV];
__device__ __half g_ah[XN], g_al[XN];
__device__ __half g_wh[4 * WN];          // fp16-rounded weights q|k|v|o

// ---------------- helpers ----------------
__device__ __forceinline__ uint32_t smem_u32(const void* p) {
    uint32_t a;
    asm("{ .reg .u64 t; cvta.to.shared.u64 t, %1; cvt.u32.u64 %0, t; }"
        : "=r"(a) : "l"(p));
    return a;
}
__device__ __forceinline__ void cp16(uint32_t saddr, const void* gaddr) {
    asm volatile("cp.async.cg.shared.global [%0], [%1], 16;"
                 :: "r"(saddr), "l"(gaddr) : "memory");
}
__device__ __forceinline__ void ldm4(uint32_t* r, uint32_t addr) {
    asm volatile("ldmatrix.sync.aligned.m8n8.x4.shared.b16 {%0,%1,%2,%3}, [%4];"
                 : "=r"(r[0]), "=r"(r[1]), "=r"(r[2]), "=r"(r[3]) : "r"(addr));
}
__device__ __forceinline__ void ldm4t(uint32_t* r, uint32_t addr) {
    asm volatile("ldmatrix.sync.aligned.m8n8.x4.trans.shared.b16 {%0,%1,%2,%3}, [%4];"
                 : "=r"(r[0]), "=r"(r[1]), "=r"(r[2]), "=r"(r[3]) : "r"(addr));
}
__device__ __forceinline__ void mma_f16(float* c, const uint32_t* a,
                                        uint32_t b0, uint32_t b1) {
    asm volatile(
        "mma.sync.aligned.m16n8k16.row.col.f32.f16.f16.f32 "
        "{%0,%1,%2,%3}, {%4,%5,%6,%7}, {%8,%9}, {%0,%1,%2,%3};"
        : "+f"(c[0]), "+f"(c[1]), "+f"(c[2]), "+f"(c[3])
        : "r"(a[0]), "r"(a[1]), "r"(a[2]), "r"(a[3]), "r"(b0), "r"(b1));
}
__device__ __forceinline__ uint32_t pack2h(float x, float y) {
    __half2 v(__float2half_rn(x), __float2half_rn(y));
    return *reinterpret_cast<uint32_t*>(&v);
}
__device__ __forceinline__ void split2h(float x, float y, uint32_t& h, uint32_t& l) {
    __half hx = __float2half_rn(x), hy = __float2half_rn(y);
    __half2 vh(hx, hy);
    __half2 vl(__float2half_rn(x - __half2float(hx)),
               __float2half_rn(y - __half2float(hy)));
    h = *reinterpret_cast<uint32_t*>(&vh);
    l = *reinterpret_cast<uint32_t*>(&vl);
}

// ---------------- fp32 -> fp16 hi/lo split ----------------
__global__ __launch_bounds__(256)
void split_kernel(const float* __restrict__ src, __half* __restrict__ hi,
                  __half* __restrict__ lo, int n4) {
    int i = blockIdx.x * blockDim.x + threadIdx.x;
    if (i >= n4) return;
    float4 v = reinterpret_cast<const float4*>(src)[i];
    uint32_t h0, l0, h1, l1;
    split2h(v.x, v.y, h0, l0);
    split2h(v.z, v.w, h1, l1);
    reinterpret_cast<uint2*>(hi)[i] = make_uint2(h0, h1);
    reinterpret_cast<uint2*>(lo)[i] = make_uint2(l0, l1);
}

// ---------------- fp32 -> fp16 round, all 4 weights in one launch ----------------
__global__ __launch_bounds__(256)
void round4_kernel(const float* __restrict__ w0, const float* __restrict__ w1,
                   const float* __restrict__ w2, const float* __restrict__ w3,
                   __half* __restrict__ dst, int n4) {
    int i = blockIdx.x * blockDim.x + threadIdx.x;
    if (i >= n4) return;
    const float* src = (blockIdx.y == 0) ? w0 : (blockIdx.y == 1) ? w1
                     : (blockIdx.y == 2) ? w2 : w3;
    float4 v = reinterpret_cast<const float4*>(src)[i];
    __half2 a(__float2half_rn(v.x), __float2half_rn(v.y));
    __half2 b(__float2half_rn(v.z), __float2half_rn(v.w));
    reinterpret_cast<uint2*>(dst)[(size_t)blockIdx.y * n4 + i] =
        make_uint2(*reinterpret_cast<uint32_t*>(&a), *reinterpret_cast<uint32_t*>(&b));
}

// ---------------- fp16 NT GEMM: C = (Ah[+Al])*Bh ----------------
// Block 256x128, BK=32, 8 warps (4 in M x 2 in N), warp tile 64x64. 3-stage.
// QKV path: Q columns (n0<768) use 2 products + hi/lo out; K/V columns use
// 1 product + hi out only (attention reads only the hi half of K/V).
#define BM 256
#define BN 128
#define BK 32
#define PITCHB 80
#define ATILE (256 * PITCHB)         // 20480
#define BTILE (128 * PITCHB)         // 10240
#define OFF_AH 0
#define OFF_AL ATILE
#define OFF_BH (2 * ATILE)
#define STAGE_BYTES (2 * ATILE + BTILE)       // 51200
#define GEMM_SMEM (3 * STAGE_BYTES)           // 153600

__device__ __forceinline__ void wait_rem(int rem) {
    if (rem >= 2)      asm volatile("cp.async.wait_group 2;" ::: "memory");
    else if (rem == 1) asm volatile("cp.async.wait_group 1;" ::: "memory");
    else               asm volatile("cp.async.wait_group 0;" ::: "memory");
}

__device__ __forceinline__ void load_stage(
    uint32_t sbase, const __half* Ah, const __half* Al, const __half* Bh,
    int m0, int n0, int k0, int K, int tid, bool use_lo) {
    #pragma unroll
    for (int l = 0; l < 4; l++) {               // A: 256 rows x 4 x 16B
        int idx = tid + l * 256;
        int r = idx >> 2;
        int c = idx & 3;
        uint32_t so = (uint32_t)(r * PITCHB + c * 16);
        size_t ga = (size_t)(m0 + r) * K + k0 + c * 8;
        cp16(sbase + OFF_AH + so, Ah + ga);
        if (use_lo) cp16(sbase + OFF_AL + so, Al + ga);
    }
    #pragma unroll
    for (int l = 0; l < 2; l++) {               // B: 128 rows x 4 x 16B
        int idx = tid + l * 256;
        int r = idx >> 2;
        int c = idx & 3;
        uint32_t so = (uint32_t)(r * PITCHB + c * 16);
        size_t gb = (size_t)(n0 + r) * K + k0 + c * 8;
        cp16(sbase + OFF_BH + so, Bh + gb);
    }
    asm volatile("cp.async.commit_group;" ::: "memory");
}

// SPLIT_OUT=true: QKV path (fp16 hi/lo out, Q pre-scaled by 0.125).
// SPLIT_OUT=false: O projection (fp32 out, always 2 products).
template<bool SPLIT_OUT>
__global__ __launch_bounds__(256)
void gemm_mma(const __half* __restrict__ Ah, const __half* __restrict__ Al,
              const __half* __restrict__ Bh,
              float* __restrict__ C, __half* __restrict__ Ch,
              __half* __restrict__ Cl, int M, int N, int K) {
    extern __shared__ char smc[];
    const uint32_t sb = smem_u32(smc);
    const int tid = threadIdx.x;
    const int lane = tid & 31;
    const int wid = tid >> 5;
    const int wm = (wid & 3) * 64;
    const int wn = (wid >> 2) * 64;
    const int m0 = blockIdx.y * BM;
    const int n0 = blockIdx.x * BN;
    const bool use_lo = !SPLIT_OUT || (n0 < 768);   // K/V columns: 1 product

    float acc[4][8][4] = {};
    const int a_lr = lane & 15, a_lc = lane >> 4;
    const int b_lr = lane & 7, b_kh = (lane >> 3) & 1, b_nh = lane >> 4;

    const int nstage = K / BK;
    load_stage(sb, Ah, Al, Bh, m0, n0, 0, K, tid, use_lo);
    if (nstage > 1)
        load_stage(sb + STAGE_BYTES, Ah, Al, Bh, m0, n0, BK, K, tid, use_lo);

    for (int kt = 0; kt < nstage; kt++) {
        if (kt + 2 < nstage)
            load_stage(sb + (uint32_t)((kt + 2) % 3) * STAGE_BYTES,
                       Ah, Al, Bh, m0, n0, (kt + 2) * BK, K, tid, use_lo);
        wait_rem(nstage - kt - 1);
        __syncthreads();

        const uint32_t st = sb + (uint32_t)(kt % 3) * STAGE_BYTES;
        #pragma unroll
        for (int kk = 0; kk < 2; kk++) {
            const uint32_t kcol = (uint32_t)((kk * 16 + a_lc * 8) * 2);
            uint32_t ah[4][4], al[4][4];
            #pragma unroll
            for (int mi = 0; mi < 4; mi++) {
                uint32_t ro = (uint32_t)((wm + mi * 16 + a_lr) * PITCHB) + kcol;
                ldm4(ah[mi], st + OFF_AH + ro);
                if (use_lo) ldm4(al[mi], st + OFF_AL + ro);
            }
            const uint32_t bkcol = (uint32_t)((kk * 16 + b_kh * 8) * 2);
            uint32_t bh[4][4];
            #pragma unroll
            for (int ni = 0; ni < 4; ni++) {
                uint32_t ro = (uint32_t)((wn + ni * 16 + b_lr + b_nh * 8) * PITCHB) + bkcol;
                ldm4(bh[ni], st + OFF_BH + ro);
            }
            #pragma unroll
            for (int mi = 0; mi < 4; mi++)
                #pragma unroll
                for (int nj = 0; nj < 8; nj++) {
                    const int ni = nj >> 1, od = (nj & 1) * 2;
                    mma_f16(acc[mi][nj], ah[mi], bh[ni][od], bh[ni][od + 1]);
                    if (use_lo)
                        mma_f16(acc[mi][nj], al[mi], bh[ni][od], bh[ni][od + 1]);
                }
        }
        __syncthreads();
    }

    const int g = lane >> 2, t = lane & 3;
    // Q columns (< 768) pre-scaled by 1/sqrt(dk)=0.125 (exact in fp16).
    const float sc = (SPLIT_OUT && n0 < 768) ? 0.125f : 1.0f;
    #pragma unroll
    for (int mi = 0; mi < 4; mi++)
        #pragma unroll
        for (int nj = 0; nj < 8; nj++) {
            int row = m0 + wm + mi * 16 + g;
            int col = n0 + wn + nj * 8 + t * 2;
            if (SPLIT_OUT) {
                uint32_t h0, l0, h1, l1;
                split2h(acc[mi][nj][0] * sc, acc[mi][nj][1] * sc, h0, l0);
                split2h(acc[mi][nj][2] * sc, acc[mi][nj][3] * sc, h1, l1);
                *reinterpret_cast<uint32_t*>(&Ch[(size_t)row * N + col]) = h0;
                *reinterpret_cast<uint32_t*>(&Ch[(size_t)(row + 8) * N + col]) = h1;
                if (use_lo) {   // lo half only consumed for Q columns
                    *reinterpret_cast<uint32_t*>(&Cl[(size_t)row * N + col]) = l0;
                    *reinterpret_cast<uint32_t*>(&Cl[(size_t)(row + 8) * N + col]) = l1;
                }
            } else {
                *reinterpret_cast<float2*>(&C[(size_t)row * N + col]) =
                    make_float2(acc[mi][nj][0], acc[mi][nj][1]);
                *reinterpret_cast<float2*>(&C[(size_t)(row + 8) * N + col]) =
                    make_float2(acc[mi][nj][2], acc[mi][nj][3]);
            }
        }
}

// ---------------- fp16 causal flash attention ----------------
// S = (Qh+Ql)*Kh (2 products) ; O = Ph*Vh (1 product).  Q pre-scaled by 0.125.
#define P144 144
#define SQH 0
#define SQL 18432
#define SKV 36864
#define KVSTAGE 18432          // KH 0 | VH 9216
#define ATT_SMEM (SKV + 3 * KVSTAGE)   // 92160

__global__ __launch_bounds__(256, 2)
void attn_mma() {
    extern __shared__ char smc[];
    const uint32_t sb = smem_u32(smc);
    const int tid = threadIdx.x;
    const int lane = tid & 31;
    const int wid = tid >> 5;
    const int qb = (int)(gridDim.x - 1) - (int)blockIdx.x;   // heavy blocks first
    const int b = blockIdx.y / NUM_HEADS;
    const int h = blockIdx.y % NUM_HEADS;
    const int wm = wid * 16;
    const int g = lane >> 2, t = lane & 3;

    const size_t qrow0 = (size_t)b * SEQ + (size_t)qb * 128;
    const size_t krow0 = (size_t)b * SEQ;
    const size_t qoff = (size_t)h * DK;
    const size_t koff = 768 + (size_t)h * DK;
    const size_t voff = 1536 + (size_t)h * DK;

    // Q tiles (hi+lo fp16), persistent
    #pragma unroll
    for (int l = 0; l < 4; l++) {
        int idx = tid + l * 256;
        int r = idx >> 3, c = idx & 7;
        size_t ga = (qrow0 + r) * D_QKV + qoff + c * 8;
        uint32_t so = (uint32_t)(r * P144 + c * 16);
        cp16(sb + SQH + so, g_qkvh + ga);
        cp16(sb + SQL + so, g_qkvl + ga);
    }

    const int ntiles = 2 * qb + 2;
    auto load_kv = [&](int kt) {
        uint32_t stb = sb + SKV + (uint32_t)(kt % 3) * KVSTAGE;
        #pragma unroll
        for (int l = 0; l < 2; l++) {
            int idx = tid + l * 256;
            int r = idx >> 3, c = idx & 7;
            size_t grow = (krow0 + (size_t)kt * 64 + r) * D_QKV;
            uint32_t so = (uint32_t)(r * P144 + c * 16);
            cp16(stb + so, g_qkvh + grow + koff + c * 8);
            cp16(stb + 9216 + so, g_qkvh + grow + voff + c * 8);
        }
        asm volatile("cp.async.commit_group;" ::: "memory");
    };

    load_kv(0);
    if (ntiles > 1) load_kv(1);
    if (ntiles > 2) load_kv(2);

    float oacc[8][4] = {};
    float m_i[2] = {-INFINITY, -INFINITY};
    float l_i[2] = {0.0f, 0.0f};

    const int a_lr = lane & 15, a_lc = lane >> 4;
    const int b_lr = lane & 7, b_kh = (lane >> 3) & 1, b_nh = lane >> 4;
    const int v_r = lane & 15, v_c = (lane >> 4) * 8;

    for (int kt = 0; kt < ntiles; kt++) {
        wait_rem(ntiles - kt - 1);
        __syncthreads();

        const uint32_t stb = sb + SKV + (uint32_t)(kt % 3) * KVSTAGE;
        const bool skip = (kt == 2 * qb + 1) && (wid < 4);

        if (!skip) {
            float sacc[8][4] = {};
            #pragma unroll
            for (int kk = 0; kk < 4; kk++) {
                const uint32_t kcol = (uint32_t)((kk * 16 + a_lc * 8) * 2);
                uint32_t qh[4], ql[4];
                ldm4(qh, sb + SQH + (uint32_t)((wm + a_lr) * P144) + kcol);
                ldm4(ql, sb + SQL + (uint32_t)((wm + a_lr) * P144) + kcol);
                const uint32_t bkcol = (uint32_t)((kk * 16 + b_kh * 8) * 2);
                #pragma unroll
                for (int np = 0; np < 4; np++) {
                    uint32_t kh[4];
                    ldm4(kh, stb + (uint32_t)((np * 16 + b_lr + b_nh * 8) * P144) + bkcol);
                    mma_f16(sacc[2 * np],     qh, kh[0], kh[1]);
                    mma_f16(sacc[2 * np],     ql, kh[0], kh[1]);
                    mma_f16(sacc[2 * np + 1], qh, kh[2], kh[3]);
                    mma_f16(sacc[2 * np + 1], ql, kh[2], kh[3]);
                }
            }

            const bool needmask = (kt == 2 * qb && wid < 4) ||
                                  (kt == 2 * qb + 1 && wid >= 4);
            if (needmask) {
                const int grow0 = qb * 128 + wm + g;
                #pragma unroll
                for (int nt = 0; nt < 8; nt++) {
                    const int gcol = kt * 64 + nt * 8 + t * 2;
                    #pragma unroll
                    for (int j = 0; j < 4; j++) {
                        const int row = grow0 + (j >> 1) * 8;
                        const int col = gcol + (j & 1);
                        if (col > row) sacc[nt][j] = -INFINITY;
                    }
                }
            }

            #pragma unroll
            for (int hh = 0; hh < 2; hh++) {
                float rm = -INFINITY;
                #pragma unroll
                for (int nt = 0; nt < 8; nt++)
                    rm = fmaxf(rm, fmaxf(sacc[nt][2 * hh], sacc[nt][2 * hh + 1]));
                rm = fmaxf(rm, __shfl_xor_sync(0xffffffffu, rm, 1));
                rm = fmaxf(rm, __shfl_xor_sync(0xffffffffu, rm, 2));
                float mn = fmaxf(m_i[hh], rm);
                float alpha = __expf(m_i[hh] - mn);
                float rs = 0.0f;
                #pragma unroll
                for (int nt = 0; nt < 8; nt++) {
                    float p0 = __expf(sacc[nt][2 * hh] - mn);
                    float p1 = __expf(sacc[nt][2 * hh + 1] - mn);
                    sacc[nt][2 * hh] = p0;
                    sacc[nt][2 * hh + 1] = p1;
                    rs += p0 + p1;
                }
                rs += __shfl_xor_sync(0xffffffffu, rs, 1);
                rs += __shfl_xor_sync(0xffffffffu, rs, 2);
                l_i[hh] = l_i[hh] * alpha + rs;
                m_i[hh] = mn;
                #pragma unroll
                for (int nt = 0; nt < 8; nt++) {
                    oacc[nt][2 * hh] *= alpha;
                    oacc[nt][2 * hh + 1] *= alpha;
                }
            }

            // ---- O += Ph Vh (1 product) ----
            #pragma unroll
            for (int ks = 0; ks < 4; ks++) {
                uint32_t ph[4];
                ph[0] = pack2h(sacc[2 * ks][0],     sacc[2 * ks][1]);
                ph[1] = pack2h(sacc[2 * ks][2],     sacc[2 * ks][3]);
                ph[2] = pack2h(sacc[2 * ks + 1][0], sacc[2 * ks + 1][1]);
                ph[3] = pack2h(sacc[2 * ks + 1][2], sacc[2 * ks + 1][3]);
                const uint32_t vrow = (uint32_t)((ks * 16 + v_r) * P144);
                #pragma unroll
                for (int np = 0; np < 4; np++) {
                    uint32_t vh[4];
                    ldm4t(vh, stb + 9216 + vrow + (uint32_t)((np * 16 + v_c) * 2));
                    mma_f16(oacc[2 * np],     ph, vh[0], vh[1]);
                    mma_f16(oacc[2 * np + 1], ph, vh[2], vh[3]);
                }
            }
        }

        __syncthreads();
        if (kt + 3 < ntiles) load_kv(kt + 3);
    }

    // epilogue: normalize, split to fp16 hi/lo for the O projection
    const float inv0 = 1.0f / l_i[0], inv1 = 1.0f / l_i[1];
    const size_t hoff = (size_t)h * DK;
    #pragma unroll
    for (int nt = 0; nt < 8; nt++) {
        size_t r0 = (qrow0 + wm + g) * D_MODEL + hoff + nt * 8 + t * 2;
        size_t r1 = r0 + 8 * D_MODEL;
        uint32_t h0, l0, h1, l1;
        split2h(oacc[nt][0] * inv0, oacc[nt][1] * inv0, h0, l0);
        split2h(oacc[nt][2] * inv1, oacc[nt][3] * inv1, h1, l1);
        *reinterpret_cast<uint32_t*>(&g_ah[r0]) = h0;
        *reinterpret_cast<uint32_t*>(&g_al[r0]) = l0;
        *reinterpret_cast<uint32_t*>(&g_ah[r1]) = h1;
        *reinterpret_cast<uint32_t*>(&g_al[r1]) = l1;
    }
}

// ---------------- launch ----------------
extern "C" void kernel_launch(void* const* d_in, const int* in_sizes, int n_in,
                              void* d_out, int out_size) {
    const float* x  = (const float*)d_in[0];
    const float* wq = (const float*)d_in[1];
    const float* wk = (const float*)d_in[2];
    const float* wv = (const float*)d_in[3];
    const float* wo = (const float*)d_in[4];
    float* out = (float*)d_out;

    __half *xh, *xl, *qkvh, *qkvl, *ah, *al, *wh;
    cudaGetSymbolAddress((void**)&xh, g_xh);
    cudaGetSymbolAddress((void**)&xl, g_xl);
    cudaGetSymbolAddress((void**)&qkvh, g_qkvh);
    cudaGetSymbolAddress((void**)&qkvl, g_qkvl);
    cudaGetSymbolAddress((void**)&ah, g_ah);
    cudaGetSymbolAddress((void**)&al, g_al);
    cudaGetSymbolAddress((void**)&wh, g_wh);

    // 1. x -> fp16 hi/lo; weights -> fp16 (one fused launch, q|k|v|o)
    split_kernel<<<(XN / 4 + 255) / 256, 256>>>(x, xh, xl, XN / 4);
    dim3 rgrid((WN / 4 + 255) / 256, 4);
    round4_kernel<<<rgrid, 256>>>(wq, wk, wv, wo, wh, WN / 4);

    // 2. fused QKV projection (N = 2304) -> fp16, Q pre-scaled + hi/lo
    cudaFuncSetAttribute(gemm_mma<true>, cudaFuncAttributeMaxDynamicSharedMemorySize, GEMM_SMEM);
    cudaFuncSetAttribute(gemm_mma<false>, cudaFuncAttributeMaxDynamicSharedMemorySize, GEMM_SMEM);
    dim3 qkvgrid(D_QKV / BN, MTOT / BM);   // (18, 16)
    gemm_mma<true><<<qkvgrid, 256, GEMM_SMEM>>>(xh, xl, wh,
                                                nullptr, qkvh, qkvl,
                                                MTOT, D_QKV, D_MODEL);

    // 3. fp16 flash attention (S 2-product, PV 1-product)
    cudaFuncSetAttribute(attn_mma, cudaFuncAttributeMaxDynamicSharedMemorySize, ATT_SMEM);
    dim3 agrid(SEQ / 128, BATCH * NUM_HEADS);
    attn_mma<<<agrid, 256, ATT_SMEM>>>();

    // 4. output projection -> fp32 (2 products)
    dim3 ogrid(D_MODEL / BN, MTOT / BM);   // (6, 16)
    gemm_mma<false><<<ogrid, 256, GEMM_SMEM>>>(ah, al, wh + 3 * WN,
                                               out, nullptr, nullptr,
                                               MTOT, D_MODEL, D_MODEL);
}

// round 10
// speedup vs baseline: 4.5096x; 1.0874x over previous
#include <cuda_runtime.h>
#include <cuda_bf16.h>
#include <cuda_fp16.h>
#include <math.h>
#include <stdint.h>

#define D_MODEL 768
#define NUM_HEADS 12
#define DK 64
#define BATCH 2
#define SEQ 2048
#define MTOT (BATCH * SEQ)          // 4096
#define XN (MTOT * D_MODEL)         // 3145728
#define WN (D_MODEL * D_MODEL)      // 589824
#define D_QKV 2304                  // fused Q|K|V column dim

// ---------------- scratch ----------------
__device__ __half g_xh[XN], g_xl[XN];
__device__ __half g_qkvh[MTOT * D_QKV], g_qkvl[MTOT * D_QKV];
__device__ __half g_ah[XN];
__device__ __half g_wh[4 * WN];          // fp16-rounded weights q|k|v|o

// ---------------- helpers ----------------
__device__ __forceinline__ uint32_t smem_u32(const void* p) {
    uint32_t a;
    asm("{ .reg .u64 t; cvta.to.shared.u64 t, %1; cvt.u32.u64 %0, t; }"
        : "=r"(a) : "l"(p));
    return a;
}
__device__ __forceinline__ void cp16(uint32_t saddr, const void* gaddr) {
    asm volatile("cp.async.cg.shared.global [%0], [%1], 16;"
                 :: "r"(saddr), "l"(gaddr) : "memory");
}
__device__ __forceinline__ void ldm4(uint32_t* r, uint32_t addr) {
    asm volatile("ldmatrix.sync.aligned.m8n8.x4.shared.b16 {%0,%1,%2,%3}, [%4];"
                 : "=r"(r[0]), "=r"(r[1]), "=r"(r[2]), "=r"(r[3]) : "r"(addr));
}
__device__ __forceinline__ void ldm4t(uint32_t* r, uint32_t addr) {
    asm volatile("ldmatrix.sync.aligned.m8n8.x4.trans.shared.b16 {%0,%1,%2,%3}, [%4];"
                 : "=r"(r[0]), "=r"(r[1]), "=r"(r[2]), "=r"(r[3]) : "r"(addr));
}
__device__ __forceinline__ void mma_f16(float* c, const uint32_t* a,
                                        uint32_t b0, uint32_t b1) {
    asm volatile(
        "mma.sync.aligned.m16n8k16.row.col.f32.f16.f16.f32 "
        "{%0,%1,%2,%3}, {%4,%5,%6,%7}, {%8,%9}, {%0,%1,%2,%3};"
        : "+f"(c[0]), "+f"(c[1]), "+f"(c[2]), "+f"(c[3])
        : "r"(a[0]), "r"(a[1]), "r"(a[2]), "r"(a[3]), "r"(b0), "r"(b1));
}
__device__ __forceinline__ uint32_t pack2h(float x, float y) {
    __half2 v(__float2half_rn(x), __float2half_rn(y));
    return *reinterpret_cast<uint32_t*>(&v);
}
__device__ __forceinline__ void split2h(float x, float y, uint32_t& h, uint32_t& l) {
    __half hx = __float2half_rn(x), hy = __float2half_rn(y);
    __half2 vh(hx, hy);
    __half2 vl(__float2half_rn(x - __half2float(hx)),
               __float2half_rn(y - __half2float(hy)));
    h = *reinterpret_cast<uint32_t*>(&vh);
    l = *reinterpret_cast<uint32_t*>(&vl);
}

// ---------------- fp32 -> fp16 hi/lo split ----------------
__global__ __launch_bounds__(256)
void split_kernel(const float* __restrict__ src, __half* __restrict__ hi,
                  __half* __restrict__ lo, int n4) {
    int i = blockIdx.x * blockDim.x + threadIdx.x;
    if (i >= n4) return;
    float4 v = reinterpret_cast<const float4*>(src)[i];
    uint32_t h0, l0, h1, l1;
    split2h(v.x, v.y, h0, l0);
    split2h(v.z, v.w, h1, l1);
    reinterpret_cast<uint2*>(hi)[i] = make_uint2(h0, h1);
    reinterpret_cast<uint2*>(lo)[i] = make_uint2(l0, l1);
}

// ---------------- fp32 -> fp16 round, all 4 weights in one launch ----------------
__global__ __launch_bounds__(256)
void round4_kernel(const float* __restrict__ w0, const float* __restrict__ w1,
                   const float* __restrict__ w2, const float* __restrict__ w3,
                   __half* __restrict__ dst, int n4) {
    int i = blockIdx.x * blockDim.x + threadIdx.x;
    if (i >= n4) return;
    const float* src = (blockIdx.y == 0) ? w0 : (blockIdx.y == 1) ? w1
                     : (blockIdx.y == 2) ? w2 : w3;
    float4 v = reinterpret_cast<const float4*>(src)[i];
    __half2 a(__float2half_rn(v.x), __float2half_rn(v.y));
    __half2 b(__float2half_rn(v.z), __float2half_rn(v.w));
    reinterpret_cast<uint2*>(dst)[(size_t)blockIdx.y * n4 + i] =
        make_uint2(*reinterpret_cast<uint32_t*>(&a), *reinterpret_cast<uint32_t*>(&b));
}

// ---------------- fp16 NT GEMM: C = (Ah[+Al])*Bh ----------------
// Block 256x128, BK=32, 8 warps (4 in M x 2 in N), warp tile 64x64. 3-stage.
#define BM 256
#define BN 128
#define BK 32
#define PITCHB 80
#define ATILE (256 * PITCHB)         // 20480
#define BTILE (128 * PITCHB)         // 10240
#define OFF_AH 0
#define OFF_AL ATILE
#define OFF_BH (2 * ATILE)
#define STAGE_BYTES (2 * ATILE + BTILE)       // 51200
#define GEMM_SMEM (3 * STAGE_BYTES)           // 153600

__device__ __forceinline__ void wait_rem(int rem) {
    if (rem >= 2)      asm volatile("cp.async.wait_group 2;" ::: "memory");
    else if (rem == 1) asm volatile("cp.async.wait_group 1;" ::: "memory");
    else               asm volatile("cp.async.wait_group 0;" ::: "memory");
}

__device__ __forceinline__ void load_stage(
    uint32_t sbase, const __half* Ah, const __half* Al, const __half* Bh,
    int m0, int n0, int k0, int K, int tid, bool use_lo) {
    #pragma unroll
    for (int l = 0; l < 4; l++) {               // A: 256 rows x 4 x 16B
        int idx = tid + l * 256;
        int r = idx >> 2;
        int c = idx & 3;
        uint32_t so = (uint32_t)(r * PITCHB + c * 16);
        size_t ga = (size_t)(m0 + r) * K + k0 + c * 8;
        cp16(sbase + OFF_AH + so, Ah + ga);
        if (use_lo) cp16(sbase + OFF_AL + so, Al + ga);
    }
    #pragma unroll
    for (int l = 0; l < 2; l++) {               // B: 128 rows x 4 x 16B
        int idx = tid + l * 256;
        int r = idx >> 2;
        int c = idx & 3;
        uint32_t so = (uint32_t)(r * PITCHB + c * 16);
        size_t gb = (size_t)(n0 + r) * K + k0 + c * 8;
        cp16(sbase + OFF_BH + so, Bh + gb);
    }
    asm volatile("cp.async.commit_group;" ::: "memory");
}

// SPLIT_OUT=true: QKV path. Q cols (n0<768): 2 products, hi/lo out, scaled by
//   0.125*log2(e) for the base-2 softmax. K/V cols: 1 product, hi out.
// SPLIT_OUT=false: O projection, fp32 out; LO2 selects 1 vs 2 products.
template<bool SPLIT_OUT, bool LO2>
__global__ __launch_bounds__(256)
void gemm_mma(const __half* __restrict__ Ah, const __half* __restrict__ Al,
              const __half* __restrict__ Bh,
              float* __restrict__ C, __half* __restrict__ Ch,
              __half* __restrict__ Cl, int M, int N, int K) {
    extern __shared__ char smc[];
    const uint32_t sb = smem_u32(smc);
    const int tid = threadIdx.x;
    const int lane = tid & 31;
    const int wid = tid >> 5;
    const int wm = (wid & 3) * 64;
    const int wn = (wid >> 2) * 64;
    const int m0 = blockIdx.y * BM;
    const int n0 = blockIdx.x * BN;
    const bool use_lo = SPLIT_OUT ? (n0 < 768) : LO2;

    float acc[4][8][4] = {};
    const int a_lr = lane & 15, a_lc = lane >> 4;
    const int b_lr = lane & 7, b_kh = (lane >> 3) & 1, b_nh = lane >> 4;

    const int nstage = K / BK;
    load_stage(sb, Ah, Al, Bh, m0, n0, 0, K, tid, use_lo);
    if (nstage > 1)
        load_stage(sb + STAGE_BYTES, Ah, Al, Bh, m0, n0, BK, K, tid, use_lo);

    for (int kt = 0; kt < nstage; kt++) {
        if (kt + 2 < nstage)
            load_stage(sb + (uint32_t)((kt + 2) % 3) * STAGE_BYTES,
                       Ah, Al, Bh, m0, n0, (kt + 2) * BK, K, tid, use_lo);
        wait_rem(nstage - kt - 1);
        __syncthreads();

        const uint32_t st = sb + (uint32_t)(kt % 3) * STAGE_BYTES;
        #pragma unroll
        for (int kk = 0; kk < 2; kk++) {
            const uint32_t kcol = (uint32_t)((kk * 16 + a_lc * 8) * 2);
            uint32_t ah[4][4], al[4][4];
            #pragma unroll
            for (int mi = 0; mi < 4; mi++) {
                uint32_t ro = (uint32_t)((wm + mi * 16 + a_lr) * PITCHB) + kcol;
                ldm4(ah[mi], st + OFF_AH + ro);
                if (use_lo) ldm4(al[mi], st + OFF_AL + ro);
            }
            const uint32_t bkcol = (uint32_t)((kk * 16 + b_kh * 8) * 2);
            uint32_t bh[4][4];
            #pragma unroll
            for (int ni = 0; ni < 4; ni++) {
                uint32_t ro = (uint32_t)((wn + ni * 16 + b_lr + b_nh * 8) * PITCHB) + bkcol;
                ldm4(bh[ni], st + OFF_BH + ro);
            }
            #pragma unroll
            for (int mi = 0; mi < 4; mi++)
                #pragma unroll
                for (int nj = 0; nj < 8; nj++) {
                    const int ni = nj >> 1, od = (nj & 1) * 2;
                    mma_f16(acc[mi][nj], ah[mi], bh[ni][od], bh[ni][od + 1]);
                    if (use_lo)
                        mma_f16(acc[mi][nj], al[mi], bh[ni][od], bh[ni][od + 1]);
                }
        }
        __syncthreads();
    }

    const int g = lane >> 2, t = lane & 3;
    // Q columns scaled by 0.125*log2(e) for the exp2-based softmax.
    const float sc = (SPLIT_OUT && n0 < 768) ? 0.180336880111112f : 1.0f;
    #pragma unroll
    for (int mi = 0; mi < 4; mi++)
        #pragma unroll
        for (int nj = 0; nj < 8; nj++) {
            int row = m0 + wm + mi * 16 + g;
            int col = n0 + wn + nj * 8 + t * 2;
            if (SPLIT_OUT) {
                uint32_t h0, l0, h1, l1;
                split2h(acc[mi][nj][0] * sc, acc[mi][nj][1] * sc, h0, l0);
                split2h(acc[mi][nj][2] * sc, acc[mi][nj][3] * sc, h1, l1);
                *reinterpret_cast<uint32_t*>(&Ch[(size_t)row * N + col]) = h0;
                *reinterpret_cast<uint32_t*>(&Ch[(size_t)(row + 8) * N + col]) = h1;
                if (use_lo) {   // lo half only consumed for Q columns
                    *reinterpret_cast<uint32_t*>(&Cl[(size_t)row * N + col]) = l0;
                    *reinterpret_cast<uint32_t*>(&Cl[(size_t)(row + 8) * N + col]) = l1;
                }
            } else {
                *reinterpret_cast<float2*>(&C[(size_t)row * N + col]) =
                    make_float2(acc[mi][nj][0], acc[mi][nj][1]);
                *reinterpret_cast<float2*>(&C[(size_t)(row + 8) * N + col]) =
                    make_float2(acc[mi][nj][2], acc[mi][nj][3]);
            }
        }
}

// ---------------- fp16 causal flash attention (base-2 softmax) ----------------
// S = (Qh+Ql)*Kh, scores pre-scaled by 0.125*log2(e); softmax via exp2f.
// O = Ph*Vh (1 product). 4 KV buffers, ONE barrier per tile:
//   wait_group(own) -> __syncthreads (publish all threads' tile kt; prove
//   tile kt-1 reads done) -> prefetch kt+3 into (kt+3)%4 == (kt-1)%4 -> compute.
#define P144 144
#define SQH 0
#define SQL 18432
#define SKV 36864
#define KVSTAGE 18432          // KH 0 | VH 9216
#define ATT_SMEM (SKV + 4 * KVSTAGE)   // 110592

__global__ __launch_bounds__(256, 2)
void attn_mma() {
    extern __shared__ char smc[];
    const uint32_t sb = smem_u32(smc);
    const int tid = threadIdx.x;
    const int lane = tid & 31;
    const int wid = tid >> 5;
    const int qb = (int)(gridDim.x - 1) - (int)blockIdx.x;   // heavy blocks first
    const int b = blockIdx.y / NUM_HEADS;
    const int h = blockIdx.y % NUM_HEADS;
    const int wm = wid * 16;
    const int g = lane >> 2, t = lane & 3;

    const size_t qrow0 = (size_t)b * SEQ + (size_t)qb * 128;
    const size_t krow0 = (size_t)b * SEQ;
    const size_t qoff = (size_t)h * DK;
    const size_t koff = 768 + (size_t)h * DK;
    const size_t voff = 1536 + (size_t)h * DK;

    // Q tiles (hi+lo fp16), persistent; folded into group 0 with load_kv(0)
    #pragma unroll
    for (int l = 0; l < 4; l++) {
        int idx = tid + l * 256;
        int r = idx >> 3, c = idx & 7;
        size_t ga = (qrow0 + r) * D_QKV + qoff + c * 8;
        uint32_t so = (uint32_t)(r * P144 + c * 16);
        cp16(sb + SQH + so, g_qkvh + ga);
        cp16(sb + SQL + so, g_qkvl + ga);
    }

    const int ntiles = 2 * qb + 2;
    auto load_kv = [&](int kt) {
        uint32_t stb = sb + SKV + (uint32_t)(kt & 3) * KVSTAGE;
        #pragma unroll
        for (int l = 0; l < 2; l++) {
            int idx = tid + l * 256;
            int r = idx >> 3, c = idx & 7;
            size_t grow = (krow0 + (size_t)kt * 64 + r) * D_QKV;
            uint32_t so = (uint32_t)(r * P144 + c * 16);
            cp16(stb + so, g_qkvh + grow + koff + c * 8);
            cp16(stb + 9216 + so, g_qkvh + grow + voff + c * 8);
        }
        asm volatile("cp.async.commit_group;" ::: "memory");
    };

    // prologue: 3 tiles in flight (groups 0,1,2)
    load_kv(0);
    if (ntiles > 1) load_kv(1);
    if (ntiles > 2) load_kv(2);

    float oacc[8][4] = {};
    float m_i[2] = {-INFINITY, -INFINITY};
    float l_i[2] = {0.0f, 0.0f};

    const int a_lr = lane & 15, a_lc = lane >> 4;
    const int b_lr = lane & 7, b_kh = (lane >> 3) & 1, b_nh = lane >> 4;
    const int v_r = lane & 15, v_c = (lane >> 4) * 8;

    for (int kt = 0; kt < ntiles; kt++) {
        // own groups: committed up to min(kt+2, ntiles-1); need group kt done.
        int rem = ntiles - 1 - kt;
        wait_rem(rem < 2 ? rem : 2);
        __syncthreads();   // publish tile kt from ALL threads; tile kt-1 reads done
        if (kt + 3 < ntiles) load_kv(kt + 3);   // overwrites (kt-1)&3 — safe now

        const uint32_t stb = sb + SKV + (uint32_t)(kt & 3) * KVSTAGE;
        const bool skip = (kt == 2 * qb + 1) && (wid < 4);

        if (!skip) {
            float sacc[8][4] = {};
            #pragma unroll
            for (int kk = 0; kk < 4; kk++) {
                const uint32_t kcol = (uint32_t)((kk * 16 + a_lc * 8) * 2);
                uint32_t qh[4], ql[4];
                ldm4(qh, sb + SQH + (uint32_t)((wm + a_lr) * P144) + kcol);
                ldm4(ql, sb + SQL + (uint32_t)((wm + a_lr) * P144) + kcol);
                const uint32_t bkcol = (uint32_t)((kk * 16 + b_kh * 8) * 2);
                #pragma unroll
                for (int np = 0; np < 4; np++) {
                    uint32_t kh[4];
                    ldm4(kh, stb + (uint32_t)((np * 16 + b_lr + b_nh * 8) * P144) + bkcol);
                    mma_f16(sacc[2 * np],     qh, kh[0], kh[1]);
                    mma_f16(sacc[2 * np],     ql, kh[0], kh[1]);
                    mma_f16(sacc[2 * np + 1], qh, kh[2], kh[3]);
                    mma_f16(sacc[2 * np + 1], ql, kh[2], kh[3]);
                }
            }

            const bool needmask = (kt == 2 * qb && wid < 4) ||
                                  (kt == 2 * qb + 1 && wid >= 4);
            if (needmask) {
                const int grow0 = qb * 128 + wm + g;
                #pragma unroll
                for (int nt = 0; nt < 8; nt++) {
                    const int gcol = kt * 64 + nt * 8 + t * 2;
                    #pragma unroll
                    for (int j = 0; j < 4; j++) {
                        const int row = grow0 + (j >> 1) * 8;
                        const int col = gcol + (j & 1);
                        if (col > row) sacc[nt][j] = -INFINITY;
                    }
                }
            }

            // base-2 online softmax per row-half
            #pragma unroll
            for (int hh = 0; hh < 2; hh++) {
                float rm = -INFINITY;
                #pragma unroll
                for (int nt = 0; nt < 8; nt++)
                    rm = fmaxf(rm, fmaxf(sacc[nt][2 * hh], sacc[nt][2 * hh + 1]));
                rm = fmaxf(rm, __shfl_xor_sync(0xffffffffu, rm, 1));
                rm = fmaxf(rm, __shfl_xor_sync(0xffffffffu, rm, 2));
                float mn = fmaxf(m_i[hh], rm);
                float alpha = exp2f(m_i[hh] - mn);
                float rs = 0.0f;
                #pragma unroll
                for (int nt = 0; nt < 8; nt++) {
                    float p0 = exp2f(sacc[nt][2 * hh] - mn);
                    float p1 = exp2f(sacc[nt][2 * hh + 1] - mn);
                    sacc[nt][2 * hh] = p0;
                    sacc[nt][2 * hh + 1] = p1;
                    rs += p0 + p1;
                }
                rs += __shfl_xor_sync(0xffffffffu, rs, 1);
                rs += __shfl_xor_sync(0xffffffffu, rs, 2);
                l_i[hh] = l_i[hh] * alpha + rs;
                m_i[hh] = mn;
                #pragma unroll
                for (int nt = 0; nt < 8; nt++) {
                    oacc[nt][2 * hh] *= alpha;
                    oacc[nt][2 * hh + 1] *= alpha;
                }
            }

            // O += Ph Vh (1 product)
            #pragma unroll
            for (int ks = 0; ks < 4; ks++) {
                uint32_t ph[4];
                ph[0] = pack2h(sacc[2 * ks][0],     sacc[2 * ks][1]);
                ph[1] = pack2h(sacc[2 * ks][2],     sacc[2 * ks][3]);
                ph[2] = pack2h(sacc[2 * ks + 1][0], sacc[2 * ks + 1][1]);
                ph[3] = pack2h(sacc[2 * ks + 1][2], sacc[2 * ks + 1][3]);
                const uint32_t vrow = (uint32_t)((ks * 16 + v_r) * P144);
                #pragma unroll
                for (int np = 0; np < 4; np++) {
                    uint32_t vh[4];
                    ldm4t(vh, stb + 9216 + vrow + (uint32_t)((np * 16 + v_c) * 2));
                    mma_f16(oacc[2 * np],     ph, vh[0], vh[1]);
                    mma_f16(oacc[2 * np + 1], ph, vh[2], vh[3]);
                }
            }
        }
    }

    // epilogue: normalize, round to fp16 (O projection reads hi only)
    const float inv0 = 1.0f / l_i[0], inv1 = 1.0f / l_i[1];
    const size_t hoff = (size_t)h * DK;
    #pragma unroll
    for (int nt = 0; nt < 8; nt++) {
        size_t r0 = (qrow0 + wm + g) * D_MODEL + hoff + nt * 8 + t * 2;
        size_t r1 = r0 + 8 * D_MODEL;
        *reinterpret_cast<uint32_t*>(&g_ah[r0]) =
            pack2h(oacc[nt][0] * inv0, oacc[nt][1] * inv0);
        *reinterpret_cast<uint32_t*>(&g_ah[r1]) =
            pack2h(oacc[nt][2] * inv1, oacc[nt][3] * inv1);
    }
}

// ---------------- launch ----------------
extern "C" void kernel_launch(void* const* d_in, const int* in_sizes, int n_in,
                              void* d_out, int out_size) {
    const float* x  = (const float*)d_in[0];
    const float* wq = (const float*)d_in[1];
    const float* wk = (const float*)d_in[2];
    const float* wv = (const float*)d_in[3];
    const float* wo = (const float*)d_in[4];
    float* out = (float*)d_out;

    __half *xh, *xl, *qkvh, *qkvl, *ah, *wh;
    cudaGetSymbolAddress((void**)&xh, g_xh);
    cudaGetSymbolAddress((void**)&xl, g_xl);
    cudaGetSymbolAddress((void**)&qkvh, g_qkvh);
    cudaGetSymbolAddress((void**)&qkvl, g_qkvl);
    cudaGetSymbolAddress((void**)&ah, g_ah);
    cudaGetSymbolAddress((void**)&wh, g_wh);

    // 1. x -> fp16 hi/lo; weights -> fp16 (one fused launch, q|k|v|o)
    split_kernel<<<(XN / 4 + 255) / 256, 256>>>(x, xh, xl, XN / 4);
    dim3 rgrid((WN / 4 + 255) / 256, 4);
    round4_kernel<<<rgrid, 256>>>(wq, wk, wv, wo, wh, WN / 4);

    // 2. fused QKV projection (N = 2304)
    cudaFuncSetAttribute((const void*)gemm_mma<true, true>,
                         cudaFuncAttributeMaxDynamicSharedMemorySize, GEMM_SMEM);
    cudaFuncSetAttribute((const void*)gemm_mma<false, false>,
                         cudaFuncAttributeMaxDynamicSharedMemorySize, GEMM_SMEM);
    dim3 qkvgrid(D_QKV / BN, MTOT / BM);   // (18, 16)
    gemm_mma<true, true><<<qkvgrid, 256, GEMM_SMEM>>>(xh, xl, wh,
                                                      nullptr, qkvh, qkvl,
                                                      MTOT, D_QKV, D_MODEL);

    // 3. fp16 flash attention (S 2-product, PV 1-product, base-2 softmax)
    cudaFuncSetAttribute(attn_mma, cudaFuncAttributeMaxDynamicSharedMemorySize, ATT_SMEM);
    dim3 agrid(SEQ / 128, BATCH * NUM_HEADS);
    attn_mma<<<agrid, 256, ATT_SMEM>>>();

    // 4. output projection -> fp32 (1 product)
    dim3 ogrid(D_MODEL / BN, MTOT / BM);   // (6, 16)
    gemm_mma<false, false><<<ogrid, 256, GEMM_SMEM>>>(ah, ah, wh + 3 * WN,
                                                      out, nullptr, nullptr,
                                                      MTOT, D_MODEL, D_MODEL);
}

// round 11
// speedup vs baseline: 5.1191x; 1.1352x over previous
#include <cuda_runtime.h>
#include <cuda_bf16.h>
#include <cuda_fp16.h>
#include <math.h>
#include <stdint.h>

#define D_MODEL 768
#define NUM_HEADS 12
#define DK 64
#define BATCH 2
#define SEQ 2048
#define MTOT (BATCH * SEQ)          // 4096
#define XN (MTOT * D_MODEL)         // 3145728
#define WN (D_MODEL * D_MODEL)      // 589824
#define D_QKV 2304                  // fused Q|K|V column dim

// ---------------- scratch ----------------
__device__ __half g_xh[XN], g_xl[XN];
__device__ __half g_qkvh[MTOT * D_QKV], g_qkvl[MTOT * D_QKV];
__device__ __half g_ah[XN];
__device__ __half g_wh[4 * WN];              // fp16-rounded weights q|k|v|o
__device__ float g_part[24 * 8 * 2 * 8192];  // split-KV partial O (unnormalized)
__device__ float g_ml[24 * 8 * 2 * 256];     // split-KV per-row (m, l)

// work items per (b,h): heaviest-first. {qb, kt_begin, kt_end, half(-1=light)}
__device__ const int4 g_items[24] = {
    {7,0,16,-1},{15,0,16,0},{15,16,32,1},{14,0,15,0},{14,15,30,1},{6,0,14,-1},
    {13,0,14,0},{13,14,28,1},{12,0,13,0},{12,13,26,1},{5,0,12,-1},{11,0,12,0},
    {11,12,24,1},{10,0,11,0},{10,11,22,1},{4,0,10,-1},{9,0,10,0},{9,10,20,1},
    {8,0,9,0},{8,9,18,1},{3,0,8,-1},{2,0,6,-1},{1,0,4,-1},{0,0,2,-1}
};

// ---------------- helpers ----------------
__device__ __forceinline__ uint32_t smem_u32(const void* p) {
    uint32_t a;
    asm("{ .reg .u64 t; cvta.to.shared.u64 t, %1; cvt.u32.u64 %0, t; }"
        : "=r"(a) : "l"(p));
    return a;
}
__device__ __forceinline__ void cp16(uint32_t saddr, const void* gaddr) {
    asm volatile("cp.async.cg.shared.global [%0], [%1], 16;"
                 :: "r"(saddr), "l"(gaddr) : "memory");
}
__device__ __forceinline__ void ldm4(uint32_t* r, uint32_t addr) {
    asm volatile("ldmatrix.sync.aligned.m8n8.x4.shared.b16 {%0,%1,%2,%3}, [%4];"
                 : "=r"(r[0]), "=r"(r[1]), "=r"(r[2]), "=r"(r[3]) : "r"(addr));
}
__device__ __forceinline__ void ldm4t(uint32_t* r, uint32_t addr) {
    asm volatile("ldmatrix.sync.aligned.m8n8.x4.trans.shared.b16 {%0,%1,%2,%3}, [%4];"
                 : "=r"(r[0]), "=r"(r[1]), "=r"(r[2]), "=r"(r[3]) : "r"(addr));
}
__device__ __forceinline__ void mma_f16(float* c, const uint32_t* a,
                                        uint32_t b0, uint32_t b1) {
    asm volatile(
        "mma.sync.aligned.m16n8k16.row.col.f32.f16.f16.f32 "
        "{%0,%1,%2,%3}, {%4,%5,%6,%7}, {%8,%9}, {%0,%1,%2,%3};"
        : "+f"(c[0]), "+f"(c[1]), "+f"(c[2]), "+f"(c[3])
        : "r"(a[0]), "r"(a[1]), "r"(a[2]), "r"(a[3]), "r"(b0), "r"(b1));
}
__device__ __forceinline__ uint32_t pack2h(float x, float y) {
    __half2 v(__float2half_rn(x), __float2half_rn(y));
    return *reinterpret_cast<uint32_t*>(&v);
}
__device__ __forceinline__ void split2h(float x, float y, uint32_t& h, uint32_t& l) {
    __half hx = __float2half_rn(x), hy = __float2half_rn(y);
    __half2 vh(hx, hy);
    __half2 vl(__float2half_rn(x - __half2float(hx)),
               __float2half_rn(y - __half2float(hy)));
    h = *reinterpret_cast<uint32_t*>(&vh);
    l = *reinterpret_cast<uint32_t*>(&vl);
}

// ---------------- fp32 -> fp16 hi/lo split ----------------
__global__ __launch_bounds__(256)
void split_kernel(const float* __restrict__ src, __half* __restrict__ hi,
                  __half* __restrict__ lo, int n4) {
    int i = blockIdx.x * blockDim.x + threadIdx.x;
    if (i >= n4) return;
    float4 v = reinterpret_cast<const float4*>(src)[i];
    uint32_t h0, l0, h1, l1;
    split2h(v.x, v.y, h0, l0);
    split2h(v.z, v.w, h1, l1);
    reinterpret_cast<uint2*>(hi)[i] = make_uint2(h0, h1);
    reinterpret_cast<uint2*>(lo)[i] = make_uint2(l0, l1);
}

// ---------------- fp32 -> fp16 round, all 4 weights in one launch ----------------
__global__ __launch_bounds__(256)
void round4_kernel(const float* __restrict__ w0, const float* __restrict__ w1,
                   const float* __restrict__ w2, const float* __restrict__ w3,
                   __half* __restrict__ dst, int n4) {
    int i = blockIdx.x * blockDim.x + threadIdx.x;
    if (i >= n4) return;
    const float* src = (blockIdx.y == 0) ? w0 : (blockIdx.y == 1) ? w1
                     : (blockIdx.y == 2) ? w2 : w3;
    float4 v = reinterpret_cast<const float4*>(src)[i];
    __half2 a(__float2half_rn(v.x), __float2half_rn(v.y));
    __half2 b(__float2half_rn(v.z), __float2half_rn(v.w));
    reinterpret_cast<uint2*>(dst)[(size_t)blockIdx.y * n4 + i] =
        make_uint2(*reinterpret_cast<uint32_t*>(&a), *reinterpret_cast<uint32_t*>(&b));
}

// ---------------- fp16 NT GEMM, templated tile: C = (Ah[+Al])*Bh ----------------
// 8 warps (4 in M x 2 in N). Warp tile = (TBM/4) x (TBN/2). 3-stage cp.async.
#define PITCHB 80

__device__ __forceinline__ void wait_rem(int rem) {
    if (rem >= 2)      asm volatile("cp.async.wait_group 2;" ::: "memory");
    else if (rem == 1) asm volatile("cp.async.wait_group 1;" ::: "memory");
    else               asm volatile("cp.async.wait_group 0;" ::: "memory");
}

template<int TBM, int TBN, bool LO2LAY>
__device__ __forceinline__ void load_stage(
    uint32_t sbase, const __half* Ah, const __half* Al, const __half* Bh,
    int m0, int n0, int k0, int K, int tid, bool use_lo) {
    const int OFF_AL = TBM * PITCHB;
    const int OFF_BH = (LO2LAY ? 2 : 1) * TBM * PITCHB;
    #pragma unroll
    for (int l = 0; l < TBM / 64; l++) {
        int idx = tid + l * 256;
        int r = idx >> 2;
        int c = idx & 3;
        uint32_t so = (uint32_t)(r * PITCHB + c * 16);
        size_t ga = (size_t)(m0 + r) * K + k0 + c * 8;
        cp16(sbase + so, Ah + ga);
        if (LO2LAY && use_lo) cp16(sbase + OFF_AL + so, Al + ga);
    }
    #pragma unroll
    for (int l = 0; l < TBN / 64; l++) {
        int idx = tid + l * 256;
        int r = idx >> 2;
        int c = idx & 3;
        uint32_t so = (uint32_t)(r * PITCHB + c * 16);
        size_t gb = (size_t)(n0 + r) * K + k0 + c * 8;
        cp16(sbase + OFF_BH + so, Bh + gb);
    }
    asm volatile("cp.async.commit_group;" ::: "memory");
}

// SPLIT_OUT=true: QKV path. Q cols (n0<768): 2 products, hi/lo out, scaled by
//   0.125*log2(e). K/V cols: 1 product, hi out. SPLIT_OUT=false: fp32 out.
template<int TBM, int TBN, bool SPLIT_OUT, bool LO2>
__global__ __launch_bounds__(256)
void gemm_mma(const __half* __restrict__ Ah, const __half* __restrict__ Al,
              const __half* __restrict__ Bh,
              float* __restrict__ C, __half* __restrict__ Ch,
              __half* __restrict__ Cl, int M, int N, int K) {
    constexpr int MI = TBM / 64;          // 16-row m-tiles per warp
    constexpr int NJ = TBN / 16;          // 8-col n-tiles per warp
    constexpr int STAGE = ((LO2 ? 2 : 1) * TBM + TBN) * PITCHB;
    extern __shared__ char smc[];
    const uint32_t sb = smem_u32(smc);
    const int tid = threadIdx.x;
    const int lane = tid & 31;
    const int wid = tid >> 5;
    const int wm = (wid & 3) * (TBM / 4);
    const int wn = (wid >> 2) * (TBN / 2);
    const int m0 = blockIdx.y * TBM;
    const int n0 = blockIdx.x * TBN;
    const bool use_lo = SPLIT_OUT ? (n0 < 768) : LO2;
    const int OFF_AL = TBM * PITCHB;
    const int OFF_BH = (LO2 ? 2 : 1) * TBM * PITCHB;

    float acc[MI][NJ][4] = {};
    const int a_lr = lane & 15, a_lc = lane >> 4;
    const int b_lr = lane & 7, b_kh = (lane >> 3) & 1, b_nh = lane >> 4;

    const int nstage = K / 32;
    load_stage<TBM, TBN, LO2>(sb, Ah, Al, Bh, m0, n0, 0, K, tid, use_lo);
    if (nstage > 1)
        load_stage<TBM, TBN, LO2>(sb + STAGE, Ah, Al, Bh, m0, n0, 32, K, tid, use_lo);

    for (int kt = 0; kt < nstage; kt++) {
        if (kt + 2 < nstage)
            load_stage<TBM, TBN, LO2>(sb + (uint32_t)((kt + 2) % 3) * STAGE,
                                      Ah, Al, Bh, m0, n0, (kt + 2) * 32, K, tid, use_lo);
        wait_rem(nstage - kt - 1);
        __syncthreads();

        const uint32_t st = sb + (uint32_t)(kt % 3) * STAGE;
        #pragma unroll
        for (int kk = 0; kk < 2; kk++) {
            const uint32_t kcol = (uint32_t)((kk * 16 + a_lc * 8) * 2);
            uint32_t ah[MI][4], al[MI][4];
            #pragma unroll
            for (int mi = 0; mi < MI; mi++) {
                uint32_t ro = (uint32_t)((wm + mi * 16 + a_lr) * PITCHB) + kcol;
                ldm4(ah[mi], st + ro);
                if (use_lo) ldm4(al[mi], st + OFF_AL + ro);
            }
            const uint32_t bkcol = (uint32_t)((kk * 16 + b_kh * 8) * 2);
            uint32_t bh[NJ / 2][4];
            #pragma unroll
            for (int ni = 0; ni < NJ / 2; ni++) {
                uint32_t ro = (uint32_t)((wn + ni * 16 + b_lr + b_nh * 8) * PITCHB) + bkcol;
                ldm4(bh[ni], st + OFF_BH + ro);
            }
            #pragma unroll
            for (int mi = 0; mi < MI; mi++)
                #pragma unroll
                for (int nj = 0; nj < NJ; nj++) {
                    const int ni = nj >> 1, od = (nj & 1) * 2;
                    mma_f16(acc[mi][nj], ah[mi], bh[ni][od], bh[ni][od + 1]);
                    if (use_lo)
                        mma_f16(acc[mi][nj], al[mi], bh[ni][od], bh[ni][od + 1]);
                }
        }
        __syncthreads();
    }

    const int g = lane >> 2, t = lane & 3;
    const float sc = (SPLIT_OUT && n0 < 768) ? 0.180336880111112f : 1.0f;
    #pragma unroll
    for (int mi = 0; mi < MI; mi++)
        #pragma unroll
        for (int nj = 0; nj < NJ; nj++) {
            int row = m0 + wm + mi * 16 + g;
            int col = n0 + wn + nj * 8 + t * 2;
            if (SPLIT_OUT) {
                uint32_t h0, l0, h1, l1;
                split2h(acc[mi][nj][0] * sc, acc[mi][nj][1] * sc, h0, l0);
                split2h(acc[mi][nj][2] * sc, acc[mi][nj][3] * sc, h1, l1);
                *reinterpret_cast<uint32_t*>(&Ch[(size_t)row * N + col]) = h0;
                *reinterpret_cast<uint32_t*>(&Ch[(size_t)(row + 8) * N + col]) = h1;
                if (use_lo) {
                    *reinterpret_cast<uint32_t*>(&Cl[(size_t)row * N + col]) = l0;
                    *reinterpret_cast<uint32_t*>(&Cl[(size_t)(row + 8) * N + col]) = l1;
                }
            } else {
                *reinterpret_cast<float2*>(&C[(size_t)row * N + col]) =
                    make_float2(acc[mi][nj][0], acc[mi][nj][1]);
                *reinterpret_cast<float2*>(&C[(size_t)(row + 8) * N + col]) =
                    make_float2(acc[mi][nj][2], acc[mi][nj][3]);
            }
        }
}

#define QKV_SMEM (3 * ((2 * 256 + 128) * PITCHB))   // 153600
#define OPJ_SMEM (3 * ((128 + 192) * PITCHB))       // 76800

// ---------------- fp16 causal flash attention, split-KV ----------------
// S = (Qh+Ql)*Kh scaled by 0.125*log2(e); exp2 softmax; O = Ph*Vh.
// grid (24 bh, 24 items). Light items write g_ah; split items write partials.
#define P144 144
#define SQH 0
#define SQL 18432
#define SKV 36864
#define KVSTAGE 18432          // KH 0 | VH 9216
#define ATT_SMEM (SKV + 4 * KVSTAGE)   // 110592

__global__ __launch_bounds__(256, 2)
void attn_mma() {
    extern __shared__ char smc[];
    const uint32_t sb = smem_u32(smc);
    const int tid = threadIdx.x;
    const int lane = tid & 31;
    const int wid = tid >> 5;
    const int bh = blockIdx.x;
    const int4 it = g_items[blockIdx.y];
    const int qb = it.x, kt0 = it.y, kt1 = it.z, hlf = it.w;
    const int b = bh / NUM_HEADS;
    const int h = bh % NUM_HEADS;
    const int wm = wid * 16;
    const int g = lane >> 2, t = lane & 3;

    const size_t qrow0 = (size_t)b * SEQ + (size_t)qb * 128;
    const size_t krow0 = (size_t)b * SEQ;
    const size_t qoff = (size_t)h * DK;
    const size_t koff = 768 + (size_t)h * DK;
    const size_t voff = 1536 + (size_t)h * DK;

    // Q tiles (hi+lo fp16), persistent; folded into group of load_kv(kt0)
    #pragma unroll
    for (int l = 0; l < 4; l++) {
        int idx = tid + l * 256;
        int r = idx >> 3, c = idx & 7;
        size_t ga = (qrow0 + r) * D_QKV + qoff + c * 8;
        uint32_t so = (uint32_t)(r * P144 + c * 16);
        cp16(sb + SQH + so, g_qkvh + ga);
        cp16(sb + SQL + so, g_qkvl + ga);
    }

    const int ntl = kt1 - kt0;   // local tile count (>= 2 always)
    auto load_kv = [&](int kt) {
        uint32_t stb = sb + SKV + (uint32_t)(kt & 3) * KVSTAGE;
        #pragma unroll
        for (int l = 0; l < 2; l++) {
            int idx = tid + l * 256;
            int r = idx >> 3, c = idx & 7;
            size_t grow = (krow0 + (size_t)kt * 64 + r) * D_QKV;
            uint32_t so = (uint32_t)(r * P144 + c * 16);
            cp16(stb + so, g_qkvh + grow + koff + c * 8);
            cp16(stb + 9216 + so, g_qkvh + grow + voff + c * 8);
        }
        asm volatile("cp.async.commit_group;" ::: "memory");
    };

    // prologue: 3 tiles in flight
    load_kv(kt0);
    if (ntl > 1) load_kv(kt0 + 1);
    if (ntl > 2) load_kv(kt0 + 2);

    float oacc[8][4] = {};
    float m_i[2] = {-INFINITY, -INFINITY};
    float l_i[2] = {0.0f, 0.0f};

    const int a_lr = lane & 15, a_lc = lane >> 4;
    const int b_lr = lane & 7, b_kh = (lane >> 3) & 1, b_nh = lane >> 4;
    const int v_r = lane & 15, v_c = (lane >> 4) * 8;

    for (int j = 0; j < ntl; j++) {
        const int kt = kt0 + j;
        int rem = ntl - 1 - j;
        wait_rem(rem < 2 ? rem : 2);
        __syncthreads();   // publish tile kt from ALL threads; tile kt-1 reads done
        if (j + 3 < ntl) load_kv(kt + 3);   // overwrites (kt-1)&3 — safe now

        const uint32_t stb = sb + SKV + (uint32_t)(kt & 3) * KVSTAGE;
        const bool skip = (kt == 2 * qb + 1) && (wid < 4);

        if (!skip) {
            float sacc[8][4] = {};
            #pragma unroll
            for (int kk = 0; kk < 4; kk++) {
                const uint32_t kcol = (uint32_t)((kk * 16 + a_lc * 8) * 2);
                uint32_t qh[4], ql[4];
                ldm4(qh, sb + SQH + (uint32_t)((wm + a_lr) * P144) + kcol);
                ldm4(ql, sb + SQL + (uint32_t)((wm + a_lr) * P144) + kcol);
                const uint32_t bkcol = (uint32_t)((kk * 16 + b_kh * 8) * 2);
                #pragma unroll
                for (int np = 0; np < 4; np++) {
                    uint32_t kh[4];
                    ldm4(kh, stb + (uint32_t)((np * 16 + b_lr + b_nh * 8) * P144) + bkcol);
                    mma_f16(sacc[2 * np],     qh, kh[0], kh[1]);
                    mma_f16(sacc[2 * np],     ql, kh[0], kh[1]);
                    mma_f16(sacc[2 * np + 1], qh, kh[2], kh[3]);
                    mma_f16(sacc[2 * np + 1], ql, kh[2], kh[3]);
                }
            }

            const bool needmask = (kt == 2 * qb && wid < 4) ||
                                  (kt == 2 * qb + 1 && wid >= 4);
            if (needmask) {
                const int grow0 = qb * 128 + wm + g;
                #pragma unroll
                for (int nt = 0; nt < 8; nt++) {
                    const int gcol = kt * 64 + nt * 8 + t * 2;
                    #pragma unroll
                    for (int jj = 0; jj < 4; jj++) {
                        const int row = grow0 + (jj >> 1) * 8;
                        const int col = gcol + (jj & 1);
                        if (col > row) sacc[nt][jj] = -INFINITY;
                    }
                }
            }

            // base-2 online softmax per row-half
            #pragma unroll
            for (int hh = 0; hh < 2; hh++) {
                float rm = -INFINITY;
                #pragma unroll
                for (int nt = 0; nt < 8; nt++)
                    rm = fmaxf(rm, fmaxf(sacc[nt][2 * hh], sacc[nt][2 * hh + 1]));
                rm = fmaxf(rm, __shfl_xor_sync(0xffffffffu, rm, 1));
                rm = fmaxf(rm, __shfl_xor_sync(0xffffffffu, rm, 2));
                float mn = fmaxf(m_i[hh], rm);
                float alpha = exp2f(m_i[hh] - mn);
                float rs = 0.0f;
                #pragma unroll
                for (int nt = 0; nt < 8; nt++) {
                    float p0 = exp2f(sacc[nt][2 * hh] - mn);
                    float p1 = exp2f(sacc[nt][2 * hh + 1] - mn);
                    sacc[nt][2 * hh] = p0;
                    sacc[nt][2 * hh + 1] = p1;
                    rs += p0 + p1;
                }
                rs += __shfl_xor_sync(0xffffffffu, rs, 1);
                rs += __shfl_xor_sync(0xffffffffu, rs, 2);
                l_i[hh] = l_i[hh] * alpha + rs;
                m_i[hh] = mn;
                #pragma unroll
                for (int nt = 0; nt < 8; nt++) {
                    oacc[nt][2 * hh] *= alpha;
                    oacc[nt][2 * hh + 1] *= alpha;
                }
            }

            // O += Ph Vh (1 product)
            #pragma unroll
            for (int ks = 0; ks < 4; ks++) {
                uint32_t ph[4];
                ph[0] = pack2h(sacc[2 * ks][0],     sacc[2 * ks][1]);
                ph[1] = pack2h(sacc[2 * ks][2],     sacc[2 * ks][3]);
                ph[2] = pack2h(sacc[2 * ks + 1][0], sacc[2 * ks + 1][1]);
                ph[3] = pack2h(sacc[2 * ks + 1][2], sacc[2 * ks + 1][3]);
                const uint32_t vrow = (uint32_t)((ks * 16 + v_r) * P144);
                #pragma unroll
                for (int np = 0; np < 4; np++) {
                    uint32_t vh[4];
                    ldm4t(vh, stb + 9216 + vrow + (uint32_t)((np * 16 + v_c) * 2));
                    mma_f16(oacc[2 * np],     ph, vh[0], vh[1]);
                    mma_f16(oacc[2 * np + 1], ph, vh[2], vh[3]);
                }
            }
        }
    }

    const int r0 = wm + g, r1 = wm + g + 8;
    if (hlf < 0) {
        // light item: normalize + write fp16 final
        const float inv0 = 1.0f / l_i[0], inv1 = 1.0f / l_i[1];
        #pragma unroll
        for (int nt = 0; nt < 8; nt++) {
            size_t a0 = (qrow0 + r0) * D_MODEL + qoff + nt * 8 + t * 2;
            size_t a1 = (qrow0 + r1) * D_MODEL + qoff + nt * 8 + t * 2;
            *reinterpret_cast<uint32_t*>(&g_ah[a0]) =
                pack2h(oacc[nt][0] * inv0, oacc[nt][1] * inv0);
            *reinterpret_cast<uint32_t*>(&g_ah[a1]) =
                pack2h(oacc[nt][2] * inv1, oacc[nt][3] * inv1);
        }
    } else {
        // split item: write unnormalized partial O + (m, l)
        const int sidx = (bh * 8 + (qb - 8)) * 2 + hlf;
        float* P = g_part + (size_t)sidx * 8192;
        #pragma unroll
        for (int nt = 0; nt < 8; nt++) {
            const int col = nt * 8 + t * 2;
            *reinterpret_cast<float2*>(&P[r0 * 64 + col]) =
                make_float2(oacc[nt][0], oacc[nt][1]);
            *reinterpret_cast<float2*>(&P[r1 * 64 + col]) =
                make_float2(oacc[nt][2], oacc[nt][3]);
        }
        if (t == 0) {
            g_ml[sidx * 256 + r0 * 2 + 0] = m_i[0];
            g_ml[sidx * 256 + r0 * 2 + 1] = l_i[0];
            g_ml[sidx * 256 + r1 * 2 + 0] = m_i[1];
            g_ml[sidx * 256 + r1 * 2 + 1] = l_i[1];
        }
    }
}

// ---------------- combine split-KV partials ----------------
// grid (8 qb', 24 bh), 256 threads. Each thread: one row, 32 cols.
__global__ __launch_bounds__(256)
void combine_kernel() {
    const int qb2 = blockIdx.x;          // qb = 8 + qb2
    const int bh = blockIdx.y;
    const int b = bh / NUM_HEADS, h = bh % NUM_HEADS;
    const int row = threadIdx.x >> 1;
    const int c0 = (threadIdx.x & 1) * 32;
    const int sidx0 = (bh * 8 + qb2) * 2;
    const float* P0 = g_part + (size_t)sidx0 * 8192;
    const float* P1 = P0 + 8192;
    const float m0 = g_ml[sidx0 * 256 + row * 2 + 0];
    const float l0 = g_ml[sidx0 * 256 + row * 2 + 1];
    const float m1 = g_ml[(sidx0 + 1) * 256 + row * 2 + 0];
    const float l1 = g_ml[(sidx0 + 1) * 256 + row * 2 + 1];
    const float m = fmaxf(m0, m1);
    const float w0 = exp2f(m0 - m), w1 = exp2f(m1 - m);
    const float inv = 1.0f / (l0 * w0 + l1 * w1);

    const size_t orow = ((size_t)b * SEQ + (size_t)(8 + qb2) * 128 + row) * D_MODEL
                        + (size_t)h * DK + c0;
    #pragma unroll
    for (int cc = 0; cc < 32; cc += 4) {
        float4 p0 = *reinterpret_cast<const float4*>(&P0[row * 64 + c0 + cc]);
        float4 p1 = *reinterpret_cast<const float4*>(&P1[row * 64 + c0 + cc]);
        uint2 o;
        o.x = pack2h((p0.x * w0 + p1.x * w1) * inv, (p0.y * w0 + p1.y * w1) * inv);
        o.y = pack2h((p0.z * w0 + p1.z * w1) * inv, (p0.w * w0 + p1.w * w1) * inv);
        *reinterpret_cast<uint2*>(&g_ah[orow + cc]) = o;
    }
}

// ---------------- launch ----------------
extern "C" void kernel_launch(void* const* d_in, const int* in_sizes, int n_in,
                              void* d_out, int out_size) {
    const float* x  = (const float*)d_in[0];
    const float* wq = (const float*)d_in[1];
    const float* wk = (const float*)d_in[2];
    const float* wv = (const float*)d_in[3];
    const float* wo = (const float*)d_in[4];
    float* out = (float*)d_out;

    __half *xh, *xl, *qkvh, *qkvl, *ah, *wh;
    cudaGetSymbolAddress((void**)&xh, g_xh);
    cudaGetSymbolAddress((void**)&xl, g_xl);
    cudaGetSymbolAddress((void**)&qkvh, g_qkvh);
    cudaGetSymbolAddress((void**)&qkvl, g_qkvl);
    cudaGetSymbolAddress((void**)&ah, g_ah);
    cudaGetSymbolAddress((void**)&wh, g_wh);

    // 1. x -> fp16 hi/lo; weights -> fp16 (one fused launch, q|k|v|o)
    split_kernel<<<(XN / 4 + 255) / 256, 256>>>(x, xh, xl, XN / 4);
    dim3 rgrid((WN / 4 + 255) / 256, 4);
    round4_kernel<<<rgrid, 256>>>(wq, wk, wv, wo, wh, WN / 4);

    // 2. fused QKV projection (N = 2304), tile 256x128
    cudaFuncSetAttribute((const void*)gemm_mma<256, 128, true, true>,
                         cudaFuncAttributeMaxDynamicSharedMemorySize, QKV_SMEM);
    cudaFuncSetAttribute((const void*)gemm_mma<128, 192, false, false>,
                         cudaFuncAttributeMaxDynamicSharedMemorySize, OPJ_SMEM);
    dim3 qkvgrid(D_QKV / 128, MTOT / 256);   // (18, 16)
    gemm_mma<256, 128, true, true><<<qkvgrid, 256, QKV_SMEM>>>(
        xh, xl, wh, nullptr, qkvh, qkvl, MTOT, D_QKV, D_MODEL);

    // 3. split-KV flash attention + combine
    cudaFuncSetAttribute(attn_mma, cudaFuncAttributeMaxDynamicSharedMemorySize, ATT_SMEM);
    dim3 agrid(24, 24);   // x = bh, y = work item (heaviest first)
    attn_mma<<<agrid, 256, ATT_SMEM>>>();
    dim3 cgrid(8, 24);
    combine_kernel<<<cgrid, 256>>>();

    // 4. output projection -> fp32, tile 128x192, single wave (128 CTAs)
    dim3 ogrid(D_MODEL / 192, MTOT / 128);   // (4, 32)
    gemm_mma<128, 192, false, false><<<ogrid, 256, OPJ_SMEM>>>(
        ah, ah, wh + 3 * WN, out, nullptr, nullptr, MTOT, D_MODEL, D_MODEL);
}

// round 12
// speedup vs baseline: 6.0440x; 1.1807x over previous
#include <cuda_runtime.h>
#include <cuda_bf16.h>
#include <cuda_fp16.h>
#include <math.h>
#include <stdint.h>

#define D_MODEL 768
#define NUM_HEADS 12
#define DK 64
#define BATCH 2
#define SEQ 2048
#define MTOT (BATCH * SEQ)          // 4096
#define XN (MTOT * D_MODEL)         // 3145728
#define WN (D_MODEL * D_MODEL)      // 589824
#define D_QKV 2304                  // fused Q|K|V column dim

// ---------------- scratch ----------------
__device__ __half g_xh[XN], g_xl[XN];
__device__ __half g_qkvh[MTOT * D_QKV];
__device__ __half g_ah[XN];
__device__ __half g_wh[4 * WN];              // fp16-rounded weights q|k|v|o
__device__ float g_part[24 * 8 * 2 * 8192];  // split-KV partial O (unnormalized)
__device__ float g_ml[24 * 8 * 2 * 256];     // split-KV per-row (m, l)

// work items per (b,h): heaviest-first. {qb, kt_begin, kt_end, half(-1=light)}
__device__ const int4 g_items[24] = {
    {7,0,16,-1},{15,0,16,0},{15,16,32,1},{14,0,15,0},{14,15,30,1},{6,0,14,-1},
    {13,0,14,0},{13,14,28,1},{12,0,13,0},{12,13,26,1},{5,0,12,-1},{11,0,12,0},
    {11,12,24,1},{10,0,11,0},{10,11,22,1},{4,0,10,-1},{9,0,10,0},{9,10,20,1},
    {8,0,9,0},{8,9,18,1},{3,0,8,-1},{2,0,6,-1},{1,0,4,-1},{0,0,2,-1}
};

// ---------------- helpers ----------------
__device__ __forceinline__ uint32_t smem_u32(const void* p) {
    uint32_t a;
    asm("{ .reg .u64 t; cvta.to.shared.u64 t, %1; cvt.u32.u64 %0, t; }"
        : "=r"(a) : "l"(p));
    return a;
}
__device__ __forceinline__ void cp16(uint32_t saddr, const void* gaddr) {
    asm volatile("cp.async.cg.shared.global [%0], [%1], 16;"
                 :: "r"(saddr), "l"(gaddr) : "memory");
}
__device__ __forceinline__ void ldm4(uint32_t* r, uint32_t addr) {
    asm volatile("ldmatrix.sync.aligned.m8n8.x4.shared.b16 {%0,%1,%2,%3}, [%4];"
                 : "=r"(r[0]), "=r"(r[1]), "=r"(r[2]), "=r"(r[3]) : "r"(addr));
}
__device__ __forceinline__ void ldm4t(uint32_t* r, uint32_t addr) {
    asm volatile("ldmatrix.sync.aligned.m8n8.x4.trans.shared.b16 {%0,%1,%2,%3}, [%4];"
                 : "=r"(r[0]), "=r"(r[1]), "=r"(r[2]), "=r"(r[3]) : "r"(addr));
}
__device__ __forceinline__ void mma_f16(float* c, const uint32_t* a,
                                        uint32_t b0, uint32_t b1) {
    asm volatile(
        "mma.sync.aligned.m16n8k16.row.col.f32.f16.f16.f32 "
        "{%0,%1,%2,%3}, {%4,%5,%6,%7}, {%8,%9}, {%0,%1,%2,%3};"
        : "+f"(c[0]), "+f"(c[1]), "+f"(c[2]), "+f"(c[3])
        : "r"(a[0]), "r"(a[1]), "r"(a[2]), "r"(a[3]), "r"(b0), "r"(b1));
}
__device__ __forceinline__ uint32_t pack2h(float x, float y) {
    __half2 v(__float2half_rn(x), __float2half_rn(y));
    return *reinterpret_cast<uint32_t*>(&v);
}
__device__ __forceinline__ void split2h(float x, float y, uint32_t& h, uint32_t& l) {
    __half hx = __float2half_rn(x), hy = __float2half_rn(y);
    __half2 vh(hx, hy);
    __half2 vl(__float2half_rn(x - __half2float(hx)),
               __float2half_rn(y - __half2float(hy)));
    h = *reinterpret_cast<uint32_t*>(&vh);
    l = *reinterpret_cast<uint32_t*>(&vl);
}

// ---------------- fp32 -> fp16 hi/lo split ----------------
__global__ __launch_bounds__(256)
void split_kernel(const float* __restrict__ src, __half* __restrict__ hi,
                  __half* __restrict__ lo, int n4) {
    int i = blockIdx.x * blockDim.x + threadIdx.x;
    if (i >= n4) return;
    float4 v = reinterpret_cast<const float4*>(src)[i];
    uint32_t h0, l0, h1, l1;
    split2h(v.x, v.y, h0, l0);
    split2h(v.z, v.w, h1, l1);
    reinterpret_cast<uint2*>(hi)[i] = make_uint2(h0, h1);
    reinterpret_cast<uint2*>(lo)[i] = make_uint2(l0, l1);
}

// ---------------- fp32 -> fp16 round, all 4 weights in one launch ----------------
__global__ __launch_bounds__(256)
void round4_kernel(const float* __restrict__ w0, const float* __restrict__ w1,
                   const float* __restrict__ w2, const float* __restrict__ w3,
                   __half* __restrict__ dst, int n4) {
    int i = blockIdx.x * blockDim.x + threadIdx.x;
    if (i >= n4) return;
    const float* src = (blockIdx.y == 0) ? w0 : (blockIdx.y == 1) ? w1
                     : (blockIdx.y == 2) ? w2 : w3;
    float4 v = reinterpret_cast<const float4*>(src)[i];
    __half2 a(__float2half_rn(v.x), __float2half_rn(v.y));
    __half2 b(__float2half_rn(v.z), __float2half_rn(v.w));
    reinterpret_cast<uint2*>(dst)[(size_t)blockIdx.y * n4 + i] =
        make_uint2(*reinterpret_cast<uint32_t*>(&a), *reinterpret_cast<uint32_t*>(&b));
}

// ---------------- fp16 NT GEMM, 128x128 tile, 2 CTAs/SM ----------------
// 8 warps (4 in M x 2 in N), warp tile 32x64. 3-stage cp.async.
// SPLIT_OUT=true (QKV): Q cols (n0<768) 2 products (accurate hi), scaled by
//   0.125*log2(e); K/V cols 1 product. fp16 hi out only.
// SPLIT_OUT=false (O-proj): 1 product, fp32 out.
#define PITCHB 80
#define GBM 128
#define GBN 128
#define G_OFF_AL (GBM * PITCHB)
#define G_OFF_BH (2 * GBM * PITCHB)
#define G_STAGE ((2 * GBM + GBN) * PITCHB)     // 30720
#define GEMM_SMEM (3 * G_STAGE)                // 92160

__device__ __forceinline__ void wait_rem(int rem) {
    if (rem >= 2)      asm volatile("cp.async.wait_group 2;" ::: "memory");
    else if (rem == 1) asm volatile("cp.async.wait_group 1;" ::: "memory");
    else               asm volatile("cp.async.wait_group 0;" ::: "memory");
}

__device__ __forceinline__ void load_stage(
    uint32_t sbase, const __half* Ah, const __half* Al, const __half* Bh,
    int m0, int n0, int k0, int K, int tid, bool use_lo) {
    #pragma unroll
    for (int l = 0; l < 2; l++) {               // A: 128 rows x 4 x 16B
        int idx = tid + l * 256;
        int r = idx >> 2;
        int c = idx & 3;
        uint32_t so = (uint32_t)(r * PITCHB + c * 16);
        size_t ga = (size_t)(m0 + r) * K + k0 + c * 8;
        cp16(sbase + so, Ah + ga);
        if (use_lo) cp16(sbase + G_OFF_AL + so, Al + ga);
    }
    #pragma unroll
    for (int l = 0; l < 2; l++) {               // B: 128 rows x 4 x 16B
        int idx = tid + l * 256;
        int r = idx >> 2;
        int c = idx & 3;
        uint32_t so = (uint32_t)(r * PITCHB + c * 16);
        size_t gb = (size_t)(n0 + r) * K + k0 + c * 8;
        cp16(sbase + G_OFF_BH + so, Bh + gb);
    }
    asm volatile("cp.async.commit_group;" ::: "memory");
}

template<bool SPLIT_OUT>
__global__ __launch_bounds__(256, 2)
void gemm_mma(const __half* __restrict__ Ah, const __half* __restrict__ Al,
              const __half* __restrict__ Bh,
              float* __restrict__ C, __half* __restrict__ Ch,
              int M, int N, int K) {
    extern __shared__ char smc[];
    const uint32_t sb = smem_u32(smc);
    const int tid = threadIdx.x;
    const int lane = tid & 31;
    const int wid = tid >> 5;
    const int wm = (wid & 3) * 32;
    const int wn = (wid >> 2) * 64;
    const int m0 = blockIdx.y * GBM;
    const int n0 = blockIdx.x * GBN;
    const bool use_lo = SPLIT_OUT && (n0 < 768);   // Q cols: 2 products

    float acc[2][8][4] = {};
    const int a_lr = lane & 15, a_lc = lane >> 4;
    const int b_lr = lane & 7, b_kh = (lane >> 3) & 1, b_nh = lane >> 4;

    const int nstage = K / 32;
    load_stage(sb, Ah, Al, Bh, m0, n0, 0, K, tid, use_lo);
    if (nstage > 1)
        load_stage(sb + G_STAGE, Ah, Al, Bh, m0, n0, 32, K, tid, use_lo);

    for (int kt = 0; kt < nstage; kt++) {
        if (kt + 2 < nstage)
            load_stage(sb + (uint32_t)((kt + 2) % 3) * G_STAGE,
                       Ah, Al, Bh, m0, n0, (kt + 2) * 32, K, tid, use_lo);
        wait_rem(nstage - kt - 1);
        __syncthreads();

        const uint32_t st = sb + (uint32_t)(kt % 3) * G_STAGE;
        #pragma unroll
        for (int kk = 0; kk < 2; kk++) {
            const uint32_t kcol = (uint32_t)((kk * 16 + a_lc * 8) * 2);
            uint32_t ah[2][4], al[2][4];
            #pragma unroll
            for (int mi = 0; mi < 2; mi++) {
                uint32_t ro = (uint32_t)((wm + mi * 16 + a_lr) * PITCHB) + kcol;
                ldm4(ah[mi], st + ro);
                if (use_lo) ldm4(al[mi], st + G_OFF_AL + ro);
            }
            const uint32_t bkcol = (uint32_t)((kk * 16 + b_kh * 8) * 2);
            uint32_t bh[4][4];
            #pragma unroll
            for (int ni = 0; ni < 4; ni++) {
                uint32_t ro = (uint32_t)((wn + ni * 16 + b_lr + b_nh * 8) * PITCHB) + bkcol;
                ldm4(bh[ni], st + G_OFF_BH + ro);
            }
            #pragma unroll
            for (int mi = 0; mi < 2; mi++)
                #pragma unroll
                for (int nj = 0; nj < 8; nj++) {
                    const int ni = nj >> 1, od = (nj & 1) * 2;
                    mma_f16(acc[mi][nj], ah[mi], bh[ni][od], bh[ni][od + 1]);
                    if (use_lo)
                        mma_f16(acc[mi][nj], al[mi], bh[ni][od], bh[ni][od + 1]);
                }
        }
        __syncthreads();
    }

    const int g = lane >> 2, t = lane & 3;
    // Q columns scaled by 0.125*log2(e) for the exp2-based softmax.
    const float sc = (SPLIT_OUT && n0 < 768) ? 0.180336880111112f : 1.0f;
    #pragma unroll
    for (int mi = 0; mi < 2; mi++)
        #pragma unroll
        for (int nj = 0; nj < 8; nj++) {
            int row = m0 + wm + mi * 16 + g;
            int col = n0 + wn + nj * 8 + t * 2;
            if (SPLIT_OUT) {
                *reinterpret_cast<uint32_t*>(&Ch[(size_t)row * N + col]) =
                    pack2h(acc[mi][nj][0] * sc, acc[mi][nj][1] * sc);
                *reinterpret_cast<uint32_t*>(&Ch[(size_t)(row + 8) * N + col]) =
                    pack2h(acc[mi][nj][2] * sc, acc[mi][nj][3] * sc);
            } else {
                *reinterpret_cast<float2*>(&C[(size_t)row * N + col]) =
                    make_float2(acc[mi][nj][0], acc[mi][nj][1]);
                *reinterpret_cast<float2*>(&C[(size_t)(row + 8) * N + col]) =
                    make_float2(acc[mi][nj][2], acc[mi][nj][3]);
            }
        }
}

// ---------------- fp16 causal flash attention, split-KV ----------------
// S = Qh*Kh (1 product), Q pre-scaled by 0.125*log2(e); exp2 softmax;
// O = Ph*Vh (1 product). grid (24 bh, 24 items), 4 KV buffers, 1 barrier/tile.
#define P144 144
#define SQH 0
#define SKV 18432
#define KVSTAGE 18432          // KH 0 | VH 9216
#define ATT_SMEM (SKV + 4 * KVSTAGE)   // 92160

__global__ __launch_bounds__(256, 2)
void attn_mma() {
    extern __shared__ char smc[];
    const uint32_t sb = smem_u32(smc);
    const int tid = threadIdx.x;
    const int lane = tid & 31;
    const int wid = tid >> 5;
    const int bh = blockIdx.x;
    const int4 it = g_items[blockIdx.y];
    const int qb = it.x, kt0 = it.y, kt1 = it.z, hlf = it.w;
    const int b = bh / NUM_HEADS;
    const int h = bh % NUM_HEADS;
    const int wm = wid * 16;
    const int g = lane >> 2, t = lane & 3;

    const size_t qrow0 = (size_t)b * SEQ + (size_t)qb * 128;
    const size_t krow0 = (size_t)b * SEQ;
    const size_t qoff = (size_t)h * DK;
    const size_t koff = 768 + (size_t)h * DK;
    const size_t voff = 1536 + (size_t)h * DK;

    // Q tile (hi fp16 only), persistent
    #pragma unroll
    for (int l = 0; l < 4; l++) {
        int idx = tid + l * 256;
        int r = idx >> 3, c = idx & 7;
        size_t ga = (qrow0 + r) * D_QKV + qoff + c * 8;
        uint32_t so = (uint32_t)(r * P144 + c * 16);
        cp16(sb + SQH + so, g_qkvh + ga);
    }

    const int ntl = kt1 - kt0;   // local tile count (>= 2 always)
    auto load_kv = [&](int kt) {
        uint32_t stb = sb + SKV + (uint32_t)(kt & 3) * KVSTAGE;
        #pragma unroll
        for (int l = 0; l < 2; l++) {
            int idx = tid + l * 256;
            int r = idx >> 3, c = idx & 7;
            size_t grow = (krow0 + (size_t)kt * 64 + r) * D_QKV;
            uint32_t so = (uint32_t)(r * P144 + c * 16);
            cp16(stb + so, g_qkvh + grow + koff + c * 8);
            cp16(stb + 9216 + so, g_qkvh + grow + voff + c * 8);
        }
        asm volatile("cp.async.commit_group;" ::: "memory");
    };

    // prologue: 3 tiles in flight
    load_kv(kt0);
    if (ntl > 1) load_kv(kt0 + 1);
    if (ntl > 2) load_kv(kt0 + 2);

    float oacc[8][4] = {};
    float m_i[2] = {-INFINITY, -INFINITY};
    float l_i[2] = {0.0f, 0.0f};

    const int a_lr = lane & 15, a_lc = lane >> 4;
    const int b_lr = lane & 7, b_kh = (lane >> 3) & 1, b_nh = lane >> 4;
    const int v_r = lane & 15, v_c = (lane >> 4) * 8;

    for (int j = 0; j < ntl; j++) {
        const int kt = kt0 + j;
        int rem = ntl - 1 - j;
        wait_rem(rem < 2 ? rem : 2);
        __syncthreads();   // publish tile kt from ALL threads; tile kt-1 reads done
        if (j + 3 < ntl) load_kv(kt + 3);   // overwrites (kt-1)&3 — safe now

        const uint32_t stb = sb + SKV + (uint32_t)(kt & 3) * KVSTAGE;
        const bool skip = (kt == 2 * qb + 1) && (wid < 4);

        if (!skip) {
            float sacc[8][4] = {};
            #pragma unroll
            for (int kk = 0; kk < 4; kk++) {
                const uint32_t kcol = (uint32_t)((kk * 16 + a_lc * 8) * 2);
                uint32_t qh[4];
                ldm4(qh, sb + SQH + (uint32_t)((wm + a_lr) * P144) + kcol);
                const uint32_t bkcol = (uint32_t)((kk * 16 + b_kh * 8) * 2);
                #pragma unroll
                for (int np = 0; np < 4; np++) {
                    uint32_t kh[4];
                    ldm4(kh, stb + (uint32_t)((np * 16 + b_lr + b_nh * 8) * P144) + bkcol);
                    mma_f16(sacc[2 * np],     qh, kh[0], kh[1]);
                    mma_f16(sacc[2 * np + 1], qh, kh[2], kh[3]);
                }
            }

            const bool needmask = (kt == 2 * qb && wid < 4) ||
                                  (kt == 2 * qb + 1 && wid >= 4);
            if (needmask) {
                const int grow0 = qb * 128 + wm + g;
                #pragma unroll
                for (int nt = 0; nt < 8; nt++) {
                    const int gcol = kt * 64 + nt * 8 + t * 2;
                    #pragma unroll
                    for (int jj = 0; jj < 4; jj++) {
                        const int row = grow0 + (jj >> 1) * 8;
                        const int col = gcol + (jj & 1);
                        if (col > row) sacc[nt][jj] = -INFINITY;
                    }
                }
            }

            // base-2 online softmax per row-half
            #pragma unroll
            for (int hh = 0; hh < 2; hh++) {
                float rm = -INFINITY;
                #pragma unroll
                for (int nt = 0; nt < 8; nt++)
                    rm = fmaxf(rm, fmaxf(sacc[nt][2 * hh], sacc[nt][2 * hh + 1]));
                rm = fmaxf(rm, __shfl_xor_sync(0xffffffffu, rm, 1));
                rm = fmaxf(rm, __shfl_xor_sync(0xffffffffu, rm, 2));
                float mn = fmaxf(m_i[hh], rm);
                float alpha = exp2f(m_i[hh] - mn);
                float rs = 0.0f;
                #pragma unroll
                for (int nt = 0; nt < 8; nt++) {
                    float p0 = exp2f(sacc[nt][2 * hh] - mn);
                    float p1 = exp2f(sacc[nt][2 * hh + 1] - mn);
                    sacc[nt][2 * hh] = p0;
                    sacc[nt][2 * hh + 1] = p1;
                    rs += p0 + p1;
                }
                rs += __shfl_xor_sync(0xffffffffu, rs, 1);
                rs += __shfl_xor_sync(0xffffffffu, rs, 2);
                l_i[hh] = l_i[hh] * alpha + rs;
                m_i[hh] = mn;
                #pragma unroll
                for (int nt = 0; nt < 8; nt++) {
                    oacc[nt][2 * hh] *= alpha;
                    oacc[nt][2 * hh + 1] *= alpha;
                }
            }

            // O += Ph Vh (1 product)
            #pragma unroll
            for (int ks = 0; ks < 4; ks++) {
                uint32_t ph[4];
                ph[0] = pack2h(sacc[2 * ks][0],     sacc[2 * ks][1]);
                ph[1] = pack2h(sacc[2 * ks][2],     sacc[2 * ks][3]);
                ph[2] = pack2h(sacc[2 * ks + 1][0], sacc[2 * ks + 1][1]);
                ph[3] = pack2h(sacc[2 * ks + 1][2], sacc[2 * ks + 1][3]);
                const uint32_t vrow = (uint32_t)((ks * 16 + v_r) * P144);
                #pragma unroll
                for (int np = 0; np < 4; np++) {
                    uint32_t vh[4];
                    ldm4t(vh, stb + 9216 + vrow + (uint32_t)((np * 16 + v_c) * 2));
                    mma_f16(oacc[2 * np],     ph, vh[0], vh[1]);
                    mma_f16(oacc[2 * np + 1], ph, vh[2], vh[3]);
                }
            }
        }
    }

    const int r0 = wm + g, r1 = wm + g + 8;
    if (hlf < 0) {
        // light item: normalize + write fp16 final
        const float inv0 = 1.0f / l_i[0], inv1 = 1.0f / l_i[1];
        #pragma unroll
        for (int nt = 0; nt < 8; nt++) {
            size_t a0 = (qrow0 + r0) * D_MODEL + qoff + nt * 8 + t * 2;
            size_t a1 = (qrow0 + r1) * D_MODEL + qoff + nt * 8 + t * 2;
            *reinterpret_cast<uint32_t*>(&g_ah[a0]) =
                pack2h(oacc[nt][0] * inv0, oacc[nt][1] * inv0);
            *reinterpret_cast<uint32_t*>(&g_ah[a1]) =
                pack2h(oacc[nt][2] * inv1, oacc[nt][3] * inv1);
        }
    } else {
        // split item: write unnormalized partial O + (m, l)
        const int sidx = (bh * 8 + (qb - 8)) * 2 + hlf;
        float* P = g_part + (size_t)sidx * 8192;
        #pragma unroll
        for (int nt = 0; nt < 8; nt++) {
            const int col = nt * 8 + t * 2;
            *reinterpret_cast<float2*>(&P[r0 * 64 + col]) =
                make_float2(oacc[nt][0], oacc[nt][1]);
            *reinterpret_cast<float2*>(&P[r1 * 64 + col]) =
                make_float2(oacc[nt][2], oacc[nt][3]);
        }
        if (t == 0) {
            g_ml[sidx * 256 + r0 * 2 + 0] = m_i[0];
            g_ml[sidx * 256 + r0 * 2 + 1] = l_i[0];
            g_ml[sidx * 256 + r1 * 2 + 0] = m_i[1];
            g_ml[sidx * 256 + r1 * 2 + 1] = l_i[1];
        }
    }
}

// ---------------- combine split-KV partials ----------------
__global__ __launch_bounds__(256)
void combine_kernel() {
    const int qb2 = blockIdx.x;          // qb = 8 + qb2
    const int bh = blockIdx.y;
    const int b = bh / NUM_HEADS, h = bh % NUM_HEADS;
    const int row = threadIdx.x >> 1;
    const int c0 = (threadIdx.x & 1) * 32;
    const int sidx0 = (bh * 8 + qb2) * 2;
    const float* P0 = g_part + (size_t)sidx0 * 8192;
    const float* P1 = P0 + 8192;
    const float m0 = g_ml[sidx0 * 256 + row * 2 + 0];
    const float l0 = g_ml[sidx0 * 256 + row * 2 + 1];
    const float m1 = g_ml[(sidx0 + 1) * 256 + row * 2 + 0];
    const float l1 = g_ml[(sidx0 + 1) * 256 + row * 2 + 1];
    const float m = fmaxf(m0, m1);
    const float w0 = exp2f(m0 - m), w1 = exp2f(m1 - m);
    const float inv = 1.0f / (l0 * w0 + l1 * w1);

    const size_t orow = ((size_t)b * SEQ + (size_t)(8 + qb2) * 128 + row) * D_MODEL
                        + (size_t)h * DK + c0;
    #pragma unroll
    for (int cc = 0; cc < 32; cc += 4) {
        float4 p0 = *reinterpret_cast<const float4*>(&P0[row * 64 + c0 + cc]);
        float4 p1 = *reinterpret_cast<const float4*>(&P1[row * 64 + c0 + cc]);
        uint2 o;
        o.x = pack2h((p0.x * w0 + p1.x * w1) * inv, (p0.y * w0 + p1.y * w1) * inv);
        o.y = pack2h((p0.z * w0 + p1.z * w1) * inv, (p0.w * w0 + p1.w * w1) * inv);
        *reinterpret_cast<uint2*>(&g_ah[orow + cc]) = o;
    }
}

// ---------------- launch ----------------
extern "C" void kernel_launch(void* const* d_in, const int* in_sizes, int n_in,
                              void* d_out, int out_size) {
    const float* x  = (const float*)d_in[0];
    const float* wq = (const float*)d_in[1];
    const float* wk = (const float*)d_in[2];
    const float* wv = (const float*)d_in[3];
    const float* wo = (const float*)d_in[4];
    float* out = (float*)d_out;

    __half *xh, *xl, *qkvh, *ah, *wh;
    cudaGetSymbolAddress((void**)&xh, g_xh);
    cudaGetSymbolAddress((void**)&xl, g_xl);
    cudaGetSymbolAddress((void**)&qkvh, g_qkvh);
    cudaGetSymbolAddress((void**)&ah, g_ah);
    cudaGetSymbolAddress((void**)&wh, g_wh);

    // 1. x -> fp16 hi/lo; weights -> fp16 (one fused launch, q|k|v|o)
    split_kernel<<<(XN / 4 + 255) / 256, 256>>>(x, xh, xl, XN / 4);
    dim3 rgrid((WN / 4 + 255) / 256, 4);
    round4_kernel<<<rgrid, 256>>>(wq, wk, wv, wo, wh, WN / 4);

    // 2. fused QKV projection (N = 2304), 128x128 tiles, 2 CTAs/SM
    cudaFuncSetAttribute((const void*)gemm_mma<true>,
                         cudaFuncAttributeMaxDynamicSharedMemorySize, GEMM_SMEM);
    cudaFuncSetAttribute((const void*)gemm_mma<false>,
                         cudaFuncAttributeMaxDynamicSharedMemorySize, GEMM_SMEM);
    dim3 qkvgrid(D_QKV / GBN, MTOT / GBM);   // (18, 32)
    gemm_mma<true><<<qkvgrid, 256, GEMM_SMEM>>>(xh, xl, wh,
                                                nullptr, qkvh,
                                                MTOT, D_QKV, D_MODEL);

    // 3. split-KV flash attention (1-product S and PV) + combine
    cudaFuncSetAttribute(attn_mma, cudaFuncAttributeMaxDynamicSharedMemorySize, ATT_SMEM);
    dim3 agrid(24, 24);   // x = bh, y = work item (heaviest first)
    attn_mma<<<agrid, 256, ATT_SMEM>>>();
    dim3 cgrid(8, 24);
    combine_kernel<<<cgrid, 256>>>();

    // 4. output projection -> fp32 (1 product), 128x128 tiles
    dim3 ogrid(D_MODEL / GBN, MTOT / GBM);   // (6, 32)
    gemm_mma<false><<<ogrid, 256, GEMM_SMEM>>>(ah, ah, wh + 3 * WN,
                                               out, nullptr,
                                               MTOT, D_MODEL, D_MODEL);
}

// round 13
// speedup vs baseline: 7.4587x; 1.2341x over previous
#include <cuda_runtime.h>
#include <cuda_bf16.h>
#include <cuda_fp16.h>
#include <math.h>
#include <stdint.h>

#define D_MODEL 768
#define NUM_HEADS 12
#define DK 64
#define BATCH 2
#define SEQ 2048
#define MTOT (BATCH * SEQ)          // 4096
#define XN (MTOT * D_MODEL)         // 3145728
#define WN (D_MODEL * D_MODEL)      // 589824
#define D_QKV 2304                  // fused Q|K|V column dim

// ---------------- scratch ----------------
__device__ __half g_xh[XN];
__device__ __half g_qkvh[MTOT * D_QKV];
__device__ __half g_ah[XN];
__device__ __half g_wh[4 * WN];              // fp16-rounded weights q|k|v|o
__device__ float g_part[24 * 8 * 2 * 8192];  // split-KV partial O (unnormalized)
__device__ float g_ml[24 * 8 * 2 * 256];     // split-KV per-row (m, l)

// work items per (b,h): heaviest-first. {qb, kt_begin, kt_end, half(-1=light)}
__device__ const int4 g_items[24] = {
    {7,0,16,-1},{15,0,16,0},{15,16,32,1},{14,0,15,0},{14,15,30,1},{6,0,14,-1},
    {13,0,14,0},{13,14,28,1},{12,0,13,0},{12,13,26,1},{5,0,12,-1},{11,0,12,0},
    {11,12,24,1},{10,0,11,0},{10,11,22,1},{4,0,10,-1},{9,0,10,0},{9,10,20,1},
    {8,0,9,0},{8,9,18,1},{3,0,8,-1},{2,0,6,-1},{1,0,4,-1},{0,0,2,-1}
};

// ---------------- helpers ----------------
__device__ __forceinline__ uint32_t smem_u32(const void* p) {
    uint32_t a;
    asm("{ .reg .u64 t; cvta.to.shared.u64 t, %1; cvt.u32.u64 %0, t; }"
        : "=r"(a) : "l"(p));
    return a;
}
__device__ __forceinline__ void cp16(uint32_t saddr, const void* gaddr) {
    asm volatile("cp.async.cg.shared.global [%0], [%1], 16;"
                 :: "r"(saddr), "l"(gaddr) : "memory");
}
__device__ __forceinline__ void ldm4(uint32_t* r, uint32_t addr) {
    asm volatile("ldmatrix.sync.aligned.m8n8.x4.shared.b16 {%0,%1,%2,%3}, [%4];"
                 : "=r"(r[0]), "=r"(r[1]), "=r"(r[2]), "=r"(r[3]) : "r"(addr));
}
__device__ __forceinline__ void ldm4t(uint32_t* r, uint32_t addr) {
    asm volatile("ldmatrix.sync.aligned.m8n8.x4.trans.shared.b16 {%0,%1,%2,%3}, [%4];"
                 : "=r"(r[0]), "=r"(r[1]), "=r"(r[2]), "=r"(r[3]) : "r"(addr));
}
__device__ __forceinline__ void mma_f16(float* c, const uint32_t* a,
                                        uint32_t b0, uint32_t b1) {
    asm volatile(
        "mma.sync.aligned.m16n8k16.row.col.f32.f16.f16.f32 "
        "{%0,%1,%2,%3}, {%4,%5,%6,%7}, {%8,%9}, {%0,%1,%2,%3};"
        : "+f"(c[0]), "+f"(c[1]), "+f"(c[2]), "+f"(c[3])
        : "r"(a[0]), "r"(a[1]), "r"(a[2]), "r"(a[3]), "r"(b0), "r"(b1));
}
__device__ __forceinline__ uint32_t pack2h(float x, float y) {
    __half2 v(__float2half_rn(x), __float2half_rn(y));
    return *reinterpret_cast<uint32_t*>(&v);
}

// ---------------- fp32 -> fp16 round: x + 4 weights, one launch ----------------
// blockIdx.y: 0 -> x (XN), 1..4 -> weights (WN each).
__global__ __launch_bounds__(256)
void round5_kernel(const float* __restrict__ x,
                   const float* __restrict__ w0, const float* __restrict__ w1,
                   const float* __restrict__ w2, const float* __restrict__ w3) {
    int i = blockIdx.x * blockDim.x + threadIdx.x;
    const int seg = blockIdx.y;
    const float* src;
    __half* dst;
    int n4;
    if (seg == 0)      { src = x;  dst = g_xh;          n4 = XN / 4; }
    else if (seg == 1) { src = w0; dst = g_wh;          n4 = WN / 4; }
    else if (seg == 2) { src = w1; dst = g_wh + WN;     n4 = WN / 4; }
    else if (seg == 3) { src = w2; dst = g_wh + 2 * WN; n4 = WN / 4; }
    else               { src = w3; dst = g_wh + 3 * WN; n4 = WN / 4; }
    if (i >= n4) return;
    float4 v = reinterpret_cast<const float4*>(src)[i];
    reinterpret_cast<uint2*>(dst)[i] =
        make_uint2(pack2h(v.x, v.y), pack2h(v.z, v.w));
}

// ---------------- fp16 NT GEMM, 128x128 tile, 1 product, 2 CTAs/SM ----------------
// 8 warps (4 in M x 2 in N), warp tile 32x64. 3-stage cp.async.
// SPLIT_OUT=true (QKV): fp16 out; Q cols (n0<768) scaled by 0.125*log2(e).
// SPLIT_OUT=false (O-proj): fp32 out.
#define PITCHB 80
#define GBM 128
#define GBN 128
#define G_OFF_BH (GBM * PITCHB)
#define G_STAGE ((GBM + GBN) * PITCHB)     // 20480
#define GEMM_SMEM (3 * G_STAGE)            // 61440

__device__ __forceinline__ void wait_rem(int rem) {
    if (rem >= 2)      asm volatile("cp.async.wait_group 2;" ::: "memory");
    else if (rem == 1) asm volatile("cp.async.wait_group 1;" ::: "memory");
    else               asm volatile("cp.async.wait_group 0;" ::: "memory");
}

__device__ __forceinline__ void load_stage(
    uint32_t sbase, const __half* Ah, const __half* Bh,
    int m0, int n0, int k0, int K, int tid) {
    #pragma unroll
    for (int l = 0; l < 2; l++) {               // A: 128 rows x 4 x 16B
        int idx = tid + l * 256;
        int r = idx >> 2;
        int c = idx & 3;
        uint32_t so = (uint32_t)(r * PITCHB + c * 16);
        cp16(sbase + so, Ah + (size_t)(m0 + r) * K + k0 + c * 8);
    }
    #pragma unroll
    for (int l = 0; l < 2; l++) {               // B: 128 rows x 4 x 16B
        int idx = tid + l * 256;
        int r = idx >> 2;
        int c = idx & 3;
        uint32_t so = (uint32_t)(r * PITCHB + c * 16);
        cp16(sbase + G_OFF_BH + so, Bh + (size_t)(n0 + r) * K + k0 + c * 8);
    }
    asm volatile("cp.async.commit_group;" ::: "memory");
}

template<bool SPLIT_OUT>
__global__ __launch_bounds__(256, 2)
void gemm_mma(const __half* __restrict__ Ah, const __half* __restrict__ Bh,
              float* __restrict__ C, __half* __restrict__ Ch,
              int M, int N, int K) {
    extern __shared__ char smc[];
    const uint32_t sb = smem_u32(smc);
    const int tid = threadIdx.x;
    const int lane = tid & 31;
    const int wid = tid >> 5;
    const int wm = (wid & 3) * 32;
    const int wn = (wid >> 2) * 64;
    const int m0 = blockIdx.y * GBM;
    const int n0 = blockIdx.x * GBN;

    float acc[2][8][4] = {};
    const int a_lr = lane & 15, a_lc = lane >> 4;
    const int b_lr = lane & 7, b_kh = (lane >> 3) & 1, b_nh = lane >> 4;

    const int nstage = K / 32;
    load_stage(sb, Ah, Bh, m0, n0, 0, K, tid);
    if (nstage > 1)
        load_stage(sb + G_STAGE, Ah, Bh, m0, n0, 32, K, tid);

    for (int kt = 0; kt < nstage; kt++) {
        if (kt + 2 < nstage)
            load_stage(sb + (uint32_t)((kt + 2) % 3) * G_STAGE,
                       Ah, Bh, m0, n0, (kt + 2) * 32, K, tid);
        wait_rem(nstage - kt - 1);
        __syncthreads();

        const uint32_t st = sb + (uint32_t)(kt % 3) * G_STAGE;
        #pragma unroll
        for (int kk = 0; kk < 2; kk++) {
            const uint32_t kcol = (uint32_t)((kk * 16 + a_lc * 8) * 2);
            uint32_t ah[2][4];
            #pragma unroll
            for (int mi = 0; mi < 2; mi++)
                ldm4(ah[mi], st + (uint32_t)((wm + mi * 16 + a_lr) * PITCHB) + kcol);
            const uint32_t bkcol = (uint32_t)((kk * 16 + b_kh * 8) * 2);
            uint32_t bh[4][4];
            #pragma unroll
            for (int ni = 0; ni < 4; ni++) {
                uint32_t ro = (uint32_t)((wn + ni * 16 + b_lr + b_nh * 8) * PITCHB) + bkcol;
                ldm4(bh[ni], st + G_OFF_BH + ro);
            }
            #pragma unroll
            for (int mi = 0; mi < 2; mi++)
                #pragma unroll
                for (int nj = 0; nj < 8; nj++) {
                    const int ni = nj >> 1, od = (nj & 1) * 2;
                    mma_f16(acc[mi][nj], ah[mi], bh[ni][od], bh[ni][od + 1]);
                }
        }
        __syncthreads();
    }

    const int g = lane >> 2, t = lane & 3;
    // Q columns scaled by 0.125*log2(e) for the exp2-based softmax.
    const float sc = (SPLIT_OUT && n0 < 768) ? 0.180336880111112f : 1.0f;
    #pragma unroll
    for (int mi = 0; mi < 2; mi++)
        #pragma unroll
        for (int nj = 0; nj < 8; nj++) {
            int row = m0 + wm + mi * 16 + g;
            int col = n0 + wn + nj * 8 + t * 2;
            if (SPLIT_OUT) {
                *reinterpret_cast<uint32_t*>(&Ch[(size_t)row * N + col]) =
                    pack2h(acc[mi][nj][0] * sc, acc[mi][nj][1] * sc);
                *reinterpret_cast<uint32_t*>(&Ch[(size_t)(row + 8) * N + col]) =
                    pack2h(acc[mi][nj][2] * sc, acc[mi][nj][3] * sc);
            } else {
                *reinterpret_cast<float2*>(&C[(size_t)row * N + col]) =
                    make_float2(acc[mi][nj][0], acc[mi][nj][1]);
                *reinterpret_cast<float2*>(&C[(size_t)(row + 8) * N + col]) =
                    make_float2(acc[mi][nj][2], acc[mi][nj][3]);
            }
        }
}

// ---------------- fp16 causal flash attention, split-KV ----------------
// S = Qh*Kh (1 product), Q pre-scaled by 0.125*log2(e); exp2 softmax;
// O = Ph*Vh (1 product). grid (24 bh, 24 items), 4 KV buffers, 1 barrier/tile.
#define P144 144
#define SQH 0
#define SKV 18432
#define KVSTAGE 18432          // KH 0 | VH 9216
#define ATT_SMEM (SKV + 4 * KVSTAGE)   // 92160

__global__ __launch_bounds__(256, 2)
void attn_mma() {
    extern __shared__ char smc[];
    const uint32_t sb = smem_u32(smc);
    const int tid = threadIdx.x;
    const int lane = tid & 31;
    const int wid = tid >> 5;
    const int bh = blockIdx.x;
    const int4 it = g_items[blockIdx.y];
    const int qb = it.x, kt0 = it.y, kt1 = it.z, hlf = it.w;
    const int b = bh / NUM_HEADS;
    const int h = bh % NUM_HEADS;
    const int wm = wid * 16;
    const int g = lane >> 2, t = lane & 3;

    const size_t qrow0 = (size_t)b * SEQ + (size_t)qb * 128;
    const size_t krow0 = (size_t)b * SEQ;
    const size_t qoff = (size_t)h * DK;
    const size_t koff = 768 + (size_t)h * DK;
    const size_t voff = 1536 + (size_t)h * DK;

    // Q tile (hi fp16), persistent
    #pragma unroll
    for (int l = 0; l < 4; l++) {
        int idx = tid + l * 256;
        int r = idx >> 3, c = idx & 7;
        size_t ga = (qrow0 + r) * D_QKV + qoff + c * 8;
        uint32_t so = (uint32_t)(r * P144 + c * 16);
        cp16(sb + SQH + so, g_qkvh + ga);
    }

    const int ntl = kt1 - kt0;   // local tile count (>= 2 always)
    auto load_kv = [&](int kt) {
        uint32_t stb = sb + SKV + (uint32_t)(kt & 3) * KVSTAGE;
        #pragma unroll
        for (int l = 0; l < 2; l++) {
            int idx = tid + l * 256;
            int r = idx >> 3, c = idx & 7;
            size_t grow = (krow0 + (size_t)kt * 64 + r) * D_QKV;
            uint32_t so = (uint32_t)(r * P144 + c * 16);
            cp16(stb + so, g_qkvh + grow + koff + c * 8);
            cp16(stb + 9216 + so, g_qkvh + grow + voff + c * 8);
        }
        asm volatile("cp.async.commit_group;" ::: "memory");
    };

    // prologue: 3 tiles in flight
    load_kv(kt0);
    if (ntl > 1) load_kv(kt0 + 1);
    if (ntl > 2) load_kv(kt0 + 2);

    float oacc[8][4] = {};
    float m_i[2] = {-INFINITY, -INFINITY};
    float l_i[2] = {0.0f, 0.0f};

    const int a_lr = lane & 15, a_lc = lane >> 4;
    const int b_lr = lane & 7, b_kh = (lane >> 3) & 1, b_nh = lane >> 4;
    const int v_r = lane & 15, v_c = (lane >> 4) * 8;

    for (int j = 0; j < ntl; j++) {
        const int kt = kt0 + j;
        int rem = ntl - 1 - j;
        wait_rem(rem < 2 ? rem : 2);
        __syncthreads();   // publish tile kt from ALL threads; tile kt-1 reads done
        if (j + 3 < ntl) load_kv(kt + 3);   // overwrites (kt-1)&3 — safe now

        const uint32_t stb = sb + SKV + (uint32_t)(kt & 3) * KVSTAGE;
        const bool skip = (kt == 2 * qb + 1) && (wid < 4);

        if (!skip) {
            float sacc[8][4] = {};
            #pragma unroll
            for (int kk = 0; kk < 4; kk++) {
                const uint32_t kcol = (uint32_t)((kk * 16 + a_lc * 8) * 2);
                uint32_t qh[4];
                ldm4(qh, sb + SQH + (uint32_t)((wm + a_lr) * P144) + kcol);
                const uint32_t bkcol = (uint32_t)((kk * 16 + b_kh * 8) * 2);
                #pragma unroll
                for (int np = 0; np < 4; np++) {
                    uint32_t kh[4];
                    ldm4(kh, stb + (uint32_t)((np * 16 + b_lr + b_nh * 8) * P144) + bkcol);
                    mma_f16(sacc[2 * np],     qh, kh[0], kh[1]);
                    mma_f16(sacc[2 * np + 1], qh, kh[2], kh[3]);
                }
            }

            const bool needmask = (kt == 2 * qb && wid < 4) ||
                                  (kt == 2 * qb + 1 && wid >= 4);
            if (needmask) {
                const int grow0 = qb * 128 + wm + g;
                #pragma unroll
                for (int nt = 0; nt < 8; nt++) {
                    const int gcol = kt * 64 + nt * 8 + t * 2;
                    #pragma unroll
                    for (int jj = 0; jj < 4; jj++) {
                        const int row = grow0 + (jj >> 1) * 8;
                        const int col = gcol + (jj & 1);
                        if (col > row) sacc[nt][jj] = -INFINITY;
                    }
                }
            }

            // base-2 online softmax per row-half
            #pragma unroll
            for (int hh = 0; hh < 2; hh++) {
                float rm = -INFINITY;
                #pragma unroll
                for (int nt = 0; nt < 8; nt++)
                    rm = fmaxf(rm, fmaxf(sacc[nt][2 * hh], sacc[nt][2 * hh + 1]));
                rm = fmaxf(rm, __shfl_xor_sync(0xffffffffu, rm, 1));
                rm = fmaxf(rm, __shfl_xor_sync(0xffffffffu, rm, 2));
                float mn = fmaxf(m_i[hh], rm);
                float alpha = exp2f(m_i[hh] - mn);
                float rs = 0.0f;
                #pragma unroll
                for (int nt = 0; nt < 8; nt++) {
                    float p0 = exp2f(sacc[nt][2 * hh] - mn);
                    float p1 = exp2f(sacc[nt][2 * hh + 1] - mn);
                    sacc[nt][2 * hh] = p0;
                    sacc[nt][2 * hh + 1] = p1;
                    rs += p0 + p1;
                }
                rs += __shfl_xor_sync(0xffffffffu, rs, 1);
                rs += __shfl_xor_sync(0xffffffffu, rs, 2);
                l_i[hh] = l_i[hh] * alpha + rs;
                m_i[hh] = mn;
                #pragma unroll
                for (int nt = 0; nt < 8; nt++) {
                    oacc[nt][2 * hh] *= alpha;
                    oacc[nt][2 * hh + 1] *= alpha;
                }
            }

            // O += Ph Vh (1 product)
            #pragma unroll
            for (int ks = 0; ks < 4; ks++) {
                uint32_t ph[4];
                ph[0] = pack2h(sacc[2 * ks][0],     sacc[2 * ks][1]);
                ph[1] = pack2h(sacc[2 * ks][2],     sacc[2 * ks][3]);
                ph[2] = pack2h(sacc[2 * ks + 1][0], sacc[2 * ks + 1][1]);
                ph[3] = pack2h(sacc[2 * ks + 1][2], sacc[2 * ks + 1][3]);
                const uint32_t vrow = (uint32_t)((ks * 16 + v_r) * P144);
                #pragma unroll
                for (int np = 0; np < 4; np++) {
                    uint32_t vh[4];
                    ldm4t(vh, stb + 9216 + vrow + (uint32_t)((np * 16 + v_c) * 2));
                    mma_f16(oacc[2 * np],     ph, vh[0], vh[1]);
                    mma_f16(oacc[2 * np + 1], ph, vh[2], vh[3]);
                }
            }
        }
    }

    const int r0 = wm + g, r1 = wm + g + 8;
    if (hlf < 0) {
        // light item: normalize + write fp16 final
        const float inv0 = 1.0f / l_i[0], inv1 = 1.0f / l_i[1];
        #pragma unroll
        for (int nt = 0; nt < 8; nt++) {
            size_t a0 = (qrow0 + r0) * D_MODEL + qoff + nt * 8 + t * 2;
            size_t a1 = (qrow0 + r1) * D_MODEL + qoff + nt * 8 + t * 2;
            *reinterpret_cast<uint32_t*>(&g_ah[a0]) =
                pack2h(oacc[nt][0] * inv0, oacc[nt][1] * inv0);
            *reinterpret_cast<uint32_t*>(&g_ah[a1]) =
                pack2h(oacc[nt][2] * inv1, oacc[nt][3] * inv1);
        }
    } else {
        // split item: write unnormalized partial O + (m, l)
        const int sidx = (bh * 8 + (qb - 8)) * 2 + hlf;
        float* P = g_part + (size_t)sidx * 8192;
        #pragma unroll
        for (int nt = 0; nt < 8; nt++) {
            const int col = nt * 8 + t * 2;
            *reinterpret_cast<float2*>(&P[r0 * 64 + col]) =
                make_float2(oacc[nt][0], oacc[nt][1]);
            *reinterpret_cast<float2*>(&P[r1 * 64 + col]) =
                make_float2(oacc[nt][2], oacc[nt][3]);
        }
        if (t == 0) {
            g_ml[sidx * 256 + r0 * 2 + 0] = m_i[0];
            g_ml[sidx * 256 + r0 * 2 + 1] = l_i[0];
            g_ml[sidx * 256 + r1 * 2 + 0] = m_i[1];
            g_ml[sidx * 256 + r1 * 2 + 1] = l_i[1];
        }
    }
}

// ---------------- combine split-KV partials ----------------
__global__ __launch_bounds__(256)
void combine_kernel() {
    const int qb2 = blockIdx.x;          // qb = 8 + qb2
    const int bh = blockIdx.y;
    const int b = bh / NUM_HEADS, h = bh % NUM_HEADS;
    const int row = threadIdx.x >> 1;
    const int c0 = (threadIdx.x & 1) * 32;
    const int sidx0 = (bh * 8 + qb2) * 2;
    const float* P0 = g_part + (size_t)sidx0 * 8192;
    const float* P1 = P0 + 8192;
    const float m0 = g_ml[sidx0 * 256 + row * 2 + 0];
    const float l0 = g_ml[sidx0 * 256 + row * 2 + 1];
    const float m1 = g_ml[(sidx0 + 1) * 256 + row * 2 + 0];
    const float l1 = g_ml[(sidx0 + 1) * 256 + row * 2 + 1];
    const float m = fmaxf(m0, m1);
    const float w0 = exp2f(m0 - m), w1 = exp2f(m1 - m);
    const float inv = 1.0f / (l0 * w0 + l1 * w1);

    const size_t orow = ((size_t)b * SEQ + (size_t)(8 + qb2) * 128 + row) * D_MODEL
                        + (size_t)h * DK + c0;
    #pragma unroll
    for (int cc = 0; cc < 32; cc += 4) {
        float4 p0 = *reinterpret_cast<const float4*>(&P0[row * 64 + c0 + cc]);
        float4 p1 = *reinterpret_cast<const float4*>(&P1[row * 64 + c0 + cc]);
        uint2 o;
        o.x = pack2h((p0.x * w0 + p1.x * w1) * inv, (p0.y * w0 + p1.y * w1) * inv);
        o.y = pack2h((p0.z * w0 + p1.z * w1) * inv, (p0.w * w0 + p1.w * w1) * inv);
        *reinterpret_cast<uint2*>(&g_ah[orow + cc]) = o;
    }
}

// ---------------- launch ----------------
extern "C" void kernel_launch(void* const* d_in, const int* in_sizes, int n_in,
                              void* d_out, int out_size) {
    const float* x  = (const float*)d_in[0];
    const float* wq = (const float*)d_in[1];
    const float* wk = (const float*)d_in[2];
    const float* wv = (const float*)d_in[3];
    const float* wo = (const float*)d_in[4];
    float* out = (float*)d_out;

    __half *xh, *qkvh, *ah, *wh;
    cudaGetSymbolAddress((void**)&xh, g_xh);
    cudaGetSymbolAddress((void**)&qkvh, g_qkvh);
    cudaGetSymbolAddress((void**)&ah, g_ah);
    cudaGetSymbolAddress((void**)&wh, g_wh);

    // 1. round x + 4 weights to fp16, ONE launch
    dim3 rgrid((XN / 4 + 255) / 256, 5);
    round5_kernel<<<rgrid, 256>>>(x, wq, wk, wv, wo);

    // 2. fused QKV projection (N = 2304), 1 product, 128x128, 2 CTAs/SM
    cudaFuncSetAttribute((const void*)gemm_mma<true>,
                         cudaFuncAttributeMaxDynamicSharedMemorySize, GEMM_SMEM);
    cudaFuncSetAttribute((const void*)gemm_mma<false>,
                         cudaFuncAttributeMaxDynamicSharedMemorySize, GEMM_SMEM);
    dim3 qkvgrid(D_QKV / GBN, MTOT / GBM);   // (18, 32)
    gemm_mma<true><<<qkvgrid, 256, GEMM_SMEM>>>(xh, wh, nullptr, qkvh,
                                                MTOT, D_QKV, D_MODEL);

    // 3. split-KV flash attention + combine
    cudaFuncSetAttribute(attn_mma, cudaFuncAttributeMaxDynamicSharedMemorySize, ATT_SMEM);
    dim3 agrid(24, 24);   // x = bh, y = work item (heaviest first)
    attn_mma<<<agrid, 256, ATT_SMEM>>>();
    dim3 cgrid(8, 24);
    combine_kernel<<<cgrid, 256>>>();

    // 4. output projection -> fp32 (1 product), 128x128 tiles
    dim3 ogrid(D_MODEL / GBN, MTOT / GBM);   // (6, 32)
    gemm_mma<false><<<ogrid, 256, GEMM_SMEM>>>(ah, wh + 3 * WN, out, nullptr,
                                               MTOT, D_MODEL, D_MODEL);
}

// round 15
// speedup vs baseline: 7.7118x; 1.0339x over previous
#include <cuda_runtime.h>
#include <cuda_bf16.h>
#include <cuda_fp16.h>
#include <math.h>
#include <stdint.h>

#define D_MODEL 768
#define NUM_HEADS 12
#define DK 64
#define BATCH 2
#define SEQ 2048
#define MTOT (BATCH * SEQ)          // 4096
#define XN (MTOT * D_MODEL)         // 3145728
#define WN (D_MODEL * D_MODEL)      // 589824
#define D_QKV 2304                  // fused Q|K|V column dim

// ---------------- scratch ----------------
__device__ __half g_xh[XN];
__device__ __half g_qkvh[MTOT * D_QKV];
__device__ __half g_ah[XN];
__device__ __half g_wh[4 * WN];              // fp16-rounded weights q|k|v|o
__device__ float g_part[24 * 8 * 2 * 8192];  // split-KV partial O (unnormalized)
__device__ float g_ml[24 * 8 * 2 * 256];     // split-KV per-row (m, l)

// work items per (b,h): heaviest-first. {qb, kt_begin, kt_end, half(-1=light)}
__device__ const int4 g_items[24] = {
    {7,0,16,-1},{15,0,16,0},{15,16,32,1},{14,0,15,0},{14,15,30,1},{6,0,14,-1},
    {13,0,14,0},{13,14,28,1},{12,0,13,0},{12,13,26,1},{5,0,12,-1},{11,0,12,0},
    {11,12,24,1},{10,0,11,0},{10,11,22,1},{4,0,10,-1},{9,0,10,0},{9,10,20,1},
    {8,0,9,0},{8,9,18,1},{3,0,8,-1},{2,0,6,-1},{1,0,4,-1},{0,0,2,-1}
};

// ---------------- helpers ----------------
__device__ __forceinline__ uint32_t smem_u32(const void* p) {
    uint32_t a;
    asm("{ .reg .u64 t; cvta.to.shared.u64 t, %1; cvt.u32.u64 %0, t; }"
        : "=r"(a) : "l"(p));
    return a;
}
__device__ __forceinline__ void cp16(uint32_t saddr, const void* gaddr) {
    asm volatile("cp.async.cg.shared.global [%0], [%1], 16;"
                 :: "r"(saddr), "l"(gaddr) : "memory");
}
__device__ __forceinline__ void ldm4(uint32_t* r, uint32_t addr) {
    asm volatile("ldmatrix.sync.aligned.m8n8.x4.shared.b16 {%0,%1,%2,%3}, [%4];"
                 : "=r"(r[0]), "=r"(r[1]), "=r"(r[2]), "=r"(r[3]) : "r"(addr));
}
__device__ __forceinline__ void ldm4t(uint32_t* r, uint32_t addr) {
    asm volatile("ldmatrix.sync.aligned.m8n8.x4.trans.shared.b16 {%0,%1,%2,%3}, [%4];"
                 : "=r"(r[0]), "=r"(r[1]), "=r"(r[2]), "=r"(r[3]) : "r"(addr));
}
__device__ __forceinline__ void mma_f16(float* c, const uint32_t* a,
                                        uint32_t b0, uint32_t b1) {
    asm volatile(
        "mma.sync.aligned.m16n8k16.row.col.f32.f16.f16.f32 "
        "{%0,%1,%2,%3}, {%4,%5,%6,%7}, {%8,%9}, {%0,%1,%2,%3};"
        : "+f"(c[0]), "+f"(c[1]), "+f"(c[2]), "+f"(c[3])
        : "r"(a[0]), "r"(a[1]), "r"(a[2]), "r"(a[3]), "r"(b0), "r"(b1));
}
__device__ __forceinline__ uint32_t pack2h(float x, float y) {
    __half2 v(__float2half_rn(x), __float2half_rn(y));
    return *reinterpret_cast<uint32_t*>(&v);
}

// ---------------- fp32 -> fp16 round: x + 4 weights, one launch ----------------
__global__ __launch_bounds__(256)
void round5_kernel(const float* __restrict__ x,
                   const float* __restrict__ w0, const float* __restrict__ w1,
                   const float* __restrict__ w2, const float* __restrict__ w3) {
    int i = blockIdx.x * blockDim.x + threadIdx.x;
    const int seg = blockIdx.y;
    const float* src;
    __half* dst;
    int n4;
    if (seg == 0)      { src = x;  dst = g_xh;          n4 = XN / 4; }
    else if (seg == 1) { src = w0; dst = g_wh;          n4 = WN / 4; }
    else if (seg == 2) { src = w1; dst = g_wh + WN;     n4 = WN / 4; }
    else if (seg == 3) { src = w2; dst = g_wh + 2 * WN; n4 = WN / 4; }
    else               { src = w3; dst = g_wh + 3 * WN; n4 = WN / 4; }
    if (i >= n4) return;
    float4 v = reinterpret_cast<const float4*>(src)[i];
    reinterpret_cast<uint2*>(dst)[i] =
        make_uint2(pack2h(v.x, v.y), pack2h(v.z, v.w));
}

// ---------------- fp16 NT GEMM, 128x128 tile, BK=64, 1 product ----------------
// 8 warps (4 in M x 2 in N), warp tile 32x64. 3-stage cp.async, pitch 144.
#define PITCHG 144
#define GBM 128
#define GBN 128
#define G_OFF_BH (GBM * PITCHG)
#define G_STAGE ((GBM + GBN) * PITCHG)     // 36864
#define GEMM_SMEM (3 * G_STAGE)            // 110592

__device__ __forceinline__ void wait_rem(int rem) {
    if (rem >= 2)      asm volatile("cp.async.wait_group 2;" ::: "memory");
    else if (rem == 1) asm volatile("cp.async.wait_group 1;" ::: "memory");
    else               asm volatile("cp.async.wait_group 0;" ::: "memory");
}

__device__ __forceinline__ void load_stage(
    uint32_t sbase, const __half* Ah, const __half* Bh,
    int m0, int n0, int k0, int K, int tid) {
    #pragma unroll
    for (int l = 0; l < 4; l++) {               // A: 128 rows x 8 x 16B
        int idx = tid + l * 256;
        int r = idx >> 3;
        int c = idx & 7;
        uint32_t so = (uint32_t)(r * PITCHG + c * 16);
        cp16(sbase + so, Ah + (size_t)(m0 + r) * K + k0 + c * 8);
    }
    #pragma unroll
    for (int l = 0; l < 4; l++) {               // B: 128 rows x 8 x 16B
        int idx = tid + l * 256;
        int r = idx >> 3;
        int c = idx & 7;
        uint32_t so = (uint32_t)(r * PITCHG + c * 16);
        cp16(sbase + G_OFF_BH + so, Bh + (size_t)(n0 + r) * K + k0 + c * 8);
    }
    asm volatile("cp.async.commit_group;" ::: "memory");
}

template<bool SPLIT_OUT>
__global__ __launch_bounds__(256, 2)
void gemm_mma(const __half* __restrict__ Ah, const __half* __restrict__ Bh,
              float* __restrict__ C, __half* __restrict__ Ch,
              int M, int N, int K) {
    extern __shared__ char smc[];
    const uint32_t sb = smem_u32(smc);
    const int tid = threadIdx.x;
    const int lane = tid & 31;
    const int wid = tid >> 5;
    const int wm = (wid & 3) * 32;
    const int wn = (wid >> 2) * 64;
    const int m0 = blockIdx.y * GBM;
    const int n0 = blockIdx.x * GBN;

    float acc[2][8][4] = {};
    const int a_lr = lane & 15, a_lc = lane >> 4;
    const int b_lr = lane & 7, b_kh = (lane >> 3) & 1, b_nh = lane >> 4;

    const int nstage = K / 64;   // 12
    load_stage(sb, Ah, Bh, m0, n0, 0, K, tid);
    if (nstage > 1)
        load_stage(sb + G_STAGE, Ah, Bh, m0, n0, 64, K, tid);

    for (int kt = 0; kt < nstage; kt++) {
        if (kt + 2 < nstage)
            load_stage(sb + (uint32_t)((kt + 2) % 3) * G_STAGE,
                       Ah, Bh, m0, n0, (kt + 2) * 64, K, tid);
        wait_rem(nstage - kt - 1);
        __syncthreads();

        const uint32_t st = sb + (uint32_t)(kt % 3) * G_STAGE;
        #pragma unroll
        for (int kk = 0; kk < 4; kk++) {         // four k16 steps per stage
            const uint32_t kcol = (uint32_t)((kk * 16 + a_lc * 8) * 2);
            uint32_t ah[2][4];
            #pragma unroll
            for (int mi = 0; mi < 2; mi++)
                ldm4(ah[mi], st + (uint32_t)((wm + mi * 16 + a_lr) * PITCHG) + kcol);
            const uint32_t bkcol = (uint32_t)((kk * 16 + b_kh * 8) * 2);
            uint32_t bh[4][4];
            #pragma unroll
            for (int ni = 0; ni < 4; ni++) {
                uint32_t ro = (uint32_t)((wn + ni * 16 + b_lr + b_nh * 8) * PITCHG) + bkcol;
                ldm4(bh[ni], st + G_OFF_BH + ro);
            }
            #pragma unroll
            for (int mi = 0; mi < 2; mi++)
                #pragma unroll
                for (int nj = 0; nj < 8; nj++) {
                    const int ni = nj >> 1, od = (nj & 1) * 2;
                    mma_f16(acc[mi][nj], ah[mi], bh[ni][od], bh[ni][od + 1]);
                }
        }
        __syncthreads();
    }

    const int g = lane >> 2, t = lane & 3;
    // Q columns scaled by 0.125*log2(e) for the exp2-based softmax.
    const float sc = (SPLIT_OUT && n0 < 768) ? 0.180336880111112f : 1.0f;
    #pragma unroll
    for (int mi = 0; mi < 2; mi++)
        #pragma unroll
        for (int nj = 0; nj < 8; nj++) {
            int row = m0 + wm + mi * 16 + g;
            int col = n0 + wn + nj * 8 + t * 2;
            if (SPLIT_OUT) {
                *reinterpret_cast<uint32_t*>(&Ch[(size_t)row * N + col]) =
                    pack2h(acc[mi][nj][0] * sc, acc[mi][nj][1] * sc);
                *reinterpret_cast<uint32_t*>(&Ch[(size_t)(row + 8) * N + col]) =
                    pack2h(acc[mi][nj][2] * sc, acc[mi][nj][3] * sc);
            } else {
                *reinterpret_cast<float2*>(&C[(size_t)row * N + col]) =
                    make_float2(acc[mi][nj][0], acc[mi][nj][1]);
                *reinterpret_cast<float2*>(&C[(size_t)(row + 8) * N + col]) =
                    make_float2(acc[mi][nj][2], acc[mi][nj][3]);
            }
        }
}

// ---------------- fp16 causal flash attention, split-KV ----------------
// S = Qh*Kh (1 product), Q pre-scaled by 0.125*log2(e); exp2 softmax;
// O = Ph*Vh (1 product). grid (24 bh, 24 items), 4 KV buffers, 1 barrier/tile.
#define P144 144
#define SQH 0
#define SKV 18432
#define KVSTAGE 18432          // KH 0 | VH 9216
#define ATT_SMEM (SKV + 4 * KVSTAGE)   // 92160

__global__ __launch_bounds__(256, 2)
void attn_mma() {
    extern __shared__ char smc[];
    const uint32_t sb = smem_u32(smc);
    const int tid = threadIdx.x;
    const int lane = tid & 31;
    const int wid = tid >> 5;
    const int bh = blockIdx.x;
    const int4 it = g_items[blockIdx.y];
    const int qb = it.x, kt0 = it.y, kt1 = it.z, hlf = it.w;
    const int b = bh / NUM_HEADS;
    const int h = bh % NUM_HEADS;
    const int wm = wid * 16;
    const int g = lane >> 2, t = lane & 3;

    const size_t qrow0 = (size_t)b * SEQ + (size_t)qb * 128;
    const size_t krow0 = (size_t)b * SEQ;
    const size_t qoff = (size_t)h * DK;
    const size_t koff = 768 + (size_t)h * DK;
    const size_t voff = 1536 + (size_t)h * DK;

    // Q tile (hi fp16), persistent
    #pragma unroll
    for (int l = 0; l < 4; l++) {
        int idx = tid + l * 256;
        int r = idx >> 3, c = idx & 7;
        size_t ga = (qrow0 + r) * D_QKV + qoff + c * 8;
        uint32_t so = (uint32_t)(r * P144 + c * 16);
        cp16(sb + SQH + so, g_qkvh + ga);
    }

    const int ntl = kt1 - kt0;   // local tile count (>= 2 always)
    auto load_kv = [&](int kt) {
        uint32_t stb = sb + SKV + (uint32_t)(kt & 3) * KVSTAGE;
        #pragma unroll
        for (int l = 0; l < 2; l++) {
            int idx = tid + l * 256;
            int r = idx >> 3, c = idx & 7;
            size_t grow = (krow0 + (size_t)kt * 64 + r) * D_QKV;
            uint32_t so = (uint32_t)(r * P144 + c * 16);
            cp16(stb + so, g_qkvh + grow + koff + c * 8);
            cp16(stb + 9216 + so, g_qkvh + grow + voff + c * 8);
        }
        asm volatile("cp.async.commit_group;" ::: "memory");
    };

    // prologue: 3 tiles in flight
    load_kv(kt0);
    if (ntl > 1) load_kv(kt0 + 1);
    if (ntl > 2) load_kv(kt0 + 2);

    float oacc[8][4] = {};
    float m_i[2] = {-INFINITY, -INFINITY};
    float l_i[2] = {0.0f, 0.0f};

    const int a_lr = lane & 15, a_lc = lane >> 4;
    const int b_lr = lane & 7, b_kh = (lane >> 3) & 1, b_nh = lane >> 4;
    const int v_r = lane & 15, v_c = (lane >> 4) * 8;

    for (int j = 0; j < ntl; j++) {
        const int kt = kt0 + j;
        int rem = ntl - 1 - j;
        wait_rem(rem < 2 ? rem : 2);
        __syncthreads();   // publish tile kt from ALL threads; tile kt-1 reads done
        if (j + 3 < ntl) load_kv(kt + 3);   // overwrites (kt-1)&3 — safe now

        const uint32_t stb = sb + SKV + (uint32_t)(kt & 3) * KVSTAGE;
        const bool skip = (kt == 2 * qb + 1) && (wid < 4);

        if (!skip) {
            float sacc[8][4] = {};
            #pragma unroll
            for (int kk = 0; kk < 4; kk++) {
                const uint32_t kcol = (uint32_t)((kk * 16 + a_lc * 8) * 2);
                uint32_t qh[4];
                ldm4(qh, sb + SQH + (uint32_t)((wm + a_lr) * P144) + kcol);
                const uint32_t bkcol = (uint32_t)((kk * 16 + b_kh * 8) * 2);
                #pragma unroll
                for (int np = 0; np < 4; np++) {
                    uint32_t kh[4];
                    ldm4(kh, stb + (uint32_t)((np * 16 + b_lr + b_nh * 8) * P144) + bkcol);
                    mma_f16(sacc[2 * np],     qh, kh[0], kh[1]);
                    mma_f16(sacc[2 * np + 1], qh, kh[2], kh[3]);
                }
            }

            const bool needmask = (kt == 2 * qb && wid < 4) ||
                                  (kt == 2 * qb + 1 && wid >= 4);
            if (needmask) {
                const int grow0 = qb * 128 + wm + g;
                #pragma unroll
                for (int nt = 0; nt < 8; nt++) {
                    const int gcol = kt * 64 + nt * 8 + t * 2;
                    #pragma unroll
                    for (int jj = 0; jj < 4; jj++) {
                        const int row = grow0 + (jj >> 1) * 8;
                        const int col = gcol + (jj & 1);
                        if (col > row) sacc[nt][jj] = -INFINITY;
                    }
                }
            }

            // base-2 online softmax per row-half
            #pragma unroll
            for (int hh = 0; hh < 2; hh++) {
                float rm = -INFINITY;
                #pragma unroll
                for (int nt = 0; nt < 8; nt++)
                    rm = fmaxf(rm, fmaxf(sacc[nt][2 * hh], sacc[nt][2 * hh + 1]));
                rm = fmaxf(rm, __shfl_xor_sync(0xffffffffu, rm, 1));
                rm = fmaxf(rm, __shfl_xor_sync(0xffffffffu, rm, 2));
                float mn = fmaxf(m_i[hh], rm);
                float alpha = exp2f(m_i[hh] - mn);
                float rs = 0.0f;
                #pragma unroll
                for (int nt = 0; nt < 8; nt++) {
                    float p0 = exp2f(sacc[nt][2 * hh] - mn);
                    float p1 = exp2f(sacc[nt][2 * hh + 1] - mn);
                    sacc[nt][2 * hh] = p0;
                    sacc[nt][2 * hh + 1] = p1;
                    rs += p0 + p1;
                }
                rs += __shfl_xor_sync(0xffffffffu, rs, 1);
                rs += __shfl_xor_sync(0xffffffffu, rs, 2);
                l_i[hh] = l_i[hh] * alpha + rs;
                m_i[hh] = mn;
                #pragma unroll
                for (int nt = 0; nt < 8; nt++) {
                    oacc[nt][2 * hh] *= alpha;
                    oacc[nt][2 * hh + 1] *= alpha;
                }
            }

            // O += Ph Vh (1 product)
            #pragma unroll
            for (int ks = 0; ks < 4; ks++) {
                uint32_t ph[4];
                ph[0] = pack2h(sacc[2 * ks][0],     sacc[2 * ks][1]);
                ph[1] = pack2h(sacc[2 * ks][2],     sacc[2 * ks][3]);
                ph[2] = pack2h(sacc[2 * ks + 1][0], sacc[2 * ks + 1][1]);
                ph[3] = pack2h(sacc[2 * ks + 1][2], sacc[2 * ks + 1][3]);
                const uint32_t vrow = (uint32_t)((ks * 16 + v_r) * P144);
                #pragma unroll
                for (int np = 0; np < 4; np++) {
                    uint32_t vh[4];
                    ldm4t(vh, stb + 9216 + vrow + (uint32_t)((np * 16 + v_c) * 2));
                    mma_f16(oacc[2 * np],     ph, vh[0], vh[1]);
                    mma_f16(oacc[2 * np + 1], ph, vh[2], vh[3]);
                }
            }
        }
    }

    const int r0 = wm + g, r1 = wm + g + 8;
    if (hlf < 0) {
        // light item: normalize + write fp16 final
        const float inv0 = 1.0f / l_i[0], inv1 = 1.0f / l_i[1];
        #pragma unroll
        for (int nt = 0; nt < 8; nt++) {
            size_t a0 = (qrow0 + r0) * D_MODEL + qoff + nt * 8 + t * 2;
            size_t a1 = (qrow0 + r1) * D_MODEL + qoff + nt * 8 + t * 2;
            *reinterpret_cast<uint32_t*>(&g_ah[a0]) =
                pack2h(oacc[nt][0] * inv0, oacc[nt][1] * inv0);
            *reinterpret_cast<uint32_t*>(&g_ah[a1]) =
                pack2h(oacc[nt][2] * inv1, oacc[nt][3] * inv1);
        }
    } else {
        // split item: write unnormalized partial O + (m, l)
        const int sidx = (bh * 8 + (qb - 8)) * 2 + hlf;
        float* P = g_part + (size_t)sidx * 8192;
        #pragma unroll
        for (int nt = 0; nt < 8; nt++) {
            const int col = nt * 8 + t * 2;
            *reinterpret_cast<float2*>(&P[r0 * 64 + col]) =
                make_float2(oacc[nt][0], oacc[nt][1]);
            *reinterpret_cast<float2*>(&P[r1 * 64 + col]) =
                make_float2(oacc[nt][2], oacc[nt][3]);
        }
        if (t == 0) {
            g_ml[sidx * 256 + r0 * 2 + 0] = m_i[0];
            g_ml[sidx * 256 + r0 * 2 + 1] = l_i[0];
            g_ml[sidx * 256 + r1 * 2 + 0] = m_i[1];
            g_ml[sidx * 256 + r1 * 2 + 1] = l_i[1];
        }
    }
}

// ---------------- combine split-KV partials ----------------
// grid (8 qb', 24 bh), 1024 threads: thread = one row x 8 cols.
__global__ __launch_bounds__(1024)
void combine_kernel() {
    const int qb2 = blockIdx.x;          // qb = 8 + qb2
    const int bh = blockIdx.y;
    const int b = bh / NUM_HEADS, h = bh % NUM_HEADS;
    const int row = threadIdx.x >> 3;
    const int c0 = (threadIdx.x & 7) * 8;
    const int sidx0 = (bh * 8 + qb2) * 2;
    const float* P0 = g_part + (size_t)sidx0 * 8192;
    const float* P1 = P0 + 8192;
    const float m0 = g_ml[sidx0 * 256 + row * 2 + 0];
    const float l0 = g_ml[sidx0 * 256 + row * 2 + 1];
    const float m1 = g_ml[(sidx0 + 1) * 256 + row * 2 + 0];
    const float l1 = g_ml[(sidx0 + 1) * 256 + row * 2 + 1];
    const float m = fmaxf(m0, m1);
    const float w0 = exp2f(m0 - m), w1 = exp2f(m1 - m);
    const float inv = 1.0f / (l0 * w0 + l1 * w1);

    const size_t orow = ((size_t)b * SEQ + (size_t)(8 + qb2) * 128 + row) * D_MODEL
                        + (size_t)h * DK + c0;
    #pragma unroll
    for (int cc = 0; cc < 8; cc += 4) {
        float4 p0 = *reinterpret_cast<const float4*>(&P0[row * 64 + c0 + cc]);
        float4 p1 = *reinterpret_cast<const float4*>(&P1[row * 64 + c0 + cc]);
        uint2 o;
        o.x = pack2h((p0.x * w0 + p1.x * w1) * inv, (p0.y * w0 + p1.y * w1) * inv);
        o.y = pack2h((p0.z * w0 + p1.z * w1) * inv, (p0.w * w0 + p1.w * w1) * inv);
        *reinterpret_cast<uint2*>(&g_ah[orow + cc]) = o;
    }
}

// ---------------- launch ----------------
extern "C" void kernel_launch(void* const* d_in, const int* in_sizes, int n_in,
                              void* d_out, int out_size) {
    const float* x  = (const float*)d_in[0];
    const float* wq = (const float*)d_in[1];
    const float* wk = (const float*)d_in[2];
    const float* wv = (const float*)d_in[3];
    const float* wo = (const float*)d_in[4];
    float* out = (float*)d_out;

    __half *xh, *qkvh, *ah, *wh;
    cudaGetSymbolAddress((void**)&xh, g_xh);
    cudaGetSymbolAddress((void**)&qkvh, g_qkvh);
    cudaGetSymbolAddress((void**)&ah, g_ah);
    cudaGetSymbolAddress((void**)&wh, g_wh);

    // 1. round x + 4 weights to fp16, ONE launch
    dim3 rgrid((XN / 4 + 255) / 256, 5);
    round5_kernel<<<rgrid, 256>>>(x, wq, wk, wv, wo);

    // 2. fused QKV projection (N = 2304), BK=64, 128x128, 2 CTAs/SM
    cudaFuncSetAttribute((const void*)gemm_mma<true>,
                         cudaFuncAttributeMaxDynamicSharedMemorySize, GEMM_SMEM);
    cudaFuncSetAttribute((const void*)gemm_mma<false>,
                         cudaFuncAttributeMaxDynamicSharedMemorySize, GEMM_SMEM);
    dim3 qkvgrid(D_QKV / GBN, MTOT / GBM);   // (18, 32)
    gemm_mma<true><<<qkvgrid, 256, GEMM_SMEM>>>(xh, wh, nullptr, qkvh,
                                                MTOT, D_QKV, D_MODEL);

    // 3. split-KV flash attention + combine
    cudaFuncSetAttribute(attn_mma, cudaFuncAttributeMaxDynamicSharedMemorySize, ATT_SMEM);
    dim3 agrid(24, 24);   // x = bh, y = work item (heaviest first)
    attn_mma<<<agrid, 256, ATT_SMEM>>>();
    dim3 cgrid(8, 24);
    combine_kernel<<<cgrid, 1024>>>();

    // 4. output projection -> fp32 (1 product), 128x128 tiles
    dim3 ogrid(D_MODEL / GBN, MTOT / GBM);   // (6, 32)
    gemm_mma<false><<<ogrid, 256, GEMM_SMEM>>>(ah, wh + 3 * WN, out, nullptr,
                                               MTOT, D_MODEL, D_MODEL);
}